// round 2
// baseline (speedup 1.0000x reference)
#include <cuda_runtime.h>
#include <cuda_bf16.h>

// Problem constants
#define NB   4
#define CIN  256
#define COUT 256
#define HH   64
#define WW   64
#define HWSZ 4096            // 64*64
#define KTAP 9
#define OFFC 18
#define GN_GROUPS 32
#define CPG  8               // channels per group
#define EPS  1e-5f

// ---------------- scratch (__device__ globals; no allocations) ----------------
__device__ float g_xt[NB * HWSZ * CIN];        // x transposed to [b][hw][c]  (16 MB)
__device__ float g_offs[NB * OFFC * HWSZ];     // offset conv output [b][ch][hw]
__device__ float g_wT[KTAP * CIN * COUT];      // deform weight [k][c][o]
__device__ float g_owT[CIN * KTAP * 20];       // offset weight [c][tap][o pad 20]
__device__ float g_stats[NB * GN_GROUPS * 2];  // (mean, rstd) per (b,g)

// ---------------- prep: transpose deform weight [o][c][k] -> [k][c][o] -------
__global__ void prep_w(const float* __restrict__ dw) {
    int i = blockIdx.x * 256 + threadIdx.x;          // over 9*256*256
    if (i >= KTAP * CIN * COUT) return;
    int o = i & 255;
    int c = (i >> 8) & 255;
    int k = i >> 16;
    g_wT[i] = dw[o * (CIN * KTAP) + c * KTAP + k];
}

// ---------------- prep: offset weight [o][c][tap] -> [c][tap][o pad 20] ------
__global__ void prep_ow(const float* __restrict__ ow) {
    int i = blockIdx.x * 256 + threadIdx.x;          // over 256*9*20
    if (i >= CIN * KTAP * 20) return;
    int j = i % 20;
    int t = (i / 20) % KTAP;
    int c = i / 180;
    g_owT[i] = (j < OFFC) ? ow[j * (CIN * KTAP) + c * KTAP + t] : 0.0f;
}

// ---------------- transpose x [b][c][hw] -> [b][hw][c] -----------------------
__global__ void transpose_x(const float* __restrict__ x) {
    __shared__ float t[32][33];
    int b   = blockIdx.z;
    int hw0 = blockIdx.x * 32;
    int c0  = blockIdx.y * 32;
    int tx  = threadIdx.x, ty = threadIdx.y;
    #pragma unroll
    for (int i = ty; i < 32; i += 8)
        t[i][tx] = x[((b * CIN + c0 + i) << 12) + hw0 + tx];
    __syncthreads();
    #pragma unroll
    for (int i = ty; i < 32; i += 8)
        g_xt[(size_t)((b << 12) + hw0 + i) * CIN + c0 + tx] = t[tx][i];
}

// ---------------- offset conv: 3x3, pad 1, 256 -> 18 (+bias) -----------------
// grid (H, B), block 64 (thread = w). Weights staged through smem.
__global__ void offset_conv(const float* __restrict__ x, const float* __restrict__ bias) {
    __shared__ float ws[64 * KTAP * 20];   // 46080 B
    int hh = blockIdx.x;
    int b  = blockIdx.y;
    int w  = threadIdx.x;

    float acc[20];
    #pragma unroll
    for (int o = 0; o < 20; ++o) acc[o] = (o < OFFC) ? bias[o] : 0.0f;

    for (int c0 = 0; c0 < CIN; c0 += 64) {
        __syncthreads();
        const float4* src = (const float4*)(g_owT + c0 * (KTAP * 20));
        float4* dst = (float4*)ws;
        for (int i = w; i < 64 * KTAP * 20 / 4; i += 64) dst[i] = src[i];
        __syncthreads();

        for (int cc = 0; cc < 64; ++cc) {
            int c = c0 + cc;
            float xv[9];
            #pragma unroll
            for (int dy = 0; dy < 3; ++dy) {
                int yy = hh + dy - 1;
                #pragma unroll
                for (int dx = 0; dx < 3; ++dx) {
                    int xx = w + dx - 1;
                    bool ok = (yy >= 0) && (yy < HH) && (xx >= 0) && (xx < WW);
                    xv[dy * 3 + dx] = ok ? x[((b * CIN + c) * HH + yy) * WW + xx] : 0.0f;
                }
            }
            #pragma unroll
            for (int t = 0; t < KTAP; ++t) {
                const float4* wv = (const float4*)&ws[(cc * KTAP + t) * 20];
                float v = xv[t];
                #pragma unroll
                for (int q = 0; q < 5; ++q) {
                    float4 wq = wv[q];
                    acc[4 * q + 0] += v * wq.x;
                    acc[4 * q + 1] += v * wq.y;
                    acc[4 * q + 2] += v * wq.z;
                    acc[4 * q + 3] += v * wq.w;
                }
            }
        }
    }
    int hw = hh * WW + w;
    #pragma unroll
    for (int o = 0; o < OFFC; ++o)
        g_offs[(b * OFFC + o) * HWSZ + hw] = acc[o];
}

// ---------------- deformable conv as implicit GEMM ----------------------------
// out[b][o][hw] = sum_{k,c} samp(b,k,hw,c) * wT[k][c][o]
// Block: 64 m-positions x 256 outputs. 256 threads, 4x16 per-thread tile.
__global__ __launch_bounds__(256, 2) void deform_gemm(float* __restrict__ out) {
    __shared__ float As[16][68];
    __shared__ float Bs[16][256];
    __shared__ float cwgt[576][4];
    __shared__ int   cidx[576][4];

    int tile = blockIdx.x;         // 0..255
    int b    = tile >> 6;
    int hw0  = (tile & 63) << 6;
    int tid  = threadIdx.x;

    // precompute bilinear corners for 64 positions x 9 taps
    for (int e = tid; e < 576; e += 256) {
        int ml = e / 9, k = e - ml * 9;
        int hw = hw0 + ml;
        int hh = hw >> 6, wp = hw & 63;
        float dy = g_offs[(b * OFFC + 2 * k) * HWSZ + hw];
        float dx = g_offs[(b * OFFC + 2 * k + 1) * HWSZ + hw];
        int ky = k / 3, kx = k - ky * 3;
        float py = (float)(hh - 1 + ky) + dy;
        float px = (float)(wp - 1 + kx) + dx;
        float y0f = floorf(py), x0f = floorf(px);
        float ty = py - y0f, tx = px - x0f;
        int y0 = (int)y0f, x0 = (int)x0f;
        #pragma unroll
        for (int j = 0; j < 4; ++j) {
            int yj = y0 + (j >> 1);
            int xj = x0 + (j & 1);
            float wj = ((j >> 1) ? ty : 1.0f - ty) * ((j & 1) ? tx : 1.0f - tx);
            bool ok = (yj >= 0) && (yj < HH) && (xj >= 0) && (xj < WW);
            cwgt[e][j] = ok ? wj : 0.0f;
            cidx[e][j] = ok ? (yj * WW + xj) * CIN : 0;
        }
    }
    __syncthreads();

    float acc[4][16];
    #pragma unroll
    for (int i = 0; i < 4; ++i)
        #pragma unroll
        for (int j = 0; j < 16; ++j) acc[i][j] = 0.0f;

    int my = tid >> 4;   // 0..15 -> m base my*4
    int tx = tid & 15;   // o quad base

    const float* xtb = g_xt + (size_t)b * HWSZ * CIN;

    for (int k = 0; k < KTAP; ++k) {
        for (int c0 = 0; c0 < CIN; c0 += 16) {
            __syncthreads();
            // load B tile (coalesced from pre-transposed weights)
            {
                const float4* src = (const float4*)(g_wT + ((size_t)k * CIN + c0) * COUT);
                float4* dst = (float4*)&Bs[0][0];
                #pragma unroll
                for (int r = 0; r < 4; ++r) dst[tid + 256 * r] = src[tid + 256 * r];
            }
            // build A tile: bilinear samples, coalesced over c
            {
                int cc = tid & 15, mg = tid >> 4;
                const float* base = xtb + (c0 + cc);
                #pragma unroll
                for (int it = 0; it < 4; ++it) {
                    int m = mg * 4 + it;
                    int e = m * 9 + k;
                    float v = cwgt[e][0] * base[cidx[e][0]]
                            + cwgt[e][1] * base[cidx[e][1]]
                            + cwgt[e][2] * base[cidx[e][2]]
                            + cwgt[e][3] * base[cidx[e][3]];
                    As[cc][m] = v;
                }
            }
            __syncthreads();
            // 64x256x16 MMA on CUDA cores
            #pragma unroll
            for (int cc = 0; cc < 16; ++cc) {
                float4 a = *(const float4*)&As[cc][my * 4];
                float av[4] = {a.x, a.y, a.z, a.w};
                #pragma unroll
                for (int g = 0; g < 4; ++g) {
                    float4 bv = *(const float4*)&Bs[cc][(tx << 2) + (g << 6)];
                    #pragma unroll
                    for (int i = 0; i < 4; ++i) {
                        acc[i][g * 4 + 0] += av[i] * bv.x;
                        acc[i][g * 4 + 1] += av[i] * bv.y;
                        acc[i][g * 4 + 2] += av[i] * bv.z;
                        acc[i][g * 4 + 3] += av[i] * bv.w;
                    }
                }
            }
        }
    }

    // store (pre-GroupNorm) into d_out
    #pragma unroll
    for (int i = 0; i < 4; ++i) {
        int m = my * 4 + i;
        #pragma unroll
        for (int g = 0; g < 4; ++g)
            #pragma unroll
            for (int j = 0; j < 4; ++j) {
                int o = (tx << 2) + j + (g << 6);
                out[((size_t)(b * COUT + o) << 12) + hw0 + m] = acc[i][g * 4 + j];
            }
    }
}

// ---------------- GroupNorm stats (deterministic block reduce) ----------------
__global__ void gn_stats(const float* __restrict__ out) {
    int bg = blockIdx.x;           // 0..127
    int b = bg >> 5, g = bg & 31;
    const float* p = out + ((size_t)(b * COUT + g * CPG) << 12);
    float s = 0.0f, sq = 0.0f;
    for (int i = threadIdx.x; i < CPG * HWSZ; i += 256) {
        float v = p[i];
        s += v; sq += v * v;
    }
    __shared__ float rs[256], rq[256];
    rs[threadIdx.x] = s; rq[threadIdx.x] = sq;
    __syncthreads();
    for (int off = 128; off > 0; off >>= 1) {
        if (threadIdx.x < off) {
            rs[threadIdx.x] += rs[threadIdx.x + off];
            rq[threadIdx.x] += rq[threadIdx.x + off];
        }
        __syncthreads();
    }
    if (threadIdx.x == 0) {
        float n = (float)(CPG * HWSZ);
        float mean = rs[0] / n;
        float var = rq[0] / n - mean * mean;
        g_stats[bg * 2 + 0] = mean;
        g_stats[bg * 2 + 1] = rsqrtf(var + EPS);
    }
}

// ---------------- GroupNorm apply + ReLU (in place) ---------------------------
__global__ void gn_apply(float* __restrict__ out,
                         const float* __restrict__ gamma,
                         const float* __restrict__ beta) {
    int idx = blockIdx.x * 256 + threadIdx.x;     // 4*256*4096 total
    int c = (idx >> 12) & 255;
    int b = idx >> 20;
    int bg = b * GN_GROUPS + (c >> 3);
    float mean = g_stats[bg * 2 + 0];
    float rstd = g_stats[bg * 2 + 1];
    float v = (out[idx] - mean) * rstd * gamma[c] + beta[c];
    out[idx] = fmaxf(v, 0.0f);
}

// ---------------- launch ------------------------------------------------------
extern "C" void kernel_launch(void* const* d_in, const int* in_sizes, int n_in,
                              void* d_out, int out_size) {
    const float* x   = (const float*)d_in[0];   // [4,256,64,64]
    const float* ow  = (const float*)d_in[1];   // [18,256,3,3]
    const float* ob  = (const float*)d_in[2];   // [18]
    const float* dw  = (const float*)d_in[3];   // [256,256,3,3]
    const float* gam = (const float*)d_in[4];   // [256]
    const float* bet = (const float*)d_in[5];   // [256]
    float* out = (float*)d_out;                 // [4,256,64,64]

    prep_w<<<(KTAP * CIN * COUT + 255) / 256, 256>>>(dw);
    prep_ow<<<(CIN * KTAP * 20 + 255) / 256, 256>>>(ow);
    transpose_x<<<dim3(HWSZ / 32, CIN / 32, NB), dim3(32, 8)>>>(x);
    offset_conv<<<dim3(HH, NB), 64>>>(x, ob);
    deform_gemm<<<256, 256>>>(out);
    gn_stats<<<NB * GN_GROUPS, 256>>>(out);
    gn_apply<<<(NB * COUT * HWSZ) / 256, 256>>>(out, gam, bet);
}

// round 4
// speedup vs baseline: 1.0599x; 1.0599x over previous
#include <cuda_runtime.h>
#include <cuda_bf16.h>

// Problem constants
#define NB   4
#define CIN  256
#define COUT 256
#define HH   64
#define WW   64
#define HWSZ 4096            // 64*64
#define KTAP 9
#define OFFC 18
#define GN_GROUPS 32
#define CPG  8               // channels per group
#define EPS  1e-5f

typedef unsigned long long u64;

// ---------------- scratch (__device__ globals; no allocations) ----------------
__device__ float g_xt[NB * HWSZ * CIN];        // x transposed to [b][hw][c]  (16 MB)
__device__ float g_offs[NB * OFFC * HWSZ];     // offset conv output [b][ch][hw]
__device__ float g_wT[KTAP * CIN * COUT];      // deform weight [k][c][o]
__device__ float g_owT[CIN * KTAP * 20];       // offset weight [c][tap][o pad 20]
__device__ float g_stats[NB * GN_GROUPS * 2];  // (mean, rstd) per (b,g)

// ---------------- prep: transpose deform weight [o][c][k] -> [k][c][o] -------
__global__ void prep_w(const float* __restrict__ dw) {
    int i = blockIdx.x * 256 + threadIdx.x;          // over 9*256*256
    if (i >= KTAP * CIN * COUT) return;
    int o = i & 255;
    int c = (i >> 8) & 255;
    int k = i >> 16;
    g_wT[i] = dw[o * (CIN * KTAP) + c * KTAP + k];
}

// ---------------- prep: offset weight [o][c][tap] -> [c][tap][o pad 20] ------
__global__ void prep_ow(const float* __restrict__ ow) {
    int i = blockIdx.x * 256 + threadIdx.x;          // over 256*9*20
    if (i >= CIN * KTAP * 20) return;
    int j = i % 20;
    int t = (i / 20) % KTAP;
    int c = i / 180;
    g_owT[i] = (j < OFFC) ? ow[j * (CIN * KTAP) + c * KTAP + t] : 0.0f;
}

// ---------------- transpose x [b][c][hw] -> [b][hw][c] -----------------------
__global__ void transpose_x(const float* __restrict__ x) {
    __shared__ float t[32][33];
    int b   = blockIdx.z;
    int hw0 = blockIdx.x * 32;
    int c0  = blockIdx.y * 32;
    int tx  = threadIdx.x, ty = threadIdx.y;
    #pragma unroll
    for (int i = ty; i < 32; i += 8)
        t[i][tx] = x[((b * CIN + c0 + i) << 12) + hw0 + tx];
    __syncthreads();
    #pragma unroll
    for (int i = ty; i < 32; i += 8)
        g_xt[(size_t)((b << 12) + hw0 + i) * CIN + c0 + tx] = t[tx][i];
}

// ---------------- offset conv v2: 3x3, pad 1, 256 -> 18 (+bias) --------------
// grid (H, B), block 512 = 64 w-positions x 8 c-groups (32 c each).
// Weights staged through smem per 4-c sub-chunk; smem reduce across c-groups.
__global__ __launch_bounds__(512) void offset_conv(const float* __restrict__ x,
                                                   const float* __restrict__ bias) {
    __shared__ float sbuf[9216];   // 36 KB: reused as ws (5760) then red (9216)
    int hh  = blockIdx.x;
    int b   = blockIdx.y;
    int tid = threadIdx.x;
    int w   = tid & 63;
    int cg  = tid >> 6;            // 0..7

    // precompute 9 taps: validity + clamped index within a channel plane
    int  off9[9];
    bool ok9[9];
    #pragma unroll
    for (int t = 0; t < KTAP; ++t) {
        int ky = t / 3, kx = t - ky * 3;
        int yy = hh + ky - 1, xx = w + kx - 1;
        bool ok = (yy >= 0) && (yy < HH) && (xx >= 0) && (xx < WW);
        ok9[t]  = ok;
        off9[t] = ok ? (yy * WW + xx) : 0;
    }

    const float* xb = x + ((size_t)(b * CIN) << 12);

    float acc[20];
    #pragma unroll
    for (int o = 0; o < 20; ++o) acc[o] = 0.0f;

    for (int ch = 0; ch < 8; ++ch) {      // 4 channels per c-group per stage
        __syncthreads();
        // stage weights: for each cgx, 720 consecutive floats starting at
        // g_owT[(cgx*32 + ch*4)*180]  ->  sbuf[cgx*720]
        for (int i = tid; i < 1440; i += 512) {          // float4 granularity
            int cgx = i / 180;
            int r   = i - cgx * 180;
            ((float4*)sbuf)[i] =
                ((const float4*)(g_owT + (size_t)(cgx * 32 + ch * 4) * 180))[r];
        }
        __syncthreads();

        const float* wsg = sbuf + cg * 720;
        #pragma unroll
        for (int cc = 0; cc < 4; ++cc) {
            int c = cg * 32 + ch * 4 + cc;
            const float* xc = xb + ((size_t)c << 12);
            float xv[9];
            #pragma unroll
            for (int t = 0; t < KTAP; ++t)
                xv[t] = ok9[t] ? xc[off9[t]] : 0.0f;
            #pragma unroll
            for (int t = 0; t < KTAP; ++t) {
                const float4* wv = (const float4*)&wsg[(cc * 9 + t) * 20];
                float v = xv[t];
                #pragma unroll
                for (int q = 0; q < 5; ++q) {
                    float4 wq = wv[q];
                    acc[4 * q + 0] += v * wq.x;
                    acc[4 * q + 1] += v * wq.y;
                    acc[4 * q + 2] += v * wq.z;
                    acc[4 * q + 3] += v * wq.w;
                }
            }
        }
    }

    // reduce partials across the 8 c-groups
    __syncthreads();
    #pragma unroll
    for (int o = 0; o < OFFC; ++o)
        sbuf[(cg * 64 + w) * OFFC + o] = acc[o];
    __syncthreads();
    for (int e = tid; e < 64 * OFFC; e += 512) {
        int ww = e / OFFC, o = e - ww * OFFC;
        float s = bias[o];
        #pragma unroll
        for (int g2 = 0; g2 < 8; ++g2)
            s += sbuf[(g2 * 64 + ww) * OFFC + o];
        g_offs[(b * OFFC + o) * HWSZ + hh * WW + ww] = s;
    }
}

// ---------------- deformable conv as implicit GEMM (f32x2 FMA) ----------------
// out[b][o][hw] = sum_{k,c} samp(b,k,hw,c) * wT[k][c][o]
// Block: 64 m-positions x 256 outputs. 256 threads, 4m x 16o per thread,
// o packed in pairs for fma.rn.f32x2 (dual-lane fp32 FMA).
__global__ __launch_bounds__(256, 2) void deform_gemm(float* __restrict__ out) {
    __shared__ float As[16][68];
    __shared__ float Bs[16][256];
    __shared__ float cwgt[576][4];
    __shared__ int   cidx[576][4];

    int tile = blockIdx.x;         // 0..255
    int b    = tile >> 6;
    int hw0  = (tile & 63) << 6;
    int tid  = threadIdx.x;

    // precompute bilinear corners for 64 positions x 9 taps
    for (int e = tid; e < 576; e += 256) {
        int ml = e / 9, k = e - ml * 9;
        int hw = hw0 + ml;
        int hh = hw >> 6, wp = hw & 63;
        float dy = g_offs[(b * OFFC + 2 * k) * HWSZ + hw];
        float dx = g_offs[(b * OFFC + 2 * k + 1) * HWSZ + hw];
        int ky = k / 3, kx = k - ky * 3;
        float py = (float)(hh - 1 + ky) + dy;
        float px = (float)(wp - 1 + kx) + dx;
        float y0f = floorf(py), x0f = floorf(px);
        float ty = py - y0f, tx = px - x0f;
        int y0 = (int)y0f, x0 = (int)x0f;
        #pragma unroll
        for (int j = 0; j < 4; ++j) {
            int yj = y0 + (j >> 1);
            int xj = x0 + (j & 1);
            float wj = ((j >> 1) ? ty : 1.0f - ty) * ((j & 1) ? tx : 1.0f - tx);
            bool ok = (yj >= 0) && (yj < HH) && (xj >= 0) && (xj < WW);
            cwgt[e][j] = ok ? wj : 0.0f;
            cidx[e][j] = ok ? (yj * WW + xj) * CIN : 0;
        }
    }
    __syncthreads();

    u64 acc2[4][8];                 // 4 m rows x 8 o-pairs (o pair = 2 floats)
    #pragma unroll
    for (int i = 0; i < 4; ++i)
        #pragma unroll
        for (int j = 0; j < 8; ++j) acc2[i][j] = 0ULL;

    int my = tid >> 4;   // 0..15 -> m base my*4
    int tx = tid & 15;   // o quad base

    const float* xtb = g_xt + (size_t)b * HWSZ * CIN;

    for (int k = 0; k < KTAP; ++k) {
        for (int c0 = 0; c0 < CIN; c0 += 16) {
            __syncthreads();
            // load B tile (coalesced from pre-transposed weights)
            {
                const float4* src = (const float4*)(g_wT + ((size_t)k * CIN + c0) * COUT);
                float4* dst = (float4*)&Bs[0][0];
                #pragma unroll
                for (int r = 0; r < 4; ++r) dst[tid + 256 * r] = src[tid + 256 * r];
            }
            // build A tile: bilinear samples, coalesced over c
            {
                int cc = tid & 15, mg = tid >> 4;
                const float* base = xtb + (c0 + cc);
                #pragma unroll
                for (int it = 0; it < 4; ++it) {
                    int m = mg * 4 + it;
                    int e = m * 9 + k;
                    float v = cwgt[e][0] * base[cidx[e][0]]
                            + cwgt[e][1] * base[cidx[e][1]]
                            + cwgt[e][2] * base[cidx[e][2]]
                            + cwgt[e][3] * base[cidx[e][3]];
                    As[cc][m] = v;
                }
            }
            __syncthreads();
            // 64x256x16 MMA on CUDA cores, packed f32x2
            #pragma unroll
            for (int cc = 0; cc < 16; ++cc) {
                float4 a = *(const float4*)&As[cc][my * 4];
                u64 ad[4];
                asm("mov.b64 %0, {%1, %1};" : "=l"(ad[0]) : "f"(a.x));
                asm("mov.b64 %0, {%1, %1};" : "=l"(ad[1]) : "f"(a.y));
                asm("mov.b64 %0, {%1, %1};" : "=l"(ad[2]) : "f"(a.z));
                asm("mov.b64 %0, {%1, %1};" : "=l"(ad[3]) : "f"(a.w));
                const u64* brow = (const u64*)&Bs[cc][0];
                #pragma unroll
                for (int g = 0; g < 4; ++g) {
                    u64 b0 = brow[(tx << 1) + (g << 5)];
                    u64 b1 = brow[(tx << 1) + (g << 5) + 1];
                    #pragma unroll
                    for (int i = 0; i < 4; ++i) {
                        asm("fma.rn.f32x2 %0, %1, %2, %0;"
                            : "+l"(acc2[i][g * 2 + 0]) : "l"(ad[i]), "l"(b0));
                        asm("fma.rn.f32x2 %0, %1, %2, %0;"
                            : "+l"(acc2[i][g * 2 + 1]) : "l"(ad[i]), "l"(b1));
                    }
                }
            }
        }
    }

    // store (pre-GroupNorm) into d_out
    #pragma unroll
    for (int i = 0; i < 4; ++i) {
        int m = my * 4 + i;
        #pragma unroll
        for (int g = 0; g < 4; ++g)
            #pragma unroll
            for (int h = 0; h < 2; ++h) {
                float lo, hi;
                asm("mov.b64 {%0, %1}, %2;" : "=f"(lo), "=f"(hi)
                    : "l"(acc2[i][g * 2 + h]));
                int o = (tx << 2) + (g << 6) + 2 * h;
                out[((size_t)(b * COUT + o) << 12) + hw0 + m]       = lo;
                out[((size_t)(b * COUT + o + 1) << 12) + hw0 + m]   = hi;
            }
    }
}

// ---------------- GroupNorm stats (deterministic block reduce) ----------------
__global__ void gn_stats(const float* __restrict__ out) {
    int bg = blockIdx.x;           // 0..127
    int b = bg >> 5, g = bg & 31;
    const float* p = out + ((size_t)(b * COUT + g * CPG) << 12);
    float s = 0.0f, sq = 0.0f;
    for (int i = threadIdx.x; i < CPG * HWSZ; i += 256) {
        float v = p[i];
        s += v; sq += v * v;
    }
    __shared__ float rs[256], rq[256];
    rs[threadIdx.x] = s; rq[threadIdx.x] = sq;
    __syncthreads();
    for (int off = 128; off > 0; off >>= 1) {
        if (threadIdx.x < off) {
            rs[threadIdx.x] += rs[threadIdx.x + off];
            rq[threadIdx.x] += rq[threadIdx.x + off];
        }
        __syncthreads();
    }
    if (threadIdx.x == 0) {
        float n = (float)(CPG * HWSZ);
        float mean = rs[0] / n;
        float var = rq[0] / n - mean * mean;
        g_stats[bg * 2 + 0] = mean;
        g_stats[bg * 2 + 1] = rsqrtf(var + EPS);
    }
}

// ---------------- GroupNorm apply + ReLU (in place) ---------------------------
__global__ void gn_apply(float* __restrict__ out,
                         const float* __restrict__ gamma,
                         const float* __restrict__ beta) {
    int idx = blockIdx.x * 256 + threadIdx.x;     // 4*256*4096 total
    int c = (idx >> 12) & 255;
    int b = idx >> 20;
    int bg = b * GN_GROUPS + (c >> 3);
    float mean = g_stats[bg * 2 + 0];
    float rstd = g_stats[bg * 2 + 1];
    float v = (out[idx] - mean) * rstd * gamma[c] + beta[c];
    out[idx] = fmaxf(v, 0.0f);
}

// ---------------- launch ------------------------------------------------------
extern "C" void kernel_launch(void* const* d_in, const int* in_sizes, int n_in,
                              void* d_out, int out_size) {
    const float* x   = (const float*)d_in[0];   // [4,256,64,64]
    const float* ow  = (const float*)d_in[1];   // [18,256,3,3]
    const float* ob  = (const float*)d_in[2];   // [18]
    const float* dw  = (const float*)d_in[3];   // [256,256,3,3]
    const float* gam = (const float*)d_in[4];   // [256]
    const float* bet = (const float*)d_in[5];   // [256]
    float* out = (float*)d_out;                 // [4,256,64,64]

    prep_w<<<(KTAP * CIN * COUT + 255) / 256, 256>>>(dw);
    prep_ow<<<(CIN * KTAP * 20 + 255) / 256, 256>>>(ow);
    transpose_x<<<dim3(HWSZ / 32, CIN / 32, NB), dim3(32, 8)>>>(x);
    offset_conv<<<dim3(HH, NB), 512>>>(x, ob);
    deform_gemm<<<256, 256>>>(out);
    gn_stats<<<NB * GN_GROUPS, 256>>>(out);
    gn_apply<<<(NB * COUT * HWSZ) / 256, 256>>>(out, gam, bet);
}

// round 7
// speedup vs baseline: 2.2760x; 2.1473x over previous
#include <cuda_runtime.h>
#include <cuda_bf16.h>
#include <cstdint>

#define NB   4
#define CIN  256
#define COUT 256
#define HH   64
#define WW   64
#define HWSZ 4096
#define KTAP 9
#define OFFC 18
#define GN_GROUPS 32
#define CPG  8
#define EPS  1e-5f

// ---------------- scratch ----------------
__device__ float g_xt[NB * HWSZ * CIN];              // x as [b][hw][c]
__device__ float g_offs[NB * OFFC * HWSZ];           // offsets [b][ch][hw]
__device__ float g_owT[CIN * KTAP * 20];             // offset weights [c][tap][o pad20]
__device__ __nv_bfloat16 g_wbf_hi[KTAP * 4 * 16384]; // weight hi, SW128 tiles [tap*4+cc][256n x 64k]
__device__ __nv_bfloat16 g_wbf_lo[KTAP * 4 * 16384]; // weight lo
__device__ float g_stats[NB * GN_GROUPS * 2];

__device__ __forceinline__ uint32_t smem_u32(const void* p) {
    uint32_t a;
    asm("{ .reg .u64 t; cvta.to.shared.u64 t, %1; cvt.u32.u64 %0, t; }" : "=r"(a) : "l"(p));
    return a;
}
__device__ __forceinline__ uint32_t swz128(uint32_t b) { return b ^ ((b >> 3) & 0x70); }

#define LDSM4(r0,r1,r2,r3,addr) \
    asm volatile("ldmatrix.sync.aligned.m8n8.x4.shared.b16 {%0,%1,%2,%3}, [%4];" \
        : "=r"(r0),"=r"(r1),"=r"(r2),"=r"(r3) : "r"(addr))

#define MMA16816(d, a, b0, b1) \
    asm volatile("mma.sync.aligned.m16n8k16.row.col.f32.bf16.bf16.f32 " \
        "{%0,%1,%2,%3}, {%4,%5,%6,%7}, {%8,%9}, {%0,%1,%2,%3};" \
        : "+f"((d)[0]),"+f"((d)[1]),"+f"((d)[2]),"+f"((d)[3]) \
        : "r"((a)[0]),"r"((a)[1]),"r"((a)[2]),"r"((a)[3]),"r"(b0),"r"(b1))

// ---------------- prep: offset weight [o][c][tap] -> [c][tap][o pad 20] ------
__global__ void prep_ow(const float* __restrict__ ow) {
    int i = blockIdx.x * 256 + threadIdx.x;
    if (i >= CIN * KTAP * 20) return;
    int j = i % 20;
    int t = (i / 20) % KTAP;
    int c = i / 180;
    g_owT[i] = (j < OFFC) ? ow[j * (CIN * KTAP) + c * KTAP + t] : 0.0f;
}

// ---------------- prep: deform weight -> bf16 hi/lo, SW128-swizzled ----------
// tile (t, cc): [n 0..255][k 0..63], value = dw[n][cc*64+k][t]
__global__ void prep_wbf(const float* __restrict__ dw) {
    int i = blockIdx.x * 256 + threadIdx.x;     // over 9*4*16384
    if (i >= KTAP * 4 * 16384) return;
    int t  = i >> 16;
    int r  = i & 65535;
    int cc = r >> 14;
    int r2 = r & 16383;
    int n  = r2 >> 6;
    int k  = r2 & 63;
    float v = dw[n * (CIN * KTAP) + (cc * 64 + k) * KTAP + t];
    __nv_bfloat16 hi = __float2bfloat16(v);
    __nv_bfloat16 lo = __float2bfloat16(v - __bfloat162float(hi));
    uint32_t sw = swz128((uint32_t)(n * 128 + k * 2)) >> 1;   // element index
    int base = (t * 4 + cc) * 16384;
    g_wbf_hi[base + sw] = hi;
    g_wbf_lo[base + sw] = lo;
}

// ---------------- transpose x [b][c][hw] -> [b][hw][c] -----------------------
__global__ void transpose_x(const float* __restrict__ x) {
    __shared__ float t[32][33];
    int b   = blockIdx.z;
    int hw0 = blockIdx.x * 32;
    int c0  = blockIdx.y * 32;
    int tx  = threadIdx.x, ty = threadIdx.y;
    #pragma unroll
    for (int i = ty; i < 32; i += 8)
        t[i][tx] = x[((b * CIN + c0 + i) << 12) + hw0 + tx];
    __syncthreads();
    #pragma unroll
    for (int i = ty; i < 32; i += 8)
        g_xt[(size_t)((b << 12) + hw0 + i) * CIN + c0 + tx] = t[tx][i];
}

// ---------------- offset conv: 3x3, pad1, 256->18 (+bias) --------------------
__global__ __launch_bounds__(512) void offset_conv(const float* __restrict__ x,
                                                   const float* __restrict__ bias) {
    __shared__ float sbuf[9216];
    int hh  = blockIdx.x;
    int b   = blockIdx.y;
    int tid = threadIdx.x;
    int w   = tid & 63;
    int cg  = tid >> 6;

    int  off9[9];
    bool ok9[9];
    #pragma unroll
    for (int t = 0; t < KTAP; ++t) {
        int ky = t / 3, kx = t - ky * 3;
        int yy = hh + ky - 1, xx = w + kx - 1;
        bool ok = (yy >= 0) && (yy < HH) && (xx >= 0) && (xx < WW);
        ok9[t]  = ok;
        off9[t] = ok ? (yy * WW + xx) : 0;
    }

    const float* xb = x + ((size_t)(b * CIN) << 12);
    float acc[20];
    #pragma unroll
    for (int o = 0; o < 20; ++o) acc[o] = 0.0f;

    for (int ch = 0; ch < 8; ++ch) {
        __syncthreads();
        for (int i = tid; i < 1440; i += 512) {
            int cgx = i / 180;
            int r   = i - cgx * 180;
            ((float4*)sbuf)[i] =
                ((const float4*)(g_owT + (size_t)(cgx * 32 + ch * 4) * 180))[r];
        }
        __syncthreads();
        const float* wsg = sbuf + cg * 720;
        #pragma unroll
        for (int cc = 0; cc < 4; ++cc) {
            int c = cg * 32 + ch * 4 + cc;
            const float* xc = xb + ((size_t)c << 12);
            float xv[9];
            #pragma unroll
            for (int t = 0; t < KTAP; ++t)
                xv[t] = ok9[t] ? xc[off9[t]] : 0.0f;
            #pragma unroll
            for (int t = 0; t < KTAP; ++t) {
                const float4* wv = (const float4*)&wsg[(cc * 9 + t) * 20];
                float v = xv[t];
                #pragma unroll
                for (int q = 0; q < 5; ++q) {
                    float4 wq = wv[q];
                    acc[4*q+0] += v * wq.x; acc[4*q+1] += v * wq.y;
                    acc[4*q+2] += v * wq.z; acc[4*q+3] += v * wq.w;
                }
            }
        }
    }
    __syncthreads();
    #pragma unroll
    for (int o = 0; o < OFFC; ++o)
        sbuf[(cg * 64 + w) * OFFC + o] = acc[o];
    __syncthreads();
    for (int e = tid; e < 64 * OFFC; e += 512) {
        int ww = e / OFFC, o = e - ww * OFFC;
        float s = bias[o];
        #pragma unroll
        for (int g2 = 0; g2 < 8; ++g2)
            s += sbuf[(g2 * 64 + ww) * OFFC + o];
        g_offs[(b * OFFC + o) * HWSZ + hh * WW + ww] = s;
    }
}

// ---------------- deformable conv: mma.sync bf16-split implicit GEMM ---------
// 128 CTAs x 512 threads. CTA tile: 128 m x 256 n. 16 warps: 4m x 4n,
// warp tile 32m x 64n, mma m16n8k16. K = 9 taps x 4 chunks of 64 c.
// Per chunk: copy pre-swizzled B hi/lo, build bilinear A hi/lo, 3-product MMA.
#define S_CW   0                          // cwgt[1152][4] floats (18432 B)
#define S_CI   18432                      // cidx[1152][4] ints   (18432 B)
#define S_AHI  36864                      // 128 x 128B
#define S_ALO  (S_AHI + 16384)
#define S_BHI  (S_ALO + 16384)            // 256 x 128B
#define S_BLO  (S_BHI + 32768)
#define S_TOT  (S_BLO + 32768)            // 135168 B

__global__ __launch_bounds__(512, 1) void deform_gemm(float* __restrict__ out) {
    extern __shared__ char smem[];
    uint32_t sb = smem_u32(smem);
    int tid = threadIdx.x;
    int wid = tid >> 5;
    int lid = tid & 31;
    int mw  = wid & 3;        // m-warp 0..3
    int nw  = wid >> 2;       // n-warp 0..3

    int tile = blockIdx.x;    // 0..127
    int b    = tile >> 5;
    int hw0  = (tile & 31) << 7;

    float* cwgt = (float*)(smem + S_CW);
    int*   cidx = (int*)(smem + S_CI);

    // corner tables: 128 m x 9 taps x 4 corners
    for (int e = tid; e < 128 * KTAP; e += 512) {
        int ml = e / 9, k = e - ml * 9;
        int hw = hw0 + ml;
        int hh = hw >> 6, wp = hw & 63;
        float dy = g_offs[(b * OFFC + 2 * k) * HWSZ + hw];
        float dx = g_offs[(b * OFFC + 2 * k + 1) * HWSZ + hw];
        int ky = k / 3, kx = k - ky * 3;
        float py = (float)(hh - 1 + ky) + dy;
        float px = (float)(wp - 1 + kx) + dx;
        float y0f = floorf(py), x0f = floorf(px);
        float ty = py - y0f, tx = px - x0f;
        int y0 = (int)y0f, x0 = (int)x0f;
        #pragma unroll
        for (int j = 0; j < 4; ++j) {
            int yj = y0 + (j >> 1);
            int xj = x0 + (j & 1);
            float wj = ((j >> 1) ? ty : 1.0f - ty) * ((j & 1) ? tx : 1.0f - tx);
            bool ok = (yj >= 0) && (yj < HH) && (xj >= 0) && (xj < WW);
            cwgt[e * 4 + j] = ok ? wj : 0.0f;
            cidx[e * 4 + j] = ok ? (yj * WW + xj) * CIN : 0;
        }
    }

    const float* xtb = g_xt + (size_t)b * HWSZ * CIN;

    // per-thread ldmatrix address components
    int arow = mw * 32 + (lid & 15);            // + i*16
    uint32_t amask = (uint32_t)((arow & 7) * 16);
    uint32_t aoff  = (uint32_t)(arow * 128) + ((lid >> 4) ? 16u : 0u);  // col-half in low bits pre-xor? no:
    // keep halves separate: col byte = kk*32 + half*16, xor amask
    uint32_t ahalf = (lid >> 4) ? 16u : 0u;
    uint32_t abase = sb + (uint32_t)(arow * 128);

    int brow_in = (lid & 7) + ((lid >> 4) << 3);        // row within 16-n group
    uint32_t bmask = (uint32_t)((lid & 7) * 16);
    uint32_t bhalf = ((lid >> 3) & 1) ? 16u : 0u;
    uint32_t bbase = sb + (uint32_t)((nw * 64 + brow_in) * 128);

    float acc[2][8][4];
    #pragma unroll
    for (int i = 0; i < 2; ++i)
        #pragma unroll
        for (int j = 0; j < 8; ++j)
            #pragma unroll
            for (int q = 0; q < 4; ++q) acc[i][j][q] = 0.0f;

    for (int ch = 0; ch < 36; ++ch) {
        int t  = ch >> 2;
        int cc = ch & 3;
        __syncthreads();   // previous chunk's MMA reads done before overwrite

        // B tiles: straight copy of pre-swizzled bf16
        {
            const float4* sh = (const float4*)(g_wbf_hi + (size_t)ch * 16384);
            const float4* sl = (const float4*)(g_wbf_lo + (size_t)ch * 16384);
            float4* dh = (float4*)(smem + S_BHI);
            float4* dl = (float4*)(smem + S_BLO);
            #pragma unroll
            for (int r = 0; r < 4; ++r) {
                dh[tid + 512 * r] = sh[tid + 512 * r];
                dl[tid + 512 * r] = sl[tid + 512 * r];
            }
        }
        // A tiles: bilinear sample 128m x 64c, split bf16 hi/lo, swizzled store
        {
            int c0 = cc * 64;
            #pragma unroll
            for (int it = 0; it < 4; ++it) {
                int e = it * 512 + tid;        // 0..2047
                int m = e >> 4;
                int q = e & 15;                // c-quad
                int ce = (m * 9 + t) * 4;
                float4 w = *(const float4*)&cwgt[ce];
                const float* base = xtb + c0 + q * 4;
                float4 s0 = *(const float4*)(base + cidx[ce + 0]);
                float4 s1 = *(const float4*)(base + cidx[ce + 1]);
                float4 s2 = *(const float4*)(base + cidx[ce + 2]);
                float4 s3 = *(const float4*)(base + cidx[ce + 3]);
                float v0 = w.x*s0.x + w.y*s1.x + w.z*s2.x + w.w*s3.x;
                float v1 = w.x*s0.y + w.y*s1.y + w.z*s2.y + w.w*s3.y;
                float v2 = w.x*s0.z + w.y*s1.z + w.z*s2.z + w.w*s3.z;
                float v3 = w.x*s0.w + w.y*s1.w + w.z*s2.w + w.w*s3.w;
                __nv_bfloat16 h0 = __float2bfloat16(v0);
                __nv_bfloat16 h1 = __float2bfloat16(v1);
                __nv_bfloat16 h2 = __float2bfloat16(v2);
                __nv_bfloat16 h3 = __float2bfloat16(v3);
                __nv_bfloat16 l0 = __float2bfloat16(v0 - __bfloat162float(h0));
                __nv_bfloat16 l1 = __float2bfloat16(v1 - __bfloat162float(h1));
                __nv_bfloat16 l2 = __float2bfloat16(v2 - __bfloat162float(h2));
                __nv_bfloat16 l3 = __float2bfloat16(v3 - __bfloat162float(h3));
                uint32_t sw = swz128((uint32_t)(m * 128 + q * 8));
                __nv_bfloat162* ph = (__nv_bfloat162*)(smem + S_AHI + sw);
                __nv_bfloat162* pl = (__nv_bfloat162*)(smem + S_ALO + sw);
                ph[0] = __nv_bfloat162(h0, h1);
                ph[1] = __nv_bfloat162(h2, h3);
                pl[0] = __nv_bfloat162(l0, l1);
                pl[1] = __nv_bfloat162(l2, l3);
            }
        }
        __syncthreads();

        // MMA: 4 k-steps of k16
        #pragma unroll
        for (int kk = 0; kk < 4; ++kk) {
            uint32_t acol = ((uint32_t)(kk * 32) + ahalf) ^ amask;
            uint32_t a_hi[2][4], a_lo[2][4];
            #pragma unroll
            for (int i = 0; i < 2; ++i) {
                uint32_t aa = abase + (uint32_t)(i * 2048) + acol;
                LDSM4(a_hi[i][0], a_hi[i][1], a_hi[i][2], a_hi[i][3], aa + S_AHI);
                LDSM4(a_lo[i][0], a_lo[i][1], a_lo[i][2], a_lo[i][3], aa + S_ALO);
            }
            uint32_t bcol = ((uint32_t)(kk * 32) + bhalf) ^ bmask;
            #pragma unroll
            for (int j2 = 0; j2 < 4; ++j2) {
                uint32_t bb = bbase + (uint32_t)(j2 * 2048) + bcol;
                uint32_t bh[4], bl[4];
                LDSM4(bh[0], bh[1], bh[2], bh[3], bb + S_BHI);
                LDSM4(bl[0], bl[1], bl[2], bl[3], bb + S_BLO);
                #pragma unroll
                for (int i = 0; i < 2; ++i) {
                    MMA16816(acc[i][2*j2],   a_hi[i], bh[0], bh[1]);
                    MMA16816(acc[i][2*j2],   a_lo[i], bh[0], bh[1]);
                    MMA16816(acc[i][2*j2],   a_hi[i], bl[0], bl[1]);
                    MMA16816(acc[i][2*j2+1], a_hi[i], bh[2], bh[3]);
                    MMA16816(acc[i][2*j2+1], a_lo[i], bh[2], bh[3]);
                    MMA16816(acc[i][2*j2+1], a_hi[i], bl[2], bl[3]);
                }
            }
        }
    }

    // store accumulators to out [b][n][hw]
    int mrow = lid >> 2;          // 0..7
    int ncol = (lid & 3) * 2;
    #pragma unroll
    for (int i = 0; i < 2; ++i) {
        int m = hw0 + mw * 32 + i * 16 + mrow;
        #pragma unroll
        for (int j = 0; j < 8; ++j) {
            int n = nw * 64 + j * 8 + ncol;
            out[((size_t)(b * COUT + n)     << 12) + m]     = acc[i][j][0];
            out[((size_t)(b * COUT + n + 1) << 12) + m]     = acc[i][j][1];
            out[((size_t)(b * COUT + n)     << 12) + m + 8] = acc[i][j][2];
            out[((size_t)(b * COUT + n + 1) << 12) + m + 8] = acc[i][j][3];
        }
    }
}

// ---------------- GroupNorm stats ---------------------------------------------
__global__ void gn_stats(const float* __restrict__ out) {
    int bg = blockIdx.x;
    int b = bg >> 5, g = bg & 31;
    const float* p = out + ((size_t)(b * COUT + g * CPG) << 12);
    float s = 0.0f, sq = 0.0f;
    for (int i = threadIdx.x; i < CPG * HWSZ; i += 256) {
        float v = p[i];
        s += v; sq += v * v;
    }
    __shared__ float rs[256], rq[256];
    rs[threadIdx.x] = s; rq[threadIdx.x] = sq;
    __syncthreads();
    for (int off = 128; off > 0; off >>= 1) {
        if (threadIdx.x < off) {
            rs[threadIdx.x] += rs[threadIdx.x + off];
            rq[threadIdx.x] += rq[threadIdx.x + off];
        }
        __syncthreads();
    }
    if (threadIdx.x == 0) {
        float n = (float)(CPG * HWSZ);
        float mean = rs[0] / n;
        float var = rq[0] / n - mean * mean;
        g_stats[bg * 2 + 0] = mean;
        g_stats[bg * 2 + 1] = rsqrtf(var + EPS);
    }
}

// ---------------- GroupNorm apply + ReLU --------------------------------------
__global__ void gn_apply(float* __restrict__ out,
                         const float* __restrict__ gamma,
                         const float* __restrict__ beta) {
    int idx = blockIdx.x * 256 + threadIdx.x;
    int c = (idx >> 12) & 255;
    int b = idx >> 20;
    int bg = b * GN_GROUPS + (c >> 3);
    float mean = g_stats[bg * 2 + 0];
    float rstd = g_stats[bg * 2 + 1];
    float v = (out[idx] - mean) * rstd * gamma[c] + beta[c];
    out[idx] = fmaxf(v, 0.0f);
}

// ---------------- launch ------------------------------------------------------
extern "C" void kernel_launch(void* const* d_in, const int* in_sizes, int n_in,
                              void* d_out, int out_size) {
    const float* x   = (const float*)d_in[0];
    const float* ow  = (const float*)d_in[1];
    const float* ob  = (const float*)d_in[2];
    const float* dw  = (const float*)d_in[3];
    const float* gam = (const float*)d_in[4];
    const float* bet = (const float*)d_in[5];
    float* out = (float*)d_out;

    cudaFuncSetAttribute(deform_gemm, cudaFuncAttributeMaxDynamicSharedMemorySize, S_TOT);

    prep_ow<<<(CIN * KTAP * 20 + 255) / 256, 256>>>(ow);
    prep_wbf<<<(KTAP * 4 * 16384 + 255) / 256, 256>>>(dw);
    transpose_x<<<dim3(HWSZ / 32, CIN / 32, NB), dim3(32, 8)>>>(x);
    offset_conv<<<dim3(HH, NB), 512>>>(x, ob);
    deform_gemm<<<128, 512, S_TOT>>>(out);
    gn_stats<<<NB * GN_GROUPS, 256>>>(out);
    gn_apply<<<(NB * COUT * HWSZ) / 256, 256>>>(out, gam, bet);
}

// round 8
// speedup vs baseline: 2.3918x; 1.0509x over previous
#include <cuda_runtime.h>
#include <cuda_bf16.h>
#include <cstdint>

#define NB   4
#define CIN  256
#define COUT 256
#define HH   64
#define WW   64
#define HWSZ 4096
#define KTAP 9
#define OFFC 18
#define GN_GROUPS 32
#define CPG  8
#define EPS  1e-5f

// ---------------- scratch ----------------
__device__ float g_xt[NB * HWSZ * CIN];              // x as [b][hw][c]
__device__ float g_offs[NB * OFFC * HWSZ];           // offsets [b][ch][hw]
__device__ __nv_bfloat16 g_wbf_hi[KTAP * 4 * 16384]; // deform W hi, SW128 tiles [tap*4+cc][256n x 64k]
__device__ __nv_bfloat16 g_wbf_lo[KTAP * 4 * 16384]; // deform W lo
__device__ __nv_bfloat16 g_owbf_hi[KTAP * 4 * 2048]; // offset W hi, SW128 tiles [tap*4+cc][32n x 64k]
__device__ __nv_bfloat16 g_owbf_lo[KTAP * 4 * 2048]; // offset W lo
__device__ float g_stats[NB * GN_GROUPS * 2];

__device__ __forceinline__ uint32_t smem_u32(const void* p) {
    uint32_t a;
    asm("{ .reg .u64 t; cvta.to.shared.u64 t, %1; cvt.u32.u64 %0, t; }" : "=r"(a) : "l"(p));
    return a;
}
__device__ __forceinline__ uint32_t swz128(uint32_t b) { return b ^ ((b >> 3) & 0x70); }

#define LDSM4(r0,r1,r2,r3,addr) \
    asm volatile("ldmatrix.sync.aligned.m8n8.x4.shared.b16 {%0,%1,%2,%3}, [%4];" \
        : "=r"(r0),"=r"(r1),"=r"(r2),"=r"(r3) : "r"(addr))

#define MMA16816(d, a, b0, b1) \
    asm volatile("mma.sync.aligned.m16n8k16.row.col.f32.bf16.bf16.f32 " \
        "{%0,%1,%2,%3}, {%4,%5,%6,%7}, {%8,%9}, {%0,%1,%2,%3};" \
        : "+f"((d)[0]),"+f"((d)[1]),"+f"((d)[2]),"+f"((d)[3]) \
        : "r"((a)[0]),"r"((a)[1]),"r"((a)[2]),"r"((a)[3]),"r"(b0),"r"(b1))

// ---------------- prep: deform weight -> bf16 hi/lo, SW128-swizzled ----------
__global__ void prep_wbf(const float* __restrict__ dw) {
    int i = blockIdx.x * 256 + threadIdx.x;     // over 9*4*16384
    if (i >= KTAP * 4 * 16384) return;
    int t  = i >> 16;
    int r  = i & 65535;
    int cc = r >> 14;
    int r2 = r & 16383;
    int n  = r2 >> 6;
    int k  = r2 & 63;
    float v = dw[n * (CIN * KTAP) + (cc * 64 + k) * KTAP + t];
    __nv_bfloat16 hi = __float2bfloat16(v);
    __nv_bfloat16 lo = __float2bfloat16(v - __bfloat162float(hi));
    uint32_t sw = swz128((uint32_t)(n * 128 + k * 2)) >> 1;
    int base = (t * 4 + cc) * 16384;
    g_wbf_hi[base + sw] = hi;
    g_wbf_lo[base + sw] = lo;
}

// ---------------- prep: offset weight -> bf16 hi/lo SW128 [32n x 64k] tiles --
__global__ void prep_owbf(const float* __restrict__ ow) {
    int i = blockIdx.x * 256 + threadIdx.x;     // over 36*2048
    if (i >= KTAP * 4 * 2048) return;
    int ch = i >> 11;
    int r  = i & 2047;
    int n  = r >> 6;
    int k  = r & 63;
    int t  = ch >> 2;
    int cc = ch & 3;
    float v = (n < OFFC) ? ow[n * (CIN * KTAP) + (cc * 64 + k) * KTAP + t] : 0.0f;
    __nv_bfloat16 hi = __float2bfloat16(v);
    __nv_bfloat16 lo = __float2bfloat16(v - __bfloat162float(hi));
    uint32_t sw = swz128((uint32_t)(n * 128 + k * 2)) >> 1;
    g_owbf_hi[ch * 2048 + sw] = hi;
    g_owbf_lo[ch * 2048 + sw] = lo;
}

// ---------------- transpose x [b][c][hw] -> [b][hw][c] -----------------------
__global__ void transpose_x(const float* __restrict__ x) {
    __shared__ float t[32][33];
    int b   = blockIdx.z;
    int hw0 = blockIdx.x * 32;
    int c0  = blockIdx.y * 32;
    int tx  = threadIdx.x, ty = threadIdx.y;
    #pragma unroll
    for (int i = ty; i < 32; i += 8)
        t[i][tx] = x[((b * CIN + c0 + i) << 12) + hw0 + tx];
    __syncthreads();
    #pragma unroll
    for (int i = ty; i < 32; i += 8)
        g_xt[(size_t)((b << 12) + hw0 + i) * CIN + c0 + tx] = t[tx][i];
}

// ---------------- offset conv via HMMA bf16-split ----------------------------
// 128 CTAs x 512 thr. CTA tile 128m x 32n(18 used). 16 warps: 8 m-warps x 2 n-warps,
// warp tile 16m x 16n. A = shifted NHWC x rows (no gather), bf16 hi/lo split.
__global__ __launch_bounds__(512) void offset_conv_mma(const float* __restrict__ bias) {
    __shared__ __align__(1024) char sA[32768];   // hi 16K | lo 16K
    __shared__ __align__(1024) char sB[8192];    // hi 4K  | lo 4K
    uint32_t sa  = smem_u32(sA);
    uint32_t sbb = smem_u32(sB);
    int tid = threadIdx.x, wid = tid >> 5, lid = tid & 31;
    int mw = wid & 7, nw = wid >> 3;
    int tile = blockIdx.x;
    int b    = tile >> 5;
    int hw0  = (tile & 31) << 7;
    const float* xtb = g_xt + (size_t)b * HWSZ * CIN;

    uint32_t amask = (uint32_t)((lid & 7) * 16);
    uint32_t ahalf = (lid >> 4) ? 16u : 0u;
    uint32_t abase = sa + (uint32_t)((mw * 16 + (lid & 15)) * 128);
    int brow_in = (lid & 7) + ((lid >> 4) << 3);
    uint32_t bhalf = ((lid >> 3) & 1) ? 16u : 0u;
    uint32_t bbase = sbb + (uint32_t)((nw * 16 + brow_in) * 128);

    float acc[2][4];
    #pragma unroll
    for (int j = 0; j < 2; ++j)
        #pragma unroll
        for (int q = 0; q < 4; ++q) acc[j][q] = 0.0f;

    for (int ch = 0; ch < 36; ++ch) {
        int t  = ch >> 2;
        int c0 = (ch & 3) * 64;
        int dyt = t / 3 - 1, dxt = t % 3 - 1;
        __syncthreads();
        // B copy (8KB)
        if (tid < 256)
            ((float4*)sB)[tid] = ((const float4*)g_owbf_hi)[ch * 256 + tid];
        else
            ((float4*)(sB + 4096))[tid - 256] = ((const float4*)g_owbf_lo)[ch * 256 + tid - 256];
        // A build: shifted x rows, bf16 split
        #pragma unroll
        for (int it = 0; it < 4; ++it) {
            int e = it * 512 + tid;
            int m = e >> 4, q = e & 15;
            int hw = hw0 + m;
            int hh = hw >> 6, wp = hw & 63;
            int yy = hh + dyt, xx = wp + dxt;
            float4 v = make_float4(0.f, 0.f, 0.f, 0.f);
            if ((unsigned)yy < 64u && (unsigned)xx < 64u)
                v = *(const float4*)(xtb + (((yy << 6) + xx) << 8) + c0 + q * 4);
            __nv_bfloat16 h0 = __float2bfloat16(v.x);
            __nv_bfloat16 h1 = __float2bfloat16(v.y);
            __nv_bfloat16 h2 = __float2bfloat16(v.z);
            __nv_bfloat16 h3 = __float2bfloat16(v.w);
            __nv_bfloat16 l0 = __float2bfloat16(v.x - __bfloat162float(h0));
            __nv_bfloat16 l1 = __float2bfloat16(v.y - __bfloat162float(h1));
            __nv_bfloat16 l2 = __float2bfloat16(v.z - __bfloat162float(h2));
            __nv_bfloat16 l3 = __float2bfloat16(v.w - __bfloat162float(h3));
            uint32_t sw = swz128((uint32_t)(m * 128 + q * 8));
            __nv_bfloat162* ph = (__nv_bfloat162*)(sA + sw);
            __nv_bfloat162* pl = (__nv_bfloat162*)(sA + 16384 + sw);
            ph[0] = __nv_bfloat162(h0, h1);
            ph[1] = __nv_bfloat162(h2, h3);
            pl[0] = __nv_bfloat162(l0, l1);
            pl[1] = __nv_bfloat162(l2, l3);
        }
        __syncthreads();
        #pragma unroll
        for (int kk = 0; kk < 4; ++kk) {
            uint32_t acol = ((uint32_t)(kk * 32) + ahalf) ^ amask;
            uint32_t a_hi[4], a_lo[4];
            LDSM4(a_hi[0], a_hi[1], a_hi[2], a_hi[3], abase + acol);
            LDSM4(a_lo[0], a_lo[1], a_lo[2], a_lo[3], abase + 16384 + acol);
            uint32_t bcol = ((uint32_t)(kk * 32) + bhalf) ^ amask;
            uint32_t bh[4], bl[4];
            LDSM4(bh[0], bh[1], bh[2], bh[3], bbase + bcol);
            LDSM4(bl[0], bl[1], bl[2], bl[3], bbase + 4096 + bcol);
            MMA16816(acc[0], a_hi, bh[0], bh[1]);
            MMA16816(acc[0], a_lo, bh[0], bh[1]);
            MMA16816(acc[0], a_hi, bl[0], bl[1]);
            MMA16816(acc[1], a_hi, bh[2], bh[3]);
            MMA16816(acc[1], a_lo, bh[2], bh[3]);
            MMA16816(acc[1], a_hi, bl[2], bl[3]);
        }
    }

    int mrow = lid >> 2, ncol = (lid & 3) * 2;
    int m = hw0 + mw * 16 + mrow;
    #pragma unroll
    for (int j2 = 0; j2 < 2; ++j2) {
        int n = nw * 16 + j2 * 8 + ncol;
        if (n < OFFC) {
            g_offs[(b * OFFC + n) * HWSZ + m]     = acc[j2][0] + bias[n];
            g_offs[(b * OFFC + n) * HWSZ + m + 8] = acc[j2][2] + bias[n];
        }
        if (n + 1 < OFFC) {
            g_offs[(b * OFFC + n + 1) * HWSZ + m]     = acc[j2][1] + bias[n + 1];
            g_offs[(b * OFFC + n + 1) * HWSZ + m + 8] = acc[j2][3] + bias[n + 1];
        }
    }
}

// ---------------- deformable conv: pipelined mma.sync bf16-split -------------
// 128 CTAs x 512 thr. CTA tile 128m x 256n, 16 warps 4m x 4n (32m x 64n each).
// Double-buffered A (built) and B (cp.async); build(ch+1) after MMA(ch).
#define DS_CW   0                          // float4 cwgt[1152]  (18432 B)
#define DS_CI   18432                      // ushort4 cidx[1152] (9216 B)
#define DS_A0   27648                      // 32KB: hi 16K | lo 16K
#define DS_A1   (DS_A0 + 32768)
#define DS_B0   (DS_A1 + 32768)            // 64KB: hi 32K | lo 32K
#define DS_B1   (DS_B0 + 65536)
#define DS_TOT  (DS_B1 + 65536)            // 224256 B

__device__ __forceinline__ void issue_B(int ch, uint32_t dst, int tid) {
    const char* srcH = (const char*)g_wbf_hi + (size_t)ch * 32768;
    const char* srcL = (const char*)g_wbf_lo + (size_t)ch * 32768;
    #pragma unroll
    for (int r = 0; r < 4; ++r) {
        int i = (tid + 512 * r) * 16;
        asm volatile("cp.async.cg.shared.global [%0], [%1], 16;" :: "r"(dst + i), "l"(srcH + i));
        asm volatile("cp.async.cg.shared.global [%0], [%1], 16;" :: "r"(dst + 32768 + i), "l"(srcL + i));
    }
    asm volatile("cp.async.commit_group;");
}

__device__ __forceinline__ void build_A(int ch, char* smem, uint32_t aoff,
                                        const float* xtb, int tid) {
    int t  = ch >> 2;
    int c0 = (ch & 3) * 64;
    const float4*  cw4 = (const float4*)(smem + DS_CW);
    const ushort4* ci4 = (const ushort4*)(smem + DS_CI);
    #pragma unroll
    for (int it = 0; it < 4; ++it) {
        int e = it * 512 + tid;
        int m = e >> 4, q = e & 15;
        int ce = m * 9 + t;
        float4  w  = cw4[ce];
        ushort4 ix = ci4[ce];
        const float* base = xtb + c0 + q * 4;
        float4 s0 = *(const float4*)(base + ((int)ix.x << 8));
        float4 s1 = *(const float4*)(base + ((int)ix.y << 8));
        float4 s2 = *(const float4*)(base + ((int)ix.z << 8));
        float4 s3 = *(const float4*)(base + ((int)ix.w << 8));
        float v0 = w.x*s0.x + w.y*s1.x + w.z*s2.x + w.w*s3.x;
        float v1 = w.x*s0.y + w.y*s1.y + w.z*s2.y + w.w*s3.y;
        float v2 = w.x*s0.z + w.y*s1.z + w.z*s2.z + w.w*s3.z;
        float v3 = w.x*s0.w + w.y*s1.w + w.z*s2.w + w.w*s3.w;
        __nv_bfloat16 h0 = __float2bfloat16(v0);
        __nv_bfloat16 h1 = __float2bfloat16(v1);
        __nv_bfloat16 h2 = __float2bfloat16(v2);
        __nv_bfloat16 h3 = __float2bfloat16(v3);
        __nv_bfloat16 l0 = __float2bfloat16(v0 - __bfloat162float(h0));
        __nv_bfloat16 l1 = __float2bfloat16(v1 - __bfloat162float(h1));
        __nv_bfloat16 l2 = __float2bfloat16(v2 - __bfloat162float(h2));
        __nv_bfloat16 l3 = __float2bfloat16(v3 - __bfloat162float(h3));
        uint32_t sw = swz128((uint32_t)(m * 128 + q * 8));
        __nv_bfloat162* ph = (__nv_bfloat162*)(smem + aoff + sw);
        __nv_bfloat162* pl = (__nv_bfloat162*)(smem + aoff + 16384 + sw);
        ph[0] = __nv_bfloat162(h0, h1);
        ph[1] = __nv_bfloat162(h2, h3);
        pl[0] = __nv_bfloat162(l0, l1);
        pl[1] = __nv_bfloat162(l2, l3);
    }
}

__global__ __launch_bounds__(512, 1) void deform_gemm(float* __restrict__ out) {
    extern __shared__ char smem[];
    uint32_t sb = smem_u32(smem);
    int tid = threadIdx.x, wid = tid >> 5, lid = tid & 31;
    int mw = wid & 3, nw = wid >> 2;
    int tile = blockIdx.x;
    int b    = tile >> 5;
    int hw0  = (tile & 31) << 7;
    const float* xtb = g_xt + (size_t)b * HWSZ * CIN;

    issue_B(0, sb + DS_B0, tid);

    // corner tables: 128 m x 9 taps
    float4*  cw4 = (float4*)(smem + DS_CW);
    ushort4* ci4 = (ushort4*)(smem + DS_CI);
    for (int e = tid; e < 128 * KTAP; e += 512) {
        int ml = e / 9, k = e - ml * 9;
        int hw = hw0 + ml;
        int hh = hw >> 6, wp = hw & 63;
        float dy = g_offs[(b * OFFC + 2 * k) * HWSZ + hw];
        float dx = g_offs[(b * OFFC + 2 * k + 1) * HWSZ + hw];
        int ky = k / 3, kx = k - ky * 3;
        float py = (float)(hh - 1 + ky) + dy;
        float px = (float)(wp - 1 + kx) + dx;
        float y0f = floorf(py), x0f = floorf(px);
        float ty = py - y0f, tx = px - x0f;
        int y0 = (int)y0f, x0 = (int)x0f;
        float wv[4]; unsigned short iv[4];
        #pragma unroll
        for (int j = 0; j < 4; ++j) {
            int yj = y0 + (j >> 1);
            int xj = x0 + (j & 1);
            float wj = ((j >> 1) ? ty : 1.0f - ty) * ((j & 1) ? tx : 1.0f - tx);
            bool ok = (yj >= 0) && (yj < HH) && (xj >= 0) && (xj < WW);
            wv[j] = ok ? wj : 0.0f;
            iv[j] = ok ? (unsigned short)(yj * WW + xj) : 0;
        }
        cw4[e] = make_float4(wv[0], wv[1], wv[2], wv[3]);
        ci4[e] = make_ushort4(iv[0], iv[1], iv[2], iv[3]);
    }
    __syncthreads();
    build_A(0, smem, DS_A0, xtb, tid);
    asm volatile("cp.async.wait_group 0;" ::: "memory");
    __syncthreads();

    uint32_t amask = (uint32_t)((lid & 7) * 16);
    uint32_t ahalf = (lid >> 4) ? 16u : 0u;
    uint32_t arowoff = (uint32_t)((mw * 32 + (lid & 15)) * 128);
    int brow_in = (lid & 7) + ((lid >> 4) << 3);
    uint32_t bhalf = ((lid >> 3) & 1) ? 16u : 0u;
    uint32_t browoff = (uint32_t)((nw * 64 + brow_in) * 128);

    float acc[2][8][4];
    #pragma unroll
    for (int i = 0; i < 2; ++i)
        #pragma unroll
        for (int j = 0; j < 8; ++j)
            #pragma unroll
            for (int q = 0; q < 4; ++q) acc[i][j][q] = 0.0f;

    for (int ch = 0; ch < 36; ++ch) {
        uint32_t aoff  = (ch & 1) ? DS_A1 : DS_A0;
        uint32_t boff  = (ch & 1) ? DS_B1 : DS_B0;
        uint32_t anoff = (ch & 1) ? DS_A0 : DS_A1;
        uint32_t bnoff = (ch & 1) ? DS_B0 : DS_B1;
        if (ch < 35) issue_B(ch + 1, sb + bnoff, tid);

        #pragma unroll
        for (int kk = 0; kk < 4; ++kk) {
            uint32_t acol = ((uint32_t)(kk * 32) + ahalf) ^ amask;
            uint32_t a_hi[2][4], a_lo[2][4];
            #pragma unroll
            for (int i = 0; i < 2; ++i) {
                uint32_t aa = sb + aoff + arowoff + (uint32_t)(i * 2048) + acol;
                LDSM4(a_hi[i][0], a_hi[i][1], a_hi[i][2], a_hi[i][3], aa);
                LDSM4(a_lo[i][0], a_lo[i][1], a_lo[i][2], a_lo[i][3], aa + 16384);
            }
            uint32_t bcol = ((uint32_t)(kk * 32) + bhalf) ^ amask;
            #pragma unroll
            for (int j2 = 0; j2 < 4; ++j2) {
                uint32_t bb = sb + boff + browoff + (uint32_t)(j2 * 2048) + bcol;
                uint32_t bh[4], bl[4];
                LDSM4(bh[0], bh[1], bh[2], bh[3], bb);
                LDSM4(bl[0], bl[1], bl[2], bl[3], bb + 32768);
                #pragma unroll
                for (int i = 0; i < 2; ++i) {
                    MMA16816(acc[i][2*j2],   a_hi[i], bh[0], bh[1]);
                    MMA16816(acc[i][2*j2],   a_lo[i], bh[0], bh[1]);
                    MMA16816(acc[i][2*j2],   a_hi[i], bl[0], bl[1]);
                    MMA16816(acc[i][2*j2+1], a_hi[i], bh[2], bh[3]);
                    MMA16816(acc[i][2*j2+1], a_lo[i], bh[2], bh[3]);
                    MMA16816(acc[i][2*j2+1], a_hi[i], bl[2], bl[3]);
                }
            }
        }

        if (ch < 35) build_A(ch + 1, smem, anoff, xtb, tid);
        asm volatile("cp.async.wait_group 0;" ::: "memory");
        __syncthreads();
    }

    // store accumulators to out [b][n][hw]
    int mrow = lid >> 2;
    int ncol = (lid & 3) * 2;
    #pragma unroll
    for (int i = 0; i < 2; ++i) {
        int m = hw0 + mw * 32 + i * 16 + mrow;
        #pragma unroll
        for (int j = 0; j < 8; ++j) {
            int n = nw * 64 + j * 8 + ncol;
            out[((size_t)(b * COUT + n)     << 12) + m]     = acc[i][j][0];
            out[((size_t)(b * COUT + n + 1) << 12) + m]     = acc[i][j][1];
            out[((size_t)(b * COUT + n)     << 12) + m + 8] = acc[i][j][2];
            out[((size_t)(b * COUT + n + 1) << 12) + m + 8] = acc[i][j][3];
        }
    }
}

// ---------------- GroupNorm stats ---------------------------------------------
__global__ void gn_stats(const float* __restrict__ out) {
    int bg = blockIdx.x;
    int b = bg >> 5, g = bg & 31;
    const float* p = out + ((size_t)(b * COUT + g * CPG) << 12);
    float s = 0.0f, sq = 0.0f;
    for (int i = threadIdx.x; i < CPG * HWSZ; i += 256) {
        float v = p[i];
        s += v; sq += v * v;
    }
    __shared__ float rs[256], rq[256];
    rs[threadIdx.x] = s; rq[threadIdx.x] = sq;
    __syncthreads();
    for (int off = 128; off > 0; off >>= 1) {
        if (threadIdx.x < off) {
            rs[threadIdx.x] += rs[threadIdx.x + off];
            rq[threadIdx.x] += rq[threadIdx.x + off];
        }
        __syncthreads();
    }
    if (threadIdx.x == 0) {
        float n = (float)(CPG * HWSZ);
        float mean = rs[0] / n;
        float var = rq[0] / n - mean * mean;
        g_stats[bg * 2 + 0] = mean;
        g_stats[bg * 2 + 1] = rsqrtf(var + EPS);
    }
}

// ---------------- GroupNorm apply + ReLU --------------------------------------
__global__ void gn_apply(float* __restrict__ out,
                         const float* __restrict__ gamma,
                         const float* __restrict__ beta) {
    int idx = blockIdx.x * 256 + threadIdx.x;
    int c = (idx >> 12) & 255;
    int b = idx >> 20;
    int bg = b * GN_GROUPS + (c >> 3);
    float mean = g_stats[bg * 2 + 0];
    float rstd = g_stats[bg * 2 + 1];
    float v = (out[idx] - mean) * rstd * gamma[c] + beta[c];
    out[idx] = fmaxf(v, 0.0f);
}

// ---------------- launch ------------------------------------------------------
extern "C" void kernel_launch(void* const* d_in, const int* in_sizes, int n_in,
                              void* d_out, int out_size) {
    const float* x   = (const float*)d_in[0];
    const float* ow  = (const float*)d_in[1];
    const float* ob  = (const float*)d_in[2];
    const float* dw  = (const float*)d_in[3];
    const float* gam = (const float*)d_in[4];
    const float* bet = (const float*)d_in[5];
    float* out = (float*)d_out;

    cudaFuncSetAttribute(deform_gemm, cudaFuncAttributeMaxDynamicSharedMemorySize, DS_TOT);

    prep_wbf<<<(KTAP * 4 * 16384 + 255) / 256, 256>>>(dw);
    prep_owbf<<<(KTAP * 4 * 2048 + 255) / 256, 256>>>(ow);
    transpose_x<<<dim3(HWSZ / 32, CIN / 32, NB), dim3(32, 8)>>>(x);
    offset_conv_mma<<<128, 512>>>(ob);
    deform_gemm<<<128, 512, DS_TOT>>>(out);
    gn_stats<<<NB * GN_GROUPS, 256>>>(out);
    gn_apply<<<(NB * COUT * HWSZ) / 256, 256>>>(out, gam, bet);
}

// round 9
// speedup vs baseline: 2.4397x; 1.0200x over previous
#include <cuda_runtime.h>
#include <cuda_bf16.h>
#include <cstdint>

#define NB   4
#define CIN  256
#define COUT 256
#define HH   64
#define WW   64
#define HWSZ 4096
#define KTAP 9
#define OFFC 18
#define GN_GROUPS 32
#define CPG  8
#define EPS  1e-5f

// ---------------- scratch ----------------
__device__ float g_xt[NB * HWSZ * CIN];              // x as [b][hw][c]
__device__ float g_offs[NB * OFFC * HWSZ];           // offsets [b][ch][hw]
__device__ __nv_bfloat16 g_wbf_hi[KTAP * 4 * 16384]; // deform W hi, SW128 tiles [tap*4+cc][256n x 64k]
__device__ __nv_bfloat16 g_wbf_lo[KTAP * 4 * 16384]; // deform W lo
__device__ __nv_bfloat16 g_owbf_hi[KTAP * 4 * 2048]; // offset W hi, SW128 tiles [tap*4+cc][32n x 64k]
__device__ __nv_bfloat16 g_owbf_lo[KTAP * 4 * 2048]; // offset W lo
__device__ float g_part[NB * GN_GROUPS * 2];         // GN partial (sum, sumsq)
__device__ float g_stats[NB * GN_GROUPS * 2];        // (mean, rstd)

__device__ __forceinline__ uint32_t smem_u32(const void* p) {
    uint32_t a;
    asm("{ .reg .u64 t; cvta.to.shared.u64 t, %1; cvt.u32.u64 %0, t; }" : "=r"(a) : "l"(p));
    return a;
}
__device__ __forceinline__ uint32_t swz128(uint32_t b) { return b ^ ((b >> 3) & 0x70); }

#define LDSM4(r0,r1,r2,r3,addr) \
    asm volatile("ldmatrix.sync.aligned.m8n8.x4.shared.b16 {%0,%1,%2,%3}, [%4];" \
        : "=r"(r0),"=r"(r1),"=r"(r2),"=r"(r3) : "r"(addr))

#define MMA16816(d, a, b0, b1) \
    asm volatile("mma.sync.aligned.m16n8k16.row.col.f32.bf16.bf16.f32 " \
        "{%0,%1,%2,%3}, {%4,%5,%6,%7}, {%8,%9}, {%0,%1,%2,%3};" \
        : "+f"((d)[0]),"+f"((d)[1]),"+f"((d)[2]),"+f"((d)[3]) \
        : "r"((a)[0]),"r"((a)[1]),"r"((a)[2]),"r"((a)[3]),"r"(b0),"r"(b1))

#define CPASYNC16(dst, src) \
    asm volatile("cp.async.cg.shared.global [%0], [%1], 16;" :: "r"(dst), "l"(src))

// ---------------- prep: deform weight -> bf16 hi/lo, SW128-swizzled ----------
__global__ void prep_wbf(const float* __restrict__ dw) {
    int i = blockIdx.x * 256 + threadIdx.x;     // over 9*4*16384
    if (i >= KTAP * 4 * 16384) return;
    int t  = i >> 16;
    int r  = i & 65535;
    int cc = r >> 14;
    int r2 = r & 16383;
    int n  = r2 >> 6;
    int k  = r2 & 63;
    float v = dw[n * (CIN * KTAP) + (cc * 64 + k) * KTAP + t];
    __nv_bfloat16 hi = __float2bfloat16(v);
    __nv_bfloat16 lo = __float2bfloat16(v - __bfloat162float(hi));
    uint32_t sw = swz128((uint32_t)(n * 128 + k * 2)) >> 1;
    int base = (t * 4 + cc) * 16384;
    g_wbf_hi[base + sw] = hi;
    g_wbf_lo[base + sw] = lo;
}

// ---------------- prep: offset weight -> bf16 hi/lo SW128 [32n x 64k] tiles --
__global__ void prep_owbf(const float* __restrict__ ow) {
    int i = blockIdx.x * 256 + threadIdx.x;     // over 36*2048
    if (blockIdx.x == 0 && threadIdx.x < NB * GN_GROUPS * 2)
        g_part[threadIdx.x] = 0.0f;             // zero GN partials
    if (i >= KTAP * 4 * 2048) return;
    int ch = i >> 11;
    int r  = i & 2047;
    int n  = r >> 6;
    int k  = r & 63;
    int t  = ch >> 2;
    int cc = ch & 3;
    float v = (n < OFFC) ? ow[n * (CIN * KTAP) + (cc * 64 + k) * KTAP + t] : 0.0f;
    __nv_bfloat16 hi = __float2bfloat16(v);
    __nv_bfloat16 lo = __float2bfloat16(v - __bfloat162float(hi));
    uint32_t sw = swz128((uint32_t)(n * 128 + k * 2)) >> 1;
    g_owbf_hi[ch * 2048 + sw] = hi;
    g_owbf_lo[ch * 2048 + sw] = lo;
}

// ---------------- transpose x [b][c][hw] -> [b][hw][c] -----------------------
__global__ void transpose_x(const float* __restrict__ x) {
    __shared__ float t[32][33];
    int b   = blockIdx.z;
    int hw0 = blockIdx.x * 32;
    int c0  = blockIdx.y * 32;
    int tx  = threadIdx.x, ty = threadIdx.y;
    #pragma unroll
    for (int i = ty; i < 32; i += 8)
        t[i][tx] = x[((b * CIN + c0 + i) << 12) + hw0 + tx];
    __syncthreads();
    #pragma unroll
    for (int i = ty; i < 32; i += 8)
        g_xt[(size_t)((b << 12) + hw0 + i) * CIN + c0 + tx] = t[tx][i];
}

// ---------------- offset conv v3: pipelined HMMA, 256 CTA x 256 thr ----------
// CTA tile: 64m (one (b,row)) x 32n. 8 warps: 4m x 2n, warp tile 16m x 16n.
// Double-buffered A (built from NHWC x, no gather) and B (cp.async).
#define OS_A0  0                      // 16KB: hi 8K | lo 8K
#define OS_A1  16384
#define OS_B0  32768                  // 8KB: hi 4K | lo 4K
#define OS_B1  40960
#define OS_TOT 49152

__device__ __forceinline__ void issue_OB(int ch, uint32_t dst, int tid) {
    const char* srcH = (const char*)g_owbf_hi + (size_t)ch * 4096;
    const char* srcL = (const char*)g_owbf_lo + (size_t)ch * 4096;
    int i = tid * 16;
    CPASYNC16(dst + i, srcH + i);
    CPASYNC16(dst + 4096 + i, srcL + i);
    asm volatile("cp.async.commit_group;");
}

__device__ __forceinline__ void build_OA(int ch, char* osm, uint32_t aoff,
                                         const float* xtb, int hh, int tid) {
    int t  = ch >> 2;
    int c0 = (ch & 3) * 64;
    int dyt = t / 3 - 1, dxt = t % 3 - 1;
    int yy = hh + dyt;
    bool rowok = ((unsigned)yy < 64u);
    #pragma unroll
    for (int it = 0; it < 4; ++it) {
        int e = it * 256 + tid;       // 0..1023 = 64m x 16q
        int m = e >> 4, q = e & 15;
        int xx = m + dxt;
        float4 v = make_float4(0.f, 0.f, 0.f, 0.f);
        if (rowok && (unsigned)xx < 64u)
            v = *(const float4*)(xtb + (((yy << 6) + xx) << 8) + c0 + q * 4);
        __nv_bfloat16 h0 = __float2bfloat16(v.x);
        __nv_bfloat16 h1 = __float2bfloat16(v.y);
        __nv_bfloat16 h2 = __float2bfloat16(v.z);
        __nv_bfloat16 h3 = __float2bfloat16(v.w);
        __nv_bfloat16 l0 = __float2bfloat16(v.x - __bfloat162float(h0));
        __nv_bfloat16 l1 = __float2bfloat16(v.y - __bfloat162float(h1));
        __nv_bfloat16 l2 = __float2bfloat16(v.z - __bfloat162float(h2));
        __nv_bfloat16 l3 = __float2bfloat16(v.w - __bfloat162float(h3));
        uint32_t sw = swz128((uint32_t)(m * 128 + q * 8));
        __nv_bfloat162* ph = (__nv_bfloat162*)(osm + aoff + sw);
        __nv_bfloat162* pl = (__nv_bfloat162*)(osm + aoff + 8192 + sw);
        ph[0] = __nv_bfloat162(h0, h1);
        ph[1] = __nv_bfloat162(h2, h3);
        pl[0] = __nv_bfloat162(l0, l1);
        pl[1] = __nv_bfloat162(l2, l3);
    }
}

__global__ __launch_bounds__(256) void offset_conv_mma(const float* __restrict__ bias) {
    extern __shared__ char osm[];
    uint32_t sb = smem_u32(osm);
    int tid = threadIdx.x, wid = tid >> 5, lid = tid & 31;
    int mw = wid & 3, nw = wid >> 2;
    int tile = blockIdx.x;            // 0..255 = 4b x 64hh
    int b  = tile >> 6;
    int hh = tile & 63;
    int hw0 = hh << 6;
    const float* xtb = g_xt + (size_t)b * HWSZ * CIN;

    issue_OB(0, sb + OS_B0, tid);
    build_OA(0, osm, OS_A0, xtb, hh, tid);
    asm volatile("cp.async.wait_group 0;" ::: "memory");
    __syncthreads();

    uint32_t amask = (uint32_t)((lid & 7) * 16);
    uint32_t ahalf = (lid >> 4) ? 16u : 0u;
    uint32_t arowoff = (uint32_t)((mw * 16 + (lid & 15)) * 128);
    int brow_in = (lid & 7) + ((lid >> 4) << 3);
    uint32_t bhalf = ((lid >> 3) & 1) ? 16u : 0u;
    uint32_t browoff = (uint32_t)((nw * 16 + brow_in) * 128);

    float acc[2][4];
    #pragma unroll
    for (int j = 0; j < 2; ++j)
        #pragma unroll
        for (int q = 0; q < 4; ++q) acc[j][q] = 0.0f;

    for (int ch = 0; ch < 36; ++ch) {
        uint32_t aoff  = (ch & 1) ? OS_A1 : OS_A0;
        uint32_t boff  = (ch & 1) ? OS_B1 : OS_B0;
        uint32_t anoff = (ch & 1) ? OS_A0 : OS_A1;
        uint32_t bnoff = (ch & 1) ? OS_B0 : OS_B1;
        if (ch < 35) issue_OB(ch + 1, sb + bnoff, tid);

        #pragma unroll
        for (int kk = 0; kk < 4; ++kk) {
            uint32_t acol = ((uint32_t)(kk * 32) + ahalf) ^ amask;
            uint32_t aa = sb + aoff + arowoff + acol;
            uint32_t a_hi[4], a_lo[4];
            LDSM4(a_hi[0], a_hi[1], a_hi[2], a_hi[3], aa);
            LDSM4(a_lo[0], a_lo[1], a_lo[2], a_lo[3], aa + 8192);
            uint32_t bcol = ((uint32_t)(kk * 32) + bhalf) ^ amask;
            uint32_t bb = sb + boff + browoff + bcol;
            uint32_t bh[4], bl[4];
            LDSM4(bh[0], bh[1], bh[2], bh[3], bb);
            LDSM4(bl[0], bl[1], bl[2], bl[3], bb + 4096);
            MMA16816(acc[0], a_hi, bh[0], bh[1]);
            MMA16816(acc[0], a_lo, bh[0], bh[1]);
            MMA16816(acc[0], a_hi, bl[0], bl[1]);
            MMA16816(acc[1], a_hi, bh[2], bh[3]);
            MMA16816(acc[1], a_lo, bh[2], bh[3]);
            MMA16816(acc[1], a_hi, bl[2], bl[3]);
        }

        if (ch < 35) build_OA(ch + 1, osm, anoff, xtb, hh, tid);
        asm volatile("cp.async.wait_group 0;" ::: "memory");
        __syncthreads();
    }

    int mrow = lid >> 2, ncol = (lid & 3) * 2;
    int m = hw0 + mw * 16 + mrow;
    #pragma unroll
    for (int j2 = 0; j2 < 2; ++j2) {
        int n = nw * 16 + j2 * 8 + ncol;
        if (n < OFFC) {
            g_offs[(b * OFFC + n) * HWSZ + m]     = acc[j2][0] + bias[n];
            g_offs[(b * OFFC + n) * HWSZ + m + 8] = acc[j2][2] + bias[n];
        }
        if (n + 1 < OFFC) {
            g_offs[(b * OFFC + n + 1) * HWSZ + m]     = acc[j2][1] + bias[n + 1];
            g_offs[(b * OFFC + n + 1) * HWSZ + m + 8] = acc[j2][3] + bias[n + 1];
        }
    }
}

// ---------------- deformable conv: pipelined mma.sync bf16-split -------------
#define DS_CW   0                          // float4 cwgt[1152]  (18432 B)
#define DS_CI   18432                      // ushort4 cidx[1152] (9216 B)
#define DS_A0   27648                      // 32KB: hi 16K | lo 16K
#define DS_A1   (DS_A0 + 32768)
#define DS_B0   (DS_A1 + 32768)            // 64KB: hi 32K | lo 32K
#define DS_B1   (DS_B0 + 65536)
#define DS_TOT  (DS_B1 + 65536)            // 224256 B

__device__ __forceinline__ void issue_B(int ch, uint32_t dst, int tid) {
    const char* srcH = (const char*)g_wbf_hi + (size_t)ch * 32768;
    const char* srcL = (const char*)g_wbf_lo + (size_t)ch * 32768;
    #pragma unroll
    for (int r = 0; r < 4; ++r) {
        int i = (tid + 512 * r) * 16;
        CPASYNC16(dst + i, srcH + i);
        CPASYNC16(dst + 32768 + i, srcL + i);
    }
    asm volatile("cp.async.commit_group;");
}

__device__ __forceinline__ void build_A(int ch, char* smem, uint32_t aoff,
                                        const float* xtb, int tid) {
    int t  = ch >> 2;
    int c0 = (ch & 3) * 64;
    const float4*  cw4 = (const float4*)(smem + DS_CW);
    const ushort4* ci4 = (const ushort4*)(smem + DS_CI);
    #pragma unroll
    for (int it = 0; it < 4; ++it) {
        int e = it * 512 + tid;
        int m = e >> 4, q = e & 15;
        int ce = m * 9 + t;
        float4  w  = cw4[ce];
        ushort4 ix = ci4[ce];
        const float* base = xtb + c0 + q * 4;
        float4 s0 = *(const float4*)(base + ((int)ix.x << 8));
        float4 s1 = *(const float4*)(base + ((int)ix.y << 8));
        float4 s2 = *(const float4*)(base + ((int)ix.z << 8));
        float4 s3 = *(const float4*)(base + ((int)ix.w << 8));
        float v0 = w.x*s0.x + w.y*s1.x + w.z*s2.x + w.w*s3.x;
        float v1 = w.x*s0.y + w.y*s1.y + w.z*s2.y + w.w*s3.y;
        float v2 = w.x*s0.z + w.y*s1.z + w.z*s2.z + w.w*s3.z;
        float v3 = w.x*s0.w + w.y*s1.w + w.z*s2.w + w.w*s3.w;
        __nv_bfloat16 h0 = __float2bfloat16(v0);
        __nv_bfloat16 h1 = __float2bfloat16(v1);
        __nv_bfloat16 h2 = __float2bfloat16(v2);
        __nv_bfloat16 h3 = __float2bfloat16(v3);
        __nv_bfloat16 l0 = __float2bfloat16(v0 - __bfloat162float(h0));
        __nv_bfloat16 l1 = __float2bfloat16(v1 - __bfloat162float(h1));
        __nv_bfloat16 l2 = __float2bfloat16(v2 - __bfloat162float(h2));
        __nv_bfloat16 l3 = __float2bfloat16(v3 - __bfloat162float(h3));
        uint32_t sw = swz128((uint32_t)(m * 128 + q * 8));
        __nv_bfloat162* ph = (__nv_bfloat162*)(smem + aoff + sw);
        __nv_bfloat162* pl = (__nv_bfloat162*)(smem + aoff + 16384 + sw);
        ph[0] = __nv_bfloat162(h0, h1);
        ph[1] = __nv_bfloat162(h2, h3);
        pl[0] = __nv_bfloat162(l0, l1);
        pl[1] = __nv_bfloat162(l2, l3);
    }
}

__global__ __launch_bounds__(512, 1) void deform_gemm(float* __restrict__ out) {
    extern __shared__ char smem[];
    uint32_t sb = smem_u32(smem);
    int tid = threadIdx.x, wid = tid >> 5, lid = tid & 31;
    int mw = wid & 3, nw = wid >> 2;
    int tile = blockIdx.x;
    int b    = tile >> 5;
    int hw0  = (tile & 31) << 7;
    const float* xtb = g_xt + (size_t)b * HWSZ * CIN;

    issue_B(0, sb + DS_B0, tid);

    float4*  cw4 = (float4*)(smem + DS_CW);
    ushort4* ci4 = (ushort4*)(smem + DS_CI);
    for (int e = tid; e < 128 * KTAP; e += 512) {
        int ml = e / 9, k = e - ml * 9;
        int hw = hw0 + ml;
        int hh = hw >> 6, wp = hw & 63;
        float dy = g_offs[(b * OFFC + 2 * k) * HWSZ + hw];
        float dx = g_offs[(b * OFFC + 2 * k + 1) * HWSZ + hw];
        int ky = k / 3, kx = k - ky * 3;
        float py = (float)(hh - 1 + ky) + dy;
        float px = (float)(wp - 1 + kx) + dx;
        float y0f = floorf(py), x0f = floorf(px);
        float ty = py - y0f, tx = px - x0f;
        int y0 = (int)y0f, x0 = (int)x0f;
        float wv[4]; unsigned short iv[4];
        #pragma unroll
        for (int j = 0; j < 4; ++j) {
            int yj = y0 + (j >> 1);
            int xj = x0 + (j & 1);
            float wj = ((j >> 1) ? ty : 1.0f - ty) * ((j & 1) ? tx : 1.0f - tx);
            bool ok = (yj >= 0) && (yj < HH) && (xj >= 0) && (xj < WW);
            wv[j] = ok ? wj : 0.0f;
            iv[j] = ok ? (unsigned short)(yj * WW + xj) : 0;
        }
        cw4[e] = make_float4(wv[0], wv[1], wv[2], wv[3]);
        ci4[e] = make_ushort4(iv[0], iv[1], iv[2], iv[3]);
    }
    __syncthreads();
    build_A(0, smem, DS_A0, xtb, tid);
    asm volatile("cp.async.wait_group 0;" ::: "memory");
    __syncthreads();

    uint32_t amask = (uint32_t)((lid & 7) * 16);
    uint32_t ahalf = (lid >> 4) ? 16u : 0u;
    uint32_t arowoff = (uint32_t)((mw * 32 + (lid & 15)) * 128);
    int brow_in = (lid & 7) + ((lid >> 4) << 3);
    uint32_t bhalf = ((lid >> 3) & 1) ? 16u : 0u;
    uint32_t browoff = (uint32_t)((nw * 64 + brow_in) * 128);

    float acc[2][8][4];
    #pragma unroll
    for (int i = 0; i < 2; ++i)
        #pragma unroll
        for (int j = 0; j < 8; ++j)
            #pragma unroll
            for (int q = 0; q < 4; ++q) acc[i][j][q] = 0.0f;

    for (int ch = 0; ch < 36; ++ch) {
        uint32_t aoff  = (ch & 1) ? DS_A1 : DS_A0;
        uint32_t boff  = (ch & 1) ? DS_B1 : DS_B0;
        uint32_t anoff = (ch & 1) ? DS_A0 : DS_A1;
        uint32_t bnoff = (ch & 1) ? DS_B0 : DS_B1;
        if (ch < 35) issue_B(ch + 1, sb + bnoff, tid);

        #pragma unroll
        for (int kk = 0; kk < 4; ++kk) {
            uint32_t acol = ((uint32_t)(kk * 32) + ahalf) ^ amask;
            uint32_t a_hi[2][4], a_lo[2][4];
            #pragma unroll
            for (int i = 0; i < 2; ++i) {
                uint32_t aa = sb + aoff + arowoff + (uint32_t)(i * 2048) + acol;
                LDSM4(a_hi[i][0], a_hi[i][1], a_hi[i][2], a_hi[i][3], aa);
                LDSM4(a_lo[i][0], a_lo[i][1], a_lo[i][2], a_lo[i][3], aa + 16384);
            }
            uint32_t bcol = ((uint32_t)(kk * 32) + bhalf) ^ amask;
            #pragma unroll
            for (int j2 = 0; j2 < 4; ++j2) {
                uint32_t bb = sb + boff + browoff + (uint32_t)(j2 * 2048) + bcol;
                uint32_t bh[4], bl[4];
                LDSM4(bh[0], bh[1], bh[2], bh[3], bb);
                LDSM4(bl[0], bl[1], bl[2], bl[3], bb + 32768);
                #pragma unroll
                for (int i = 0; i < 2; ++i) {
                    MMA16816(acc[i][2*j2],   a_hi[i], bh[0], bh[1]);
                    MMA16816(acc[i][2*j2],   a_lo[i], bh[0], bh[1]);
                    MMA16816(acc[i][2*j2],   a_hi[i], bl[0], bl[1]);
                    MMA16816(acc[i][2*j2+1], a_hi[i], bh[2], bh[3]);
                    MMA16816(acc[i][2*j2+1], a_lo[i], bh[2], bh[3]);
                    MMA16816(acc[i][2*j2+1], a_hi[i], bl[2], bl[3]);
                }
            }
        }

        if (ch < 35) build_A(ch + 1, smem, anoff, xtb, tid);
        asm volatile("cp.async.wait_group 0;" ::: "memory");
        __syncthreads();
    }

    // store accumulators to out [b][n][hw]
    int mrow = lid >> 2;
    int ncol = (lid & 3) * 2;
    #pragma unroll
    for (int i = 0; i < 2; ++i) {
        int m = hw0 + mw * 32 + i * 16 + mrow;
        #pragma unroll
        for (int j = 0; j < 8; ++j) {
            int n = nw * 64 + j * 8 + ncol;
            out[((size_t)(b * COUT + n)     << 12) + m]     = acc[i][j][0];
            out[((size_t)(b * COUT + n + 1) << 12) + m]     = acc[i][j][1];
            out[((size_t)(b * COUT + n)     << 12) + m + 8] = acc[i][j][2];
            out[((size_t)(b * COUT + n + 1) << 12) + m + 8] = acc[i][j][3];
        }
    }

    // fused GroupNorm partial reduction: group of n = n>>3 = nw*8 + j
    #pragma unroll
    for (int j = 0; j < 8; ++j) {
        float s = 0.0f, sq = 0.0f;
        #pragma unroll
        for (int i = 0; i < 2; ++i)
            #pragma unroll
            for (int q = 0; q < 4; ++q) {
                float v = acc[i][j][q];
                s += v; sq += v * v;
            }
        #pragma unroll
        for (int off = 16; off > 0; off >>= 1) {
            s  += __shfl_xor_sync(0xFFFFFFFF, s,  off);
            sq += __shfl_xor_sync(0xFFFFFFFF, sq, off);
        }
        if (lid == 0) {
            int bg = b * GN_GROUPS + nw * 8 + j;
            atomicAdd(&g_part[bg * 2 + 0], s);
            atomicAdd(&g_part[bg * 2 + 1], sq);
        }
    }
}

// ---------------- GN finalize: partials -> (mean, rstd) ----------------------
__global__ void gn_finalize() {
    int bg = threadIdx.x;
    if (bg >= NB * GN_GROUPS) return;
    float n = (float)(CPG * HWSZ);
    float mean = g_part[bg * 2 + 0] / n;
    float var  = g_part[bg * 2 + 1] / n - mean * mean;
    g_stats[bg * 2 + 0] = mean;
    g_stats[bg * 2 + 1] = rsqrtf(var + EPS);
}

// ---------------- GroupNorm apply + ReLU --------------------------------------
__global__ void gn_apply(float* __restrict__ out,
                         const float* __restrict__ gamma,
                         const float* __restrict__ beta) {
    int idx = blockIdx.x * 256 + threadIdx.x;
    int c = (idx >> 12) & 255;
    int b = idx >> 20;
    int bg = b * GN_GROUPS + (c >> 3);
    float mean = g_stats[bg * 2 + 0];
    float rstd = g_stats[bg * 2 + 1];
    float v = (out[idx] - mean) * rstd * gamma[c] + beta[c];
    out[idx] = fmaxf(v, 0.0f);
}

// ---------------- launch ------------------------------------------------------
extern "C" void kernel_launch(void* const* d_in, const int* in_sizes, int n_in,
                              void* d_out, int out_size) {
    const float* x   = (const float*)d_in[0];
    const float* ow  = (const float*)d_in[1];
    const float* ob  = (const float*)d_in[2];
    const float* dw  = (const float*)d_in[3];
    const float* gam = (const float*)d_in[4];
    const float* bet = (const float*)d_in[5];
    float* out = (float*)d_out;

    cudaFuncSetAttribute(deform_gemm, cudaFuncAttributeMaxDynamicSharedMemorySize, DS_TOT);
    cudaFuncSetAttribute(offset_conv_mma, cudaFuncAttributeMaxDynamicSharedMemorySize, OS_TOT);

    prep_wbf<<<(KTAP * 4 * 16384 + 255) / 256, 256>>>(dw);
    prep_owbf<<<(KTAP * 4 * 2048 + 255) / 256, 256>>>(ow);
    transpose_x<<<dim3(HWSZ / 32, CIN / 32, NB), dim3(32, 8)>>>(x);
    offset_conv_mma<<<256, 256, OS_TOT>>>(ob);
    deform_gemm<<<128, 512, DS_TOT>>>(out);
    gn_finalize<<<1, 128>>>();
    gn_apply<<<(NB * COUT * HWSZ) / 256, 256>>>(out, gam, bet);
}

// round 11
// speedup vs baseline: 2.6598x; 1.0902x over previous
#include <cuda_runtime.h>
#include <cuda_bf16.h>
#include <cstdint>

#define NB   4
#define CIN  256
#define COUT 256
#define HH   64
#define WW   64
#define HWSZ 4096
#define KTAP 9
#define OFFC 18
#define GN_GROUPS 32
#define CPG  8
#define EPS  1e-5f

// ---------------- scratch ----------------
__device__ float g_xt[NB * HWSZ * CIN];              // x as [b][hw][c]
__device__ float g_offs[NB * OFFC * HWSZ];           // offsets [b][ch][hw]
__device__ float g_offp[2 * NB * OFFC * HWSZ];       // split-K partials
__device__ __nv_bfloat16 g_wbf_hi[KTAP * 4 * 16384]; // deform W hi, SW128 tiles [tap*4+cc][256n x 64k]
__device__ __nv_bfloat16 g_wbf_lo[KTAP * 4 * 16384]; // deform W lo
__device__ __nv_bfloat16 g_owbf_hi[KTAP * 4 * 2048]; // offset W hi, SW128 tiles [tap*4+cc][32n x 64k]
__device__ __nv_bfloat16 g_owbf_lo[KTAP * 4 * 2048]; // offset W lo
__device__ float g_part[NB * GN_GROUPS * 2];         // GN partial (sum, sumsq)
__device__ float g_stats[NB * GN_GROUPS * 2];        // (mean, rstd)

__device__ __forceinline__ uint32_t smem_u32(const void* p) {
    uint32_t a;
    asm("{ .reg .u64 t; cvta.to.shared.u64 t, %1; cvt.u32.u64 %0, t; }" : "=r"(a) : "l"(p));
    return a;
}
__device__ __forceinline__ uint32_t swz128(uint32_t b) { return b ^ ((b >> 3) & 0x70); }

#define LDSM4(r0,r1,r2,r3,addr) \
    asm volatile("ldmatrix.sync.aligned.m8n8.x4.shared.b16 {%0,%1,%2,%3}, [%4];" \
        : "=r"(r0),"=r"(r1),"=r"(r2),"=r"(r3) : "r"(addr))

#define MMA16816(d, a, b0, b1) \
    asm volatile("mma.sync.aligned.m16n8k16.row.col.f32.bf16.bf16.f32 " \
        "{%0,%1,%2,%3}, {%4,%5,%6,%7}, {%8,%9}, {%0,%1,%2,%3};" \
        : "+f"((d)[0]),"+f"((d)[1]),"+f"((d)[2]),"+f"((d)[3]) \
        : "r"((a)[0]),"r"((a)[1]),"r"((a)[2]),"r"((a)[3]),"r"(b0),"r"(b1))

#define CPASYNC16(dst, src) \
    asm volatile("cp.async.cg.shared.global [%0], [%1], 16;" :: "r"(dst), "l"(src))

// ---------------- prep: deform weight -> bf16 hi/lo, SW128-swizzled ----------
__global__ void prep_wbf(const float* __restrict__ dw) {
    int i = blockIdx.x * 256 + threadIdx.x;     // over 9*4*16384
    if (i >= KTAP * 4 * 16384) return;
    int t  = i >> 16;
    int r  = i & 65535;
    int cc = r >> 14;
    int r2 = r & 16383;
    int n  = r2 >> 6;
    int k  = r2 & 63;
    float v = dw[n * (CIN * KTAP) + (cc * 64 + k) * KTAP + t];
    __nv_bfloat16 hi = __float2bfloat16(v);
    __nv_bfloat16 lo = __float2bfloat16(v - __bfloat162float(hi));
    uint32_t sw = swz128((uint32_t)(n * 128 + k * 2)) >> 1;
    int base = (t * 4 + cc) * 16384;
    g_wbf_hi[base + sw] = hi;
    g_wbf_lo[base + sw] = lo;
}

// ---------------- prep: offset weight -> bf16 hi/lo SW128 [32n x 64k] tiles --
__global__ void prep_owbf(const float* __restrict__ ow) {
    int i = blockIdx.x * 256 + threadIdx.x;     // over 36*2048
    if (blockIdx.x == 0 && threadIdx.x < NB * GN_GROUPS * 2)
        g_part[threadIdx.x] = 0.0f;             // zero GN partials
    if (i >= KTAP * 4 * 2048) return;
    int ch = i >> 11;
    int r  = i & 2047;
    int n  = r >> 6;
    int k  = r & 63;
    int t  = ch >> 2;
    int cc = ch & 3;
    float v = (n < OFFC) ? ow[n * (CIN * KTAP) + (cc * 64 + k) * KTAP + t] : 0.0f;
    __nv_bfloat16 hi = __float2bfloat16(v);
    __nv_bfloat16 lo = __float2bfloat16(v - __bfloat162float(hi));
    uint32_t sw = swz128((uint32_t)(n * 128 + k * 2)) >> 1;
    g_owbf_hi[ch * 2048 + sw] = hi;
    g_owbf_lo[ch * 2048 + sw] = lo;
}

// ---------------- transpose x [b][c][hw] -> [b][hw][c] -----------------------
__global__ void transpose_x(const float* __restrict__ x) {
    __shared__ float t[32][33];
    int b   = blockIdx.z;
    int hw0 = blockIdx.x * 32;
    int c0  = blockIdx.y * 32;
    int tx  = threadIdx.x, ty = threadIdx.y;
    #pragma unroll
    for (int i = ty; i < 32; i += 8)
        t[i][tx] = x[((b * CIN + c0 + i) << 12) + hw0 + tx];
    __syncthreads();
    #pragma unroll
    for (int i = ty; i < 32; i += 8)
        g_xt[(size_t)((b << 12) + hw0 + i) * CIN + c0 + tx] = t[tx][i];
}

// ---------------- offset conv v4: split-K(2) pipelined HMMA ------------------
// 512 CTAs (2 K-halves x 4b x 64row) x 256 thr. CTA tile 64m x 32n, 18 chunks.
#define OS_A0  0                      // 16KB: hi 8K | lo 8K
#define OS_A1  16384
#define OS_B0  32768                  // 8KB: hi 4K | lo 4K
#define OS_B1  40960
#define OS_TOT 49152

__device__ __forceinline__ void issue_OB(int ch, uint32_t dst, int tid) {
    const char* srcH = (const char*)g_owbf_hi + (size_t)ch * 4096;
    const char* srcL = (const char*)g_owbf_lo + (size_t)ch * 4096;
    int i = tid * 16;
    CPASYNC16(dst + i, srcH + i);
    CPASYNC16(dst + 4096 + i, srcL + i);
    asm volatile("cp.async.commit_group;");
}

__device__ __forceinline__ void build_OA(int ch, char* osm, uint32_t aoff,
                                         const float* xtb, int hh, int tid) {
    int t  = ch >> 2;
    int c0 = (ch & 3) * 64;
    int dyt = t / 3 - 1, dxt = t % 3 - 1;
    int yy = hh + dyt;
    bool rowok = ((unsigned)yy < 64u);
    #pragma unroll
    for (int it = 0; it < 4; ++it) {
        int e = it * 256 + tid;       // 0..1023 = 64m x 16q
        int m = e >> 4, q = e & 15;
        int xx = m + dxt;
        float4 v = make_float4(0.f, 0.f, 0.f, 0.f);
        if (rowok && (unsigned)xx < 64u)
            v = *(const float4*)(xtb + (((yy << 6) + xx) << 8) + c0 + q * 4);
        __nv_bfloat16 h0 = __float2bfloat16(v.x);
        __nv_bfloat16 h1 = __float2bfloat16(v.y);
        __nv_bfloat16 h2 = __float2bfloat16(v.z);
        __nv_bfloat16 h3 = __float2bfloat16(v.w);
        __nv_bfloat16 l0 = __float2bfloat16(v.x - __bfloat162float(h0));
        __nv_bfloat16 l1 = __float2bfloat16(v.y - __bfloat162float(h1));
        __nv_bfloat16 l2 = __float2bfloat16(v.z - __bfloat162float(h2));
        __nv_bfloat16 l3 = __float2bfloat16(v.w - __bfloat162float(h3));
        uint32_t sw = swz128((uint32_t)(m * 128 + q * 8));
        __nv_bfloat162* ph = (__nv_bfloat162*)(osm + aoff + sw);
        __nv_bfloat162* pl = (__nv_bfloat162*)(osm + aoff + 8192 + sw);
        ph[0] = __nv_bfloat162(h0, h1);
        ph[1] = __nv_bfloat162(h2, h3);
        pl[0] = __nv_bfloat162(l0, l1);
        pl[1] = __nv_bfloat162(l2, l3);
    }
}

__global__ __launch_bounds__(256) void offset_conv_mma() {
    extern __shared__ char osm[];
    uint32_t sb = smem_u32(osm);
    int tid = threadIdx.x, wid = tid >> 5, lid = tid & 31;
    int mw = wid & 3, nw = wid >> 2;
    int blk = blockIdx.x;             // 0..511 = 2half x 4b x 64hh
    int half = blk >> 8;
    int b    = (blk >> 6) & 3;
    int hh   = blk & 63;
    int hw0  = hh << 6;
    int ch0  = half * 18;
    const float* xtb = g_xt + (size_t)b * HWSZ * CIN;

    issue_OB(ch0, sb + OS_B0, tid);
    build_OA(ch0, osm, OS_A0, xtb, hh, tid);
    asm volatile("cp.async.wait_group 0;" ::: "memory");
    __syncthreads();

    uint32_t amask = (uint32_t)((lid & 7) * 16);
    uint32_t ahalf = (lid >> 4) ? 16u : 0u;
    uint32_t arowoff = (uint32_t)((mw * 16 + (lid & 15)) * 128);
    int brow_in = (lid & 7) + ((lid >> 4) << 3);
    uint32_t bhalf = ((lid >> 3) & 1) ? 16u : 0u;
    uint32_t browoff = (uint32_t)((nw * 16 + brow_in) * 128);

    float acc[2][4];
    #pragma unroll
    for (int j = 0; j < 2; ++j)
        #pragma unroll
        for (int q = 0; q < 4; ++q) acc[j][q] = 0.0f;

    for (int lch = 0; lch < 18; ++lch) {
        uint32_t aoff  = (lch & 1) ? OS_A1 : OS_A0;
        uint32_t boff  = (lch & 1) ? OS_B1 : OS_B0;
        uint32_t anoff = (lch & 1) ? OS_A0 : OS_A1;
        uint32_t bnoff = (lch & 1) ? OS_B0 : OS_B1;
        if (lch < 17) issue_OB(ch0 + lch + 1, sb + bnoff, tid);

        #pragma unroll
        for (int kk = 0; kk < 4; ++kk) {
            uint32_t acol = ((uint32_t)(kk * 32) + ahalf) ^ amask;
            uint32_t aa = sb + aoff + arowoff + acol;
            uint32_t a_hi[4], a_lo[4];
            LDSM4(a_hi[0], a_hi[1], a_hi[2], a_hi[3], aa);
            LDSM4(a_lo[0], a_lo[1], a_lo[2], a_lo[3], aa + 8192);
            uint32_t bcol = ((uint32_t)(kk * 32) + bhalf) ^ amask;
            uint32_t bb = sb + boff + browoff + bcol;
            uint32_t bh[4], bl[4];
            LDSM4(bh[0], bh[1], bh[2], bh[3], bb);
            LDSM4(bl[0], bl[1], bl[2], bl[3], bb + 4096);
            MMA16816(acc[0], a_hi, bh[0], bh[1]);
            MMA16816(acc[0], a_lo, bh[0], bh[1]);
            MMA16816(acc[0], a_hi, bl[0], bl[1]);
            MMA16816(acc[1], a_hi, bh[2], bh[3]);
            MMA16816(acc[1], a_lo, bh[2], bh[3]);
            MMA16816(acc[1], a_hi, bl[2], bl[3]);
        }

        if (lch < 17) build_OA(ch0 + lch + 1, osm, anoff, xtb, hh, tid);
        asm volatile("cp.async.wait_group 0;" ::: "memory");
        __syncthreads();
    }

    float* dst = g_offp + (size_t)half * (NB * OFFC * HWSZ);
    int mrow = lid >> 2, ncol = (lid & 3) * 2;
    int m = hw0 + mw * 16 + mrow;
    #pragma unroll
    for (int j2 = 0; j2 < 2; ++j2) {
        int n = nw * 16 + j2 * 8 + ncol;
        if (n < OFFC) {
            dst[(b * OFFC + n) * HWSZ + m]     = acc[j2][0];
            dst[(b * OFFC + n) * HWSZ + m + 8] = acc[j2][2];
        }
        if (n + 1 < OFFC) {
            dst[(b * OFFC + n + 1) * HWSZ + m]     = acc[j2][1];
            dst[(b * OFFC + n + 1) * HWSZ + m + 8] = acc[j2][3];
        }
    }
}

// ---------------- combine split-K halves + bias ------------------------------
__global__ void combine_offs(const float* __restrict__ bias) {
    int i = blockIdx.x * 256 + threadIdx.x;     // float4 over NB*OFFC*HWSZ/4
    if (i >= NB * OFFC * HWSZ / 4) return;
    int o = (i >> 10) % OFFC;
    float bv = bias[o];
    float4 a = ((const float4*)g_offp)[i];
    float4 c = ((const float4*)(g_offp + NB * OFFC * HWSZ))[i];
    float4 r = make_float4(a.x + c.x + bv, a.y + c.y + bv, a.z + c.z + bv, a.w + c.w + bv);
    ((float4*)g_offs)[i] = r;
}

// ---------------- deformable conv: pipelined mma.sync bf16-split -------------
#define DS_CW   0                          // float4 cwgt[1152]  (18432 B)
#define DS_CI   18432                      // ushort4 cidx[1152] (9216 B)
#define DS_A0   27648                      // 32KB: hi 16K | lo 16K
#define DS_A1   (DS_A0 + 32768)
#define DS_B0   (DS_A1 + 32768)            // 64KB: hi 32K | lo 32K
#define DS_B1   (DS_B0 + 65536)
#define DS_TOT  (DS_B1 + 65536)            // 224256 B
// epilogue staging tile (re-uses A/B region): 256n x 132 floats = 135168 B
#define DS_TILE DS_A0

__device__ __forceinline__ void issue_B(int ch, uint32_t dst, int tid) {
    const char* srcH = (const char*)g_wbf_hi + (size_t)ch * 32768;
    const char* srcL = (const char*)g_wbf_lo + (size_t)ch * 32768;
    #pragma unroll
    for (int r = 0; r < 4; ++r) {
        int i = (tid + 512 * r) * 16;
        CPASYNC16(dst + i, srcH + i);
        CPASYNC16(dst + 32768 + i, srcL + i);
    }
    asm volatile("cp.async.commit_group;");
}

__device__ __forceinline__ void build_A(int ch, char* smem, uint32_t aoff,
                                        const float* xtb, int tid) {
    int t  = ch >> 2;
    int c0 = (ch & 3) * 64;
    const float4*  cw4 = (const float4*)(smem + DS_CW);
    const ushort4* ci4 = (const ushort4*)(smem + DS_CI);
    #pragma unroll
    for (int it = 0; it < 4; ++it) {
        int e = it * 512 + tid;
        int m = e >> 4, q = e & 15;
        int ce = m * 9 + t;
        float4  w  = cw4[ce];
        ushort4 ix = ci4[ce];
        const float* base = xtb + c0 + q * 4;
        float4 s0 = *(const float4*)(base + ((int)ix.x << 8));
        float4 s1 = *(const float4*)(base + ((int)ix.y << 8));
        float4 s2 = *(const float4*)(base + ((int)ix.z << 8));
        float4 s3 = *(const float4*)(base + ((int)ix.w << 8));
        float v0 = w.x*s0.x + w.y*s1.x + w.z*s2.x + w.w*s3.x;
        float v1 = w.x*s0.y + w.y*s1.y + w.z*s2.y + w.w*s3.y;
        float v2 = w.x*s0.z + w.y*s1.z + w.z*s2.z + w.w*s3.z;
        float v3 = w.x*s0.w + w.y*s1.w + w.z*s2.w + w.w*s3.w;
        __nv_bfloat16 h0 = __float2bfloat16(v0);
        __nv_bfloat16 h1 = __float2bfloat16(v1);
        __nv_bfloat16 h2 = __float2bfloat16(v2);
        __nv_bfloat16 h3 = __float2bfloat16(v3);
        __nv_bfloat16 l0 = __float2bfloat16(v0 - __bfloat162float(h0));
        __nv_bfloat16 l1 = __float2bfloat16(v1 - __bfloat162float(h1));
        __nv_bfloat16 l2 = __float2bfloat16(v2 - __bfloat162float(h2));
        __nv_bfloat16 l3 = __float2bfloat16(v3 - __bfloat162float(h3));
        uint32_t sw = swz128((uint32_t)(m * 128 + q * 8));
        __nv_bfloat162* ph = (__nv_bfloat162*)(smem + aoff + sw);
        __nv_bfloat162* pl = (__nv_bfloat162*)(smem + aoff + 16384 + sw);
        ph[0] = __nv_bfloat162(h0, h1);
        ph[1] = __nv_bfloat162(h2, h3);
        pl[0] = __nv_bfloat162(l0, l1);
        pl[1] = __nv_bfloat162(l2, l3);
    }
}

__global__ __launch_bounds__(512, 1) void deform_gemm(float* __restrict__ out) {
    extern __shared__ char smem[];
    uint32_t sb = smem_u32(smem);
    int tid = threadIdx.x, wid = tid >> 5, lid = tid & 31;
    int mw = wid & 3, nw = wid >> 2;
    int blk = blockIdx.x;
    int b    = blk >> 5;
    int hw0  = (blk & 31) << 7;
    const float* xtb = g_xt + (size_t)b * HWSZ * CIN;

    issue_B(0, sb + DS_B0, tid);

    float4*  cw4 = (float4*)(smem + DS_CW);
    ushort4* ci4 = (ushort4*)(smem + DS_CI);
    for (int e = tid; e < 128 * KTAP; e += 512) {
        int ml = e / 9, k = e - ml * 9;
        int hw = hw0 + ml;
        int hh = hw >> 6, wp = hw & 63;
        float dy = g_offs[(b * OFFC + 2 * k) * HWSZ + hw];
        float dx = g_offs[(b * OFFC + 2 * k + 1) * HWSZ + hw];
        int ky = k / 3, kx = k - ky * 3;
        float py = (float)(hh - 1 + ky) + dy;
        float px = (float)(wp - 1 + kx) + dx;
        float y0f = floorf(py), x0f = floorf(px);
        float ty = py - y0f, tx = px - x0f;
        int y0 = (int)y0f, x0 = (int)x0f;
        float wv[4]; unsigned short iv[4];
        #pragma unroll
        for (int j = 0; j < 4; ++j) {
            int yj = y0 + (j >> 1);
            int xj = x0 + (j & 1);
            float wj = ((j >> 1) ? ty : 1.0f - ty) * ((j & 1) ? tx : 1.0f - tx);
            bool ok = (yj >= 0) && (yj < HH) && (xj >= 0) && (xj < WW);
            wv[j] = ok ? wj : 0.0f;
            iv[j] = ok ? (unsigned short)(yj * WW + xj) : 0;
        }
        cw4[e] = make_float4(wv[0], wv[1], wv[2], wv[3]);
        ci4[e] = make_ushort4(iv[0], iv[1], iv[2], iv[3]);
    }
    __syncthreads();
    build_A(0, smem, DS_A0, xtb, tid);
    asm volatile("cp.async.wait_group 0;" ::: "memory");
    __syncthreads();

    uint32_t amask = (uint32_t)((lid & 7) * 16);
    uint32_t ahalf = (lid >> 4) ? 16u : 0u;
    uint32_t arowoff = (uint32_t)((mw * 32 + (lid & 15)) * 128);
    int brow_in = (lid & 7) + ((lid >> 4) << 3);
    uint32_t bhalf = ((lid >> 3) & 1) ? 16u : 0u;
    uint32_t browoff = (uint32_t)((nw * 64 + brow_in) * 128);

    float acc[2][8][4];
    #pragma unroll
    for (int i = 0; i < 2; ++i)
        #pragma unroll
        for (int j = 0; j < 8; ++j)
            #pragma unroll
            for (int q = 0; q < 4; ++q) acc[i][j][q] = 0.0f;

    for (int ch = 0; ch < 36; ++ch) {
        uint32_t aoff  = (ch & 1) ? DS_A1 : DS_A0;
        uint32_t boff  = (ch & 1) ? DS_B1 : DS_B0;
        uint32_t anoff = (ch & 1) ? DS_A0 : DS_A1;
        uint32_t bnoff = (ch & 1) ? DS_B0 : DS_B1;
        if (ch < 35) issue_B(ch + 1, sb + bnoff, tid);

        #pragma unroll
        for (int kk = 0; kk < 4; ++kk) {
            uint32_t acol = ((uint32_t)(kk * 32) + ahalf) ^ amask;
            uint32_t a_hi[2][4], a_lo[2][4];
            #pragma unroll
            for (int i = 0; i < 2; ++i) {
                uint32_t aa = sb + aoff + arowoff + (uint32_t)(i * 2048) + acol;
                LDSM4(a_hi[i][0], a_hi[i][1], a_hi[i][2], a_hi[i][3], aa);
                LDSM4(a_lo[i][0], a_lo[i][1], a_lo[i][2], a_lo[i][3], aa + 16384);
            }
            uint32_t bcol = ((uint32_t)(kk * 32) + bhalf) ^ amask;
            #pragma unroll
            for (int j2 = 0; j2 < 4; ++j2) {
                uint32_t bb = sb + boff + browoff + (uint32_t)(j2 * 2048) + bcol;
                uint32_t bh[4], bl[4];
                LDSM4(bh[0], bh[1], bh[2], bh[3], bb);
                LDSM4(bl[0], bl[1], bl[2], bl[3], bb + 32768);
                #pragma unroll
                for (int i = 0; i < 2; ++i) {
                    MMA16816(acc[i][2*j2],   a_hi[i], bh[0], bh[1]);
                    MMA16816(acc[i][2*j2],   a_lo[i], bh[0], bh[1]);
                    MMA16816(acc[i][2*j2],   a_hi[i], bl[0], bl[1]);
                    MMA16816(acc[i][2*j2+1], a_hi[i], bh[2], bh[3]);
                    MMA16816(acc[i][2*j2+1], a_lo[i], bh[2], bh[3]);
                    MMA16816(acc[i][2*j2+1], a_hi[i], bl[2], bl[3]);
                }
            }
        }

        if (ch < 35) build_A(ch + 1, smem, anoff, xtb, tid);
        asm volatile("cp.async.wait_group 0;" ::: "memory");
        __syncthreads();
    }

    // epilogue: stage accumulators into smem tile [n][m] (stride 132, conflict-free),
    // then fully coalesced float4 stores to out [b][n][hw]
    float* etile = (float*)(smem + DS_TILE);
    int mrow = lid >> 2;
    int ncol = (lid & 3) * 2;
    #pragma unroll
    for (int i = 0; i < 2; ++i) {
        int ml = mw * 32 + i * 16 + mrow;
        #pragma unroll
        for (int j = 0; j < 8; ++j) {
            int n = nw * 64 + j * 8 + ncol;
            etile[n * 132 + ml]           = acc[i][j][0];
            etile[(n + 1) * 132 + ml]     = acc[i][j][1];
            etile[n * 132 + ml + 8]       = acc[i][j][2];
            etile[(n + 1) * 132 + ml + 8] = acc[i][j][3];
        }
    }

    // fused GroupNorm partial reduction (register-based, overlaps staging sync)
    #pragma unroll
    for (int j = 0; j < 8; ++j) {
        float s = 0.0f, sq = 0.0f;
        #pragma unroll
        for (int i = 0; i < 2; ++i)
            #pragma unroll
            for (int q = 0; q < 4; ++q) {
                float v = acc[i][j][q];
                s += v; sq += v * v;
            }
        #pragma unroll
        for (int off = 16; off > 0; off >>= 1) {
            s  += __shfl_xor_sync(0xFFFFFFFF, s,  off);
            sq += __shfl_xor_sync(0xFFFFFFFF, sq, off);
        }
        if (lid == 0) {
            int bg = b * GN_GROUPS + nw * 8 + j;
            atomicAdd(&g_part[bg * 2 + 0], s);
            atomicAdd(&g_part[bg * 2 + 1], sq);
        }
    }
    __syncthreads();

    #pragma unroll
    for (int it = 0; it < 16; ++it) {
        int e = it * 512 + tid;        // over 256n x 32 float4
        int n  = e >> 5;
        int mq = e & 31;
        float4 v = ((const float4*)(etile + n * 132))[mq];
        *(float4*)(out + (((size_t)(b * COUT + n)) << 12) + hw0 + mq * 4) = v;
    }
}

// ---------------- GN finalize: partials -> (mean, rstd) ----------------------
__global__ void gn_finalize() {
    int bg = threadIdx.x;
    if (bg >= NB * GN_GROUPS) return;
    float n = (float)(CPG * HWSZ);
    float mean = g_part[bg * 2 + 0] / n;
    float var  = g_part[bg * 2 + 1] / n - mean * mean;
    g_stats[bg * 2 + 0] = mean;
    g_stats[bg * 2 + 1] = rsqrtf(var + EPS);
}

// ---------------- GroupNorm apply + ReLU (float4) -----------------------------
__global__ void gn_apply(float* __restrict__ out,
                         const float* __restrict__ gamma,
                         const float* __restrict__ beta) {
    int i = blockIdx.x * 256 + threadIdx.x;       // float4 over 4*256*4096/4
    int c = (i >> 10) & 255;
    int b = i >> 18;
    int bg = b * GN_GROUPS + (c >> 3);
    float mean = g_stats[bg * 2 + 0];
    float rstd = g_stats[bg * 2 + 1];
    float gmul = rstd * gamma[c];
    float add  = beta[c] - mean * gmul;
    float4 v = ((const float4*)out)[i];
    v.x = fmaxf(v.x * gmul + add, 0.0f);
    v.y = fmaxf(v.y * gmul + add, 0.0f);
    v.z = fmaxf(v.z * gmul + add, 0.0f);
    v.w = fmaxf(v.w * gmul + add, 0.0f);
    ((float4*)out)[i] = v;
}

// ---------------- launch ------------------------------------------------------
extern "C" void kernel_launch(void* const* d_in, const int* in_sizes, int n_in,
                              void* d_out, int out_size) {
    const float* x   = (const float*)d_in[0];
    const float* ow  = (const float*)d_in[1];
    const float* ob  = (const float*)d_in[2];
    const float* dw  = (const float*)d_in[3];
    const float* gam = (const float*)d_in[4];
    const float* bet = (const float*)d_in[5];
    float* out = (float*)d_out;

    cudaFuncSetAttribute(deform_gemm, cudaFuncAttributeMaxDynamicSharedMemorySize, DS_TOT);
    cudaFuncSetAttribute(offset_conv_mma, cudaFuncAttributeMaxDynamicSharedMemorySize, OS_TOT);

    prep_wbf<<<(KTAP * 4 * 16384 + 255) / 256, 256>>>(dw);
    prep_owbf<<<(KTAP * 4 * 2048 + 255) / 256, 256>>>(ow);
    transpose_x<<<dim3(HWSZ / 32, CIN / 32, NB), dim3(32, 8)>>>(x);
    offset_conv_mma<<<512, 256, OS_TOT>>>();
    combine_offs<<<(NB * OFFC * HWSZ / 4 + 255) / 256, 256>>>(ob);
    deform_gemm<<<128, 512, DS_TOT>>>(out);
    gn_finalize<<<1, 128>>>();
    gn_apply<<<(NB * COUT * HWSZ / 4 + 255) / 256, 256>>>(out, gam, bet);
}

// round 12
// speedup vs baseline: 2.8220x; 1.0610x over previous
#include <cuda_runtime.h>
#include <cuda_bf16.h>
#include <cstdint>

#define NB   4
#define CIN  256
#define COUT 256
#define HH   64
#define WW   64
#define HWSZ 4096
#define KTAP 9
#define OFFC 18
#define GN_GROUPS 32
#define CPG  8
#define EPS  1e-5f

// ---------------- scratch ----------------
__device__ float g_xt[NB * HWSZ * CIN];              // x as [b][hw][c]
__device__ float g_offs[NB * OFFC * HWSZ];           // offsets [b][ch][hw]
__device__ float g_offp[2 * NB * OFFC * HWSZ];       // split-K partials
__device__ __nv_bfloat16 g_wbf_hi[KTAP * 4 * 16384]; // deform W hi, SW128 tiles [tap*4+cc][256n x 64k]
__device__ __nv_bfloat16 g_wbf_lo[KTAP * 4 * 16384]; // deform W lo
__device__ __nv_bfloat16 g_owbf_hi[KTAP * 4 * 2048]; // offset W hi, SW128 tiles [tap*4+cc][32n x 64k]
__device__ __nv_bfloat16 g_owbf_lo[KTAP * 4 * 2048]; // offset W lo
__device__ float g_part[NB * GN_GROUPS * 2];         // GN partial (sum, sumsq)
__device__ float g_stats[NB * GN_GROUPS * 2];        // (mean, rstd)

__device__ __forceinline__ uint32_t smem_u32(const void* p) {
    uint32_t a;
    asm("{ .reg .u64 t; cvta.to.shared.u64 t, %1; cvt.u32.u64 %0, t; }" : "=r"(a) : "l"(p));
    return a;
}
__device__ __forceinline__ uint32_t swz128(uint32_t b) { return b ^ ((b >> 3) & 0x70); }

#define LDSM4(r0,r1,r2,r3,addr) \
    asm volatile("ldmatrix.sync.aligned.m8n8.x4.shared.b16 {%0,%1,%2,%3}, [%4];" \
        : "=r"(r0),"=r"(r1),"=r"(r2),"=r"(r3) : "r"(addr))

#define MMA16816(d, a, b0, b1) \
    asm volatile("mma.sync.aligned.m16n8k16.row.col.f32.bf16.bf16.f32 " \
        "{%0,%1,%2,%3}, {%4,%5,%6,%7}, {%8,%9}, {%0,%1,%2,%3};" \
        : "+f"((d)[0]),"+f"((d)[1]),"+f"((d)[2]),"+f"((d)[3]) \
        : "r"((a)[0]),"r"((a)[1]),"r"((a)[2]),"r"((a)[3]),"r"(b0),"r"(b1))

#define CPASYNC16(dst, src) \
    asm volatile("cp.async.cg.shared.global [%0], [%1], 16;" :: "r"(dst), "l"(src))

// ---------------- prep: deform weight -> bf16 hi/lo, SW128-swizzled ----------
__global__ void prep_wbf(const float* __restrict__ dw) {
    int i = blockIdx.x * 256 + threadIdx.x;     // over 9*4*16384
    if (i >= KTAP * 4 * 16384) return;
    int t  = i >> 16;
    int r  = i & 65535;
    int cc = r >> 14;
    int r2 = r & 16383;
    int n  = r2 >> 6;
    int k  = r2 & 63;
    float v = dw[n * (CIN * KTAP) + (cc * 64 + k) * KTAP + t];
    __nv_bfloat16 hi = __float2bfloat16(v);
    __nv_bfloat16 lo = __float2bfloat16(v - __bfloat162float(hi));
    uint32_t sw = swz128((uint32_t)(n * 128 + k * 2)) >> 1;
    int base = (t * 4 + cc) * 16384;
    g_wbf_hi[base + sw] = hi;
    g_wbf_lo[base + sw] = lo;
}

// ---------------- prep: offset weight -> bf16 hi/lo SW128 [32n x 64k] tiles --
__global__ void prep_owbf(const float* __restrict__ ow) {
    int i = blockIdx.x * 256 + threadIdx.x;     // over 36*2048
    if (blockIdx.x == 0 && threadIdx.x < NB * GN_GROUPS * 2)
        g_part[threadIdx.x] = 0.0f;             // zero GN partials
    if (i >= KTAP * 4 * 2048) return;
    int ch = i >> 11;
    int r  = i & 2047;
    int n  = r >> 6;
    int k  = r & 63;
    int t  = ch >> 2;
    int cc = ch & 3;
    float v = (n < OFFC) ? ow[n * (CIN * KTAP) + (cc * 64 + k) * KTAP + t] : 0.0f;
    __nv_bfloat16 hi = __float2bfloat16(v);
    __nv_bfloat16 lo = __float2bfloat16(v - __bfloat162float(hi));
    uint32_t sw = swz128((uint32_t)(n * 128 + k * 2)) >> 1;
    g_owbf_hi[ch * 2048 + sw] = hi;
    g_owbf_lo[ch * 2048 + sw] = lo;
}

// ---------------- transpose x [b][c][hw] -> [b][hw][c] -----------------------
__global__ void transpose_x(const float* __restrict__ x) {
    __shared__ float t[32][33];
    int b   = blockIdx.z;
    int hw0 = blockIdx.x * 32;
    int c0  = blockIdx.y * 32;
    int tx  = threadIdx.x, ty = threadIdx.y;
    #pragma unroll
    for (int i = ty; i < 32; i += 8)
        t[i][tx] = x[((b * CIN + c0 + i) << 12) + hw0 + tx];
    __syncthreads();
    #pragma unroll
    for (int i = ty; i < 32; i += 8)
        g_xt[(size_t)((b << 12) + hw0 + i) * CIN + c0 + tx] = t[tx][i];
}

// ---------------- offset conv v4: split-K(2) pipelined HMMA ------------------
#define OS_A0  0                      // 16KB: hi 8K | lo 8K
#define OS_A1  16384
#define OS_B0  32768                  // 8KB: hi 4K | lo 4K
#define OS_B1  40960
#define OS_TOT 49152

__device__ __forceinline__ void issue_OB(int ch, uint32_t dst, int tid) {
    const char* srcH = (const char*)g_owbf_hi + (size_t)ch * 4096;
    const char* srcL = (const char*)g_owbf_lo + (size_t)ch * 4096;
    int i = tid * 16;
    CPASYNC16(dst + i, srcH + i);
    CPASYNC16(dst + 4096 + i, srcL + i);
    asm volatile("cp.async.commit_group;");
}

__device__ __forceinline__ void build_OA(int ch, char* osm, uint32_t aoff,
                                         const float* xtb, int hh, int tid) {
    int t  = ch >> 2;
    int c0 = (ch & 3) * 64;
    int dyt = t / 3 - 1, dxt = t % 3 - 1;
    int yy = hh + dyt;
    bool rowok = ((unsigned)yy < 64u);
    #pragma unroll
    for (int it = 0; it < 4; ++it) {
        int e = it * 256 + tid;       // 0..1023 = 64m x 16q
        int m = e >> 4, q = e & 15;
        int xx = m + dxt;
        float4 v = make_float4(0.f, 0.f, 0.f, 0.f);
        if (rowok && (unsigned)xx < 64u)
            v = *(const float4*)(xtb + (((yy << 6) + xx) << 8) + c0 + q * 4);
        __nv_bfloat16 h0 = __float2bfloat16(v.x);
        __nv_bfloat16 h1 = __float2bfloat16(v.y);
        __nv_bfloat16 h2 = __float2bfloat16(v.z);
        __nv_bfloat16 h3 = __float2bfloat16(v.w);
        __nv_bfloat16 l0 = __float2bfloat16(v.x - __bfloat162float(h0));
        __nv_bfloat16 l1 = __float2bfloat16(v.y - __bfloat162float(h1));
        __nv_bfloat16 l2 = __float2bfloat16(v.z - __bfloat162float(h2));
        __nv_bfloat16 l3 = __float2bfloat16(v.w - __bfloat162float(h3));
        uint32_t sw = swz128((uint32_t)(m * 128 + q * 8));
        __nv_bfloat162* ph = (__nv_bfloat162*)(osm + aoff + sw);
        __nv_bfloat162* pl = (__nv_bfloat162*)(osm + aoff + 8192 + sw);
        ph[0] = __nv_bfloat162(h0, h1);
        ph[1] = __nv_bfloat162(h2, h3);
        pl[0] = __nv_bfloat162(l0, l1);
        pl[1] = __nv_bfloat162(l2, l3);
    }
}

__global__ __launch_bounds__(256) void offset_conv_mma() {
    extern __shared__ char osm[];
    uint32_t sb = smem_u32(osm);
    int tid = threadIdx.x, wid = tid >> 5, lid = tid & 31;
    int mw = wid & 3, nw = wid >> 2;
    int blk = blockIdx.x;             // 0..511 = 2half x 4b x 64hh
    int half = blk >> 8;
    int b    = (blk >> 6) & 3;
    int hh   = blk & 63;
    int hw0  = hh << 6;
    int ch0  = half * 18;
    const float* xtb = g_xt + (size_t)b * HWSZ * CIN;

    issue_OB(ch0, sb + OS_B0, tid);
    build_OA(ch0, osm, OS_A0, xtb, hh, tid);
    asm volatile("cp.async.wait_group 0;" ::: "memory");
    __syncthreads();

    uint32_t amask = (uint32_t)((lid & 7) * 16);
    uint32_t ahalf = (lid >> 4) ? 16u : 0u;
    uint32_t arowoff = (uint32_t)((mw * 16 + (lid & 15)) * 128);
    int brow_in = (lid & 7) + ((lid >> 4) << 3);
    uint32_t bhalf = ((lid >> 3) & 1) ? 16u : 0u;
    uint32_t browoff = (uint32_t)((nw * 16 + brow_in) * 128);

    float acc[2][4];
    #pragma unroll
    for (int j = 0; j < 2; ++j)
        #pragma unroll
        for (int q = 0; q < 4; ++q) acc[j][q] = 0.0f;

    for (int lch = 0; lch < 18; ++lch) {
        uint32_t aoff  = (lch & 1) ? OS_A1 : OS_A0;
        uint32_t boff  = (lch & 1) ? OS_B1 : OS_B0;
        uint32_t anoff = (lch & 1) ? OS_A0 : OS_A1;
        uint32_t bnoff = (lch & 1) ? OS_B0 : OS_B1;
        if (lch < 17) issue_OB(ch0 + lch + 1, sb + bnoff, tid);

        #pragma unroll
        for (int kk = 0; kk < 4; ++kk) {
            uint32_t acol = ((uint32_t)(kk * 32) + ahalf) ^ amask;
            uint32_t aa = sb + aoff + arowoff + acol;
            uint32_t a_hi[4], a_lo[4];
            LDSM4(a_hi[0], a_hi[1], a_hi[2], a_hi[3], aa);
            LDSM4(a_lo[0], a_lo[1], a_lo[2], a_lo[3], aa + 8192);
            uint32_t bcol = ((uint32_t)(kk * 32) + bhalf) ^ amask;
            uint32_t bb = sb + boff + browoff + bcol;
            uint32_t bh[4], bl[4];
            LDSM4(bh[0], bh[1], bh[2], bh[3], bb);
            LDSM4(bl[0], bl[1], bl[2], bl[3], bb + 4096);
            MMA16816(acc[0], a_hi, bh[0], bh[1]);
            MMA16816(acc[0], a_lo, bh[0], bh[1]);
            MMA16816(acc[0], a_hi, bl[0], bl[1]);
            MMA16816(acc[1], a_hi, bh[2], bh[3]);
            MMA16816(acc[1], a_lo, bh[2], bh[3]);
            MMA16816(acc[1], a_hi, bl[2], bl[3]);
        }

        if (lch < 17) build_OA(ch0 + lch + 1, osm, anoff, xtb, hh, tid);
        asm volatile("cp.async.wait_group 0;" ::: "memory");
        __syncthreads();
    }

    float* dst = g_offp + (size_t)half * (NB * OFFC * HWSZ);
    int mrow = lid >> 2, ncol = (lid & 3) * 2;
    int m = hw0 + mw * 16 + mrow;
    #pragma unroll
    for (int j2 = 0; j2 < 2; ++j2) {
        int n = nw * 16 + j2 * 8 + ncol;
        if (n < OFFC) {
            dst[(b * OFFC + n) * HWSZ + m]     = acc[j2][0];
            dst[(b * OFFC + n) * HWSZ + m + 8] = acc[j2][2];
        }
        if (n + 1 < OFFC) {
            dst[(b * OFFC + n + 1) * HWSZ + m]     = acc[j2][1];
            dst[(b * OFFC + n + 1) * HWSZ + m + 8] = acc[j2][3];
        }
    }
}

// ---------------- combine split-K halves + bias ------------------------------
__global__ void combine_offs(const float* __restrict__ bias) {
    int i = blockIdx.x * 256 + threadIdx.x;     // float4 over NB*OFFC*HWSZ/4
    if (i >= NB * OFFC * HWSZ / 4) return;
    int o = (i >> 10) % OFFC;
    float bv = bias[o];
    float4 a = ((const float4*)g_offp)[i];
    float4 c = ((const float4*)(g_offp + NB * OFFC * HWSZ))[i];
    float4 r = make_float4(a.x + c.x + bv, a.y + c.y + bv, a.z + c.z + bv, a.w + c.w + bv);
    ((float4*)g_offs)[i] = r;
}

// ---------------- deformable conv: interleaved-pipeline mma.sync bf16-split --
// 128 CTAs x 512 thr. CTA tile 128m x 256n, 16 warps 4m x 4n.
// Per kk MMA step: issue next-chunk gather LDGs (regs), MMA, convert+store.
#define DS_CW   0                          // float4 cwgt[1152]  (18432 B)
#define DS_CI   18432                      // ushort4 cidx[1152] (9216 B)
#define DS_A0   27648                      // 32KB: hi 16K | lo 16K
#define DS_A1   (DS_A0 + 32768)
#define DS_B0   (DS_A1 + 32768)            // 64KB: hi 32K | lo 32K
#define DS_B1   (DS_B0 + 65536)
#define DS_TOT  (DS_B1 + 65536)            // 224256 B
#define DS_TILE DS_A0                      // epilogue staging (256n x 132 f)

__device__ __forceinline__ void issue_B(int ch, uint32_t dst, int tid) {
    const char* srcH = (const char*)g_wbf_hi + (size_t)ch * 32768;
    const char* srcL = (const char*)g_wbf_lo + (size_t)ch * 32768;
    #pragma unroll
    for (int r = 0; r < 4; ++r) {
        int i = (tid + 512 * r) * 16;
        CPASYNC16(dst + i, srcH + i);
        CPASYNC16(dst + 32768 + i, srcL + i);
    }
    asm volatile("cp.async.commit_group;");
}

__global__ __launch_bounds__(512, 1) void deform_gemm(float* __restrict__ out) {
    extern __shared__ char smem[];
    uint32_t sb = smem_u32(smem);
    int tid = threadIdx.x, wid = tid >> 5, lid = tid & 31;
    int mw = wid & 3, nw = wid >> 2;
    int blk = blockIdx.x;
    int b    = blk >> 5;
    int hw0  = (blk & 31) << 7;
    const float* xtb = g_xt + (size_t)b * HWSZ * CIN;

    issue_B(0, sb + DS_B0, tid);

    float4*  cw4 = (float4*)(smem + DS_CW);
    ushort4* ci4 = (ushort4*)(smem + DS_CI);
    for (int e = tid; e < 128 * KTAP; e += 512) {
        int ml = e / 9, k = e - ml * 9;
        int hw = hw0 + ml;
        int hh = hw >> 6, wp = hw & 63;
        float dy = g_offs[(b * OFFC + 2 * k) * HWSZ + hw];
        float dx = g_offs[(b * OFFC + 2 * k + 1) * HWSZ + hw];
        int ky = k / 3, kx = k - ky * 3;
        float py = (float)(hh - 1 + ky) + dy;
        float px = (float)(wp - 1 + kx) + dx;
        float y0f = floorf(py), x0f = floorf(px);
        float ty = py - y0f, tx = px - x0f;
        int y0 = (int)y0f, x0 = (int)x0f;
        float wv[4]; unsigned short iv[4];
        #pragma unroll
        for (int j = 0; j < 4; ++j) {
            int yj = y0 + (j >> 1);
            int xj = x0 + (j & 1);
            float wj = ((j >> 1) ? ty : 1.0f - ty) * ((j & 1) ? tx : 1.0f - tx);
            bool ok = (yj >= 0) && (yj < HH) && (xj >= 0) && (xj < WW);
            wv[j] = ok ? wj : 0.0f;
            iv[j] = ok ? (unsigned short)(yj * WW + xj) : 0;
        }
        cw4[e] = make_float4(wv[0], wv[1], wv[2], wv[3]);
        ci4[e] = make_ushort4(iv[0], iv[1], iv[2], iv[3]);
    }
    __syncthreads();

    // build chunk 0 A tile (un-pipelined prologue)
    {
        int c0 = 0;
        #pragma unroll
        for (int it = 0; it < 4; ++it) {
            int e = it * 512 + tid;
            int m = e >> 4, q = e & 15;
            int ce = m * 9;                      // tap 0
            float4  w  = cw4[ce];
            ushort4 ix = ci4[ce];
            const float* base = xtb + c0 + q * 4;
            float4 s0 = *(const float4*)(base + ((int)ix.x << 8));
            float4 s1 = *(const float4*)(base + ((int)ix.y << 8));
            float4 s2 = *(const float4*)(base + ((int)ix.z << 8));
            float4 s3 = *(const float4*)(base + ((int)ix.w << 8));
            float v0 = w.x*s0.x + w.y*s1.x + w.z*s2.x + w.w*s3.x;
            float v1 = w.x*s0.y + w.y*s1.y + w.z*s2.y + w.w*s3.y;
            float v2 = w.x*s0.z + w.y*s1.z + w.z*s2.z + w.w*s3.z;
            float v3 = w.x*s0.w + w.y*s1.w + w.z*s2.w + w.w*s3.w;
            __nv_bfloat16 h0 = __float2bfloat16(v0);
            __nv_bfloat16 h1 = __float2bfloat16(v1);
            __nv_bfloat16 h2 = __float2bfloat16(v2);
            __nv_bfloat16 h3 = __float2bfloat16(v3);
            __nv_bfloat16 l0 = __float2bfloat16(v0 - __bfloat162float(h0));
            __nv_bfloat16 l1 = __float2bfloat16(v1 - __bfloat162float(h1));
            __nv_bfloat16 l2 = __float2bfloat16(v2 - __bfloat162float(h2));
            __nv_bfloat16 l3 = __float2bfloat16(v3 - __bfloat162float(h3));
            uint32_t sw = swz128((uint32_t)(m * 128 + q * 8));
            __nv_bfloat162* ph = (__nv_bfloat162*)(smem + DS_A0 + sw);
            __nv_bfloat162* pl = (__nv_bfloat162*)(smem + DS_A0 + 16384 + sw);
            ph[0] = __nv_bfloat162(h0, h1);
            ph[1] = __nv_bfloat162(h2, h3);
            pl[0] = __nv_bfloat162(l0, l1);
            pl[1] = __nv_bfloat162(l2, l3);
        }
    }
    asm volatile("cp.async.wait_group 0;" ::: "memory");
    __syncthreads();

    uint32_t amask = (uint32_t)((lid & 7) * 16);
    uint32_t ahalf = (lid >> 4) ? 16u : 0u;
    uint32_t arowoff = (uint32_t)((mw * 32 + (lid & 15)) * 128);
    int brow_in = (lid & 7) + ((lid >> 4) << 3);
    uint32_t bhalf = ((lid >> 3) & 1) ? 16u : 0u;
    uint32_t browoff = (uint32_t)((nw * 64 + brow_in) * 128);

    float acc[2][8][4];
    #pragma unroll
    for (int i = 0; i < 2; ++i)
        #pragma unroll
        for (int j = 0; j < 8; ++j)
            #pragma unroll
            for (int q = 0; q < 4; ++q) acc[i][j][q] = 0.0f;

    for (int ch = 0; ch < 36; ++ch) {
        uint32_t aoff  = (ch & 1) ? DS_A1 : DS_A0;
        uint32_t boff  = (ch & 1) ? DS_B1 : DS_B0;
        uint32_t anoff = (ch & 1) ? DS_A0 : DS_A1;
        uint32_t bnoff = (ch & 1) ? DS_B0 : DS_B1;
        bool dob = (ch < 35);
        if (dob) issue_B(ch + 1, sb + bnoff, tid);
        int tn  = (ch + 1) >> 2;
        int c0n = ((ch + 1) & 3) * 64;

        #pragma unroll
        for (int kk = 0; kk < 4; ++kk) {
            // ---- issue gathers for next chunk's build iteration it=kk ----
            float4 gw; float4 s0, s1, s2, s3;
            int gm = 0, gq = 0;
            if (dob) {
                int e = kk * 512 + tid;
                gm = e >> 4; gq = e & 15;
                int ce = gm * 9 + tn;
                gw = cw4[ce];
                ushort4 gix = ci4[ce];
                const float* gbase = xtb + c0n + gq * 4;
                s0 = *(const float4*)(gbase + ((int)gix.x << 8));
                s1 = *(const float4*)(gbase + ((int)gix.y << 8));
                s2 = *(const float4*)(gbase + ((int)gix.z << 8));
                s3 = *(const float4*)(gbase + ((int)gix.w << 8));
            }

            // ---- MMA step kk ----
            uint32_t acol = ((uint32_t)(kk * 32) + ahalf) ^ amask;
            uint32_t a_hi[2][4], a_lo[2][4];
            #pragma unroll
            for (int i = 0; i < 2; ++i) {
                uint32_t aa = sb + aoff + arowoff + (uint32_t)(i * 2048) + acol;
                LDSM4(a_hi[i][0], a_hi[i][1], a_hi[i][2], a_hi[i][3], aa);
                LDSM4(a_lo[i][0], a_lo[i][1], a_lo[i][2], a_lo[i][3], aa + 16384);
            }
            uint32_t bcol = ((uint32_t)(kk * 32) + bhalf) ^ amask;
            #pragma unroll
            for (int j2 = 0; j2 < 4; ++j2) {
                uint32_t bb = sb + boff + browoff + (uint32_t)(j2 * 2048) + bcol;
                uint32_t bh[4], bl[4];
                LDSM4(bh[0], bh[1], bh[2], bh[3], bb);
                LDSM4(bl[0], bl[1], bl[2], bl[3], bb + 32768);
                #pragma unroll
                for (int i = 0; i < 2; ++i) {
                    MMA16816(acc[i][2*j2],   a_hi[i], bh[0], bh[1]);
                    MMA16816(acc[i][2*j2],   a_lo[i], bh[0], bh[1]);
                    MMA16816(acc[i][2*j2],   a_hi[i], bl[0], bl[1]);
                    MMA16816(acc[i][2*j2+1], a_hi[i], bh[2], bh[3]);
                    MMA16816(acc[i][2*j2+1], a_lo[i], bh[2], bh[3]);
                    MMA16816(acc[i][2*j2+1], a_hi[i], bl[2], bl[3]);
                }
            }

            // ---- convert + store next chunk A (it=kk) ----
            if (dob) {
                float v0 = gw.x*s0.x + gw.y*s1.x + gw.z*s2.x + gw.w*s3.x;
                float v1 = gw.x*s0.y + gw.y*s1.y + gw.z*s2.y + gw.w*s3.y;
                float v2 = gw.x*s0.z + gw.y*s1.z + gw.z*s2.z + gw.w*s3.z;
                float v3 = gw.x*s0.w + gw.y*s1.w + gw.z*s2.w + gw.w*s3.w;
                __nv_bfloat16 h0 = __float2bfloat16(v0);
                __nv_bfloat16 h1 = __float2bfloat16(v1);
                __nv_bfloat16 h2 = __float2bfloat16(v2);
                __nv_bfloat16 h3 = __float2bfloat16(v3);
                __nv_bfloat16 l0 = __float2bfloat16(v0 - __bfloat162float(h0));
                __nv_bfloat16 l1 = __float2bfloat16(v1 - __bfloat162float(h1));
                __nv_bfloat16 l2 = __float2bfloat16(v2 - __bfloat162float(h2));
                __nv_bfloat16 l3 = __float2bfloat16(v3 - __bfloat162float(h3));
                uint32_t sw = swz128((uint32_t)(gm * 128 + gq * 8));
                __nv_bfloat162* ph = (__nv_bfloat162*)(smem + anoff + sw);
                __nv_bfloat162* pl = (__nv_bfloat162*)(smem + anoff + 16384 + sw);
                ph[0] = __nv_bfloat162(h0, h1);
                ph[1] = __nv_bfloat162(h2, h3);
                pl[0] = __nv_bfloat162(l0, l1);
                pl[1] = __nv_bfloat162(l2, l3);
            }
        }

        asm volatile("cp.async.wait_group 0;" ::: "memory");
        __syncthreads();
    }

    // epilogue: stage accumulators into smem tile [n][m] (stride 132),
    // then fully coalesced float4 stores to out [b][n][hw]
    float* etile = (float*)(smem + DS_TILE);
    int mrow = lid >> 2;
    int ncol = (lid & 3) * 2;
    #pragma unroll
    for (int i = 0; i < 2; ++i) {
        int ml = mw * 32 + i * 16 + mrow;
        #pragma unroll
        for (int j = 0; j < 8; ++j) {
            int n = nw * 64 + j * 8 + ncol;
            etile[n * 132 + ml]           = acc[i][j][0];
            etile[(n + 1) * 132 + ml]     = acc[i][j][1];
            etile[n * 132 + ml + 8]       = acc[i][j][2];
            etile[(n + 1) * 132 + ml + 8] = acc[i][j][3];
        }
    }

    // fused GroupNorm partial reduction
    #pragma unroll
    for (int j = 0; j < 8; ++j) {
        float s = 0.0f, sq = 0.0f;
        #pragma unroll
        for (int i = 0; i < 2; ++i)
            #pragma unroll
            for (int q = 0; q < 4; ++q) {
                float v = acc[i][j][q];
                s += v; sq += v * v;
            }
        #pragma unroll
        for (int off = 16; off > 0; off >>= 1) {
            s  += __shfl_xor_sync(0xFFFFFFFF, s,  off);
            sq += __shfl_xor_sync(0xFFFFFFFF, sq, off);
        }
        if (lid == 0) {
            int bg = b * GN_GROUPS + nw * 8 + j;
            atomicAdd(&g_part[bg * 2 + 0], s);
            atomicAdd(&g_part[bg * 2 + 1], sq);
        }
    }
    __syncthreads();

    #pragma unroll
    for (int it = 0; it < 16; ++it) {
        int e = it * 512 + tid;        // over 256n x 32 float4
        int n  = e >> 5;
        int mq = e & 31;
        float4 v = ((const float4*)(etile + n * 132))[mq];
        *(float4*)(out + (((size_t)(b * COUT + n)) << 12) + hw0 + mq * 4) = v;
    }
}

// ---------------- GN finalize: partials -> (mean, rstd) ----------------------
__global__ void gn_finalize() {
    int bg = threadIdx.x;
    if (bg >= NB * GN_GROUPS) return;
    float n = (float)(CPG * HWSZ);
    float mean = g_part[bg * 2 + 0] / n;
    float var  = g_part[bg * 2 + 1] / n - mean * mean;
    g_stats[bg * 2 + 0] = mean;
    g_stats[bg * 2 + 1] = rsqrtf(var + EPS);
}

// ---------------- GroupNorm apply + ReLU (float4) -----------------------------
__global__ void gn_apply(float* __restrict__ out,
                         const float* __restrict__ gamma,
                         const float* __restrict__ beta) {
    int i = blockIdx.x * 256 + threadIdx.x;       // float4 over 4*256*4096/4
    int c = (i >> 10) & 255;
    int b = i >> 18;
    int bg = b * GN_GROUPS + (c >> 3);
    float mean = g_stats[bg * 2 + 0];
    float rstd = g_stats[bg * 2 + 1];
    float gmul = rstd * gamma[c];
    float add  = beta[c] - mean * gmul;
    float4 v = ((const float4*)out)[i];
    v.x = fmaxf(v.x * gmul + add, 0.0f);
    v.y = fmaxf(v.y * gmul + add, 0.0f);
    v.z = fmaxf(v.z * gmul + add, 0.0f);
    v.w = fmaxf(v.w * gmul + add, 0.0f);
    ((float4*)out)[i] = v;
}

// ---------------- launch ------------------------------------------------------
extern "C" void kernel_launch(void* const* d_in, const int* in_sizes, int n_in,
                              void* d_out, int out_size) {
    const float* x   = (const float*)d_in[0];
    const float* ow  = (const float*)d_in[1];
    const float* ob  = (const float*)d_in[2];
    const float* dw  = (const float*)d_in[3];
    const float* gam = (const float*)d_in[4];
    const float* bet = (const float*)d_in[5];
    float* out = (float*)d_out;

    cudaFuncSetAttribute(deform_gemm, cudaFuncAttributeMaxDynamicSharedMemorySize, DS_TOT);
    cudaFuncSetAttribute(offset_conv_mma, cudaFuncAttributeMaxDynamicSharedMemorySize, OS_TOT);

    prep_wbf<<<(KTAP * 4 * 16384 + 255) / 256, 256>>>(dw);
    prep_owbf<<<(KTAP * 4 * 2048 + 255) / 256, 256>>>(ow);
    transpose_x<<<dim3(HWSZ / 32, CIN / 32, NB), dim3(32, 8)>>>(x);
    offset_conv_mma<<<512, 256, OS_TOT>>>();
    combine_offs<<<(NB * OFFC * HWSZ / 4 + 255) / 256, 256>>>(ob);
    deform_gemm<<<128, 512, DS_TOT>>>(out);
    gn_finalize<<<1, 128>>>();
    gn_apply<<<(NB * COUT * HWSZ / 4 + 255) / 256, 256>>>(out, gam, bet);
}

// round 14
// speedup vs baseline: 3.6036x; 1.2769x over previous
#include <cuda_runtime.h>
#include <cuda_fp16.h>
#include <cstdint>

#define NB   4
#define CIN  256
#define COUT 256
#define HH   64
#define WW   64
#define HWSZ 4096
#define KTAP 9
#define OFFC 18
#define GN_GROUPS 32
#define CPG  8
#define EPS  1e-5f

// ---------------- scratch ----------------
__device__ float g_xt[NB * HWSZ * CIN];              // x as [b][hw][c]
__device__ float g_offs[NB * OFFC * HWSZ];           // offsets [b][ch][hw]
__device__ float g_offp[2 * NB * OFFC * HWSZ];       // split-K partials
__device__ __half g_wbf[KTAP * 4 * 16384];           // deform W fp16, SW128 tiles [tap*4+cc][256n x 64k]
__device__ __half g_owbf[KTAP * 4 * 2048];           // offset W fp16, SW128 tiles [tap*4+cc][32n x 64k]
__device__ float g_part[NB * GN_GROUPS * 2];         // GN partial (sum, sumsq)
__device__ float g_stats[NB * GN_GROUPS * 2];        // (mean, rstd)

__device__ __forceinline__ uint32_t smem_u32(const void* p) {
    uint32_t a;
    asm("{ .reg .u64 t; cvta.to.shared.u64 t, %1; cvt.u32.u64 %0, t; }" : "=r"(a) : "l"(p));
    return a;
}
__device__ __forceinline__ uint32_t swz128(uint32_t b) { return b ^ ((b >> 3) & 0x70); }

#define LDSM4(r0,r1,r2,r3,addr) \
    asm volatile("ldmatrix.sync.aligned.m8n8.x4.shared.b16 {%0,%1,%2,%3}, [%4];" \
        : "=r"(r0),"=r"(r1),"=r"(r2),"=r"(r3) : "r"(addr))

#define MMAF16(d, a, b0, b1) \
    asm volatile("mma.sync.aligned.m16n8k16.row.col.f32.f16.f16.f32 " \
        "{%0,%1,%2,%3}, {%4,%5,%6,%7}, {%8,%9}, {%0,%1,%2,%3};" \
        : "+f"((d)[0]),"+f"((d)[1]),"+f"((d)[2]),"+f"((d)[3]) \
        : "r"((a)[0]),"r"((a)[1]),"r"((a)[2]),"r"((a)[3]),"r"(b0),"r"(b1))

#define CPASYNC16(dst, src) \
    asm volatile("cp.async.cg.shared.global [%0], [%1], 16;" :: "r"(dst), "l"(src))

// ---------------- prep: deform weight -> fp16, SW128-swizzled ----------------
__global__ void prep_wbf(const float* __restrict__ dw) {
    int i = blockIdx.x * 256 + threadIdx.x;     // over 9*4*16384
    if (i >= KTAP * 4 * 16384) return;
    int t  = i >> 16;
    int r  = i & 65535;
    int cc = r >> 14;
    int r2 = r & 16383;
    int n  = r2 >> 6;
    int k  = r2 & 63;
    float v = dw[n * (CIN * KTAP) + (cc * 64 + k) * KTAP + t];
    uint32_t sw = swz128((uint32_t)(n * 128 + k * 2)) >> 1;
    g_wbf[(t * 4 + cc) * 16384 + sw] = __float2half_rn(v);
}

// ---------------- prep: offset weight -> fp16 SW128 [32n x 64k] tiles --------
__global__ void prep_owbf(const float* __restrict__ ow) {
    int i = blockIdx.x * 256 + threadIdx.x;     // over 36*2048
    if (blockIdx.x == 0 && threadIdx.x < NB * GN_GROUPS * 2)
        g_part[threadIdx.x] = 0.0f;             // zero GN partials
    if (i >= KTAP * 4 * 2048) return;
    int ch = i >> 11;
    int r  = i & 2047;
    int n  = r >> 6;
    int k  = r & 63;
    int t  = ch >> 2;
    int cc = ch & 3;
    float v = (n < OFFC) ? ow[n * (CIN * KTAP) + (cc * 64 + k) * KTAP + t] : 0.0f;
    uint32_t sw = swz128((uint32_t)(n * 128 + k * 2)) >> 1;
    g_owbf[ch * 2048 + sw] = __float2half_rn(v);
}

// ---------------- transpose x [b][c][hw] -> [b][hw][c] -----------------------
__global__ void transpose_x(const float* __restrict__ x) {
    __shared__ float t[32][33];
    int b   = blockIdx.z;
    int hw0 = blockIdx.x * 32;
    int c0  = blockIdx.y * 32;
    int tx  = threadIdx.x, ty = threadIdx.y;
    #pragma unroll
    for (int i = ty; i < 32; i += 8)
        t[i][tx] = x[((b * CIN + c0 + i) << 12) + hw0 + tx];
    __syncthreads();
    #pragma unroll
    for (int i = ty; i < 32; i += 8)
        g_xt[(size_t)((b << 12) + hw0 + i) * CIN + c0 + tx] = t[tx][i];
}

// ---------------- offset conv v5: fp16 single-product, split-K(2) ------------
// 512 CTAs (2 K-halves x 4b x 64row) x 256 thr. CTA tile 64m x 32n, 18 chunks.
#define OS_A0  0                      // 8KB fp16 A
#define OS_A1  8192
#define OS_B0  16384                  // 4KB fp16 B
#define OS_B1  20480
#define OS_TOT 24576

__device__ __forceinline__ void issue_OB(int ch, uint32_t dst, int tid) {
    if (tid < 256) {
        const char* src = (const char*)g_owbf + (size_t)ch * 4096;
        int i = tid * 16;
        CPASYNC16(dst + i, src + i);
    }
    asm volatile("cp.async.commit_group;");
}

__device__ __forceinline__ void build_OA(int ch, char* osm, uint32_t aoff,
                                         const float* xtb, int hh, int tid) {
    int t  = ch >> 2;
    int c0 = (ch & 3) * 64;
    int dyt = t / 3 - 1, dxt = t % 3 - 1;
    int yy = hh + dyt;
    bool rowok = ((unsigned)yy < 64u);
    #pragma unroll
    for (int it = 0; it < 4; ++it) {
        int e = it * 256 + tid;       // 0..1023 = 64m x 16q
        int m = e >> 4, q = e & 15;
        int xx = m + dxt;
        float4 v = make_float4(0.f, 0.f, 0.f, 0.f);
        if (rowok && (unsigned)xx < 64u)
            v = *(const float4*)(xtb + (((yy << 6) + xx) << 8) + c0 + q * 4);
        uint32_t sw = swz128((uint32_t)(m * 128 + q * 8));
        __half2* ph = (__half2*)(osm + aoff + sw);
        ph[0] = __half2(__float2half_rn(v.x), __float2half_rn(v.y));
        ph[1] = __half2(__float2half_rn(v.z), __float2half_rn(v.w));
    }
}

__global__ __launch_bounds__(256) void offset_conv_mma() {
    extern __shared__ char osm[];
    uint32_t sb = smem_u32(osm);
    int tid = threadIdx.x, wid = tid >> 5, lid = tid & 31;
    int mw = wid & 3, nw = wid >> 2;
    int blk = blockIdx.x;             // 0..511 = 2half x 4b x 64hh
    int half = blk >> 8;
    int b    = (blk >> 6) & 3;
    int hh   = blk & 63;
    int hw0  = hh << 6;
    int ch0  = half * 18;
    const float* xtb = g_xt + (size_t)b * HWSZ * CIN;

    issue_OB(ch0, sb + OS_B0, tid);
    build_OA(ch0, osm, OS_A0, xtb, hh, tid);
    asm volatile("cp.async.wait_group 0;" ::: "memory");
    __syncthreads();

    uint32_t amask = (uint32_t)((lid & 7) * 16);
    uint32_t ahalf = (lid >> 4) ? 16u : 0u;
    uint32_t arowoff = (uint32_t)((mw * 16 + (lid & 15)) * 128);
    int brow_in = (lid & 7) + ((lid >> 4) << 3);
    uint32_t bhalf = ((lid >> 3) & 1) ? 16u : 0u;
    uint32_t browoff = (uint32_t)((nw * 16 + brow_in) * 128);

    float acc[2][4];
    #pragma unroll
    for (int j = 0; j < 2; ++j)
        #pragma unroll
        for (int q = 0; q < 4; ++q) acc[j][q] = 0.0f;

    for (int lch = 0; lch < 18; ++lch) {
        uint32_t aoff  = (lch & 1) ? OS_A1 : OS_A0;
        uint32_t boff  = (lch & 1) ? OS_B1 : OS_B0;
        uint32_t anoff = (lch & 1) ? OS_A0 : OS_A1;
        uint32_t bnoff = (lch & 1) ? OS_B0 : OS_B1;
        if (lch < 17) issue_OB(ch0 + lch + 1, sb + bnoff, tid);

        #pragma unroll
        for (int kk = 0; kk < 4; ++kk) {
            uint32_t acol = ((uint32_t)(kk * 32) + ahalf) ^ amask;
            uint32_t aa = sb + aoff + arowoff + acol;
            uint32_t av[4];
            LDSM4(av[0], av[1], av[2], av[3], aa);
            uint32_t bcol = ((uint32_t)(kk * 32) + bhalf) ^ amask;
            uint32_t bb = sb + boff + browoff + bcol;
            uint32_t bh[4];
            LDSM4(bh[0], bh[1], bh[2], bh[3], bb);
            MMAF16(acc[0], av, bh[0], bh[1]);
            MMAF16(acc[1], av, bh[2], bh[3]);
        }

        if (lch < 17) build_OA(ch0 + lch + 1, osm, anoff, xtb, hh, tid);
        asm volatile("cp.async.wait_group 0;" ::: "memory");
        __syncthreads();
    }

    float* dst = g_offp + (size_t)half * (NB * OFFC * HWSZ);
    int mrow = lid >> 2, ncol = (lid & 3) * 2;
    int m = hw0 + mw * 16 + mrow;
    #pragma unroll
    for (int j2 = 0; j2 < 2; ++j2) {
        int n = nw * 16 + j2 * 8 + ncol;
        if (n < OFFC) {
            dst[(b * OFFC + n) * HWSZ + m]     = acc[j2][0];
            dst[(b * OFFC + n) * HWSZ + m + 8] = acc[j2][2];
        }
        if (n + 1 < OFFC) {
            dst[(b * OFFC + n + 1) * HWSZ + m]     = acc[j2][1];
            dst[(b * OFFC + n + 1) * HWSZ + m + 8] = acc[j2][3];
        }
    }
}

// ---------------- combine split-K halves + bias ------------------------------
__global__ void combine_offs(const float* __restrict__ bias) {
    int i = blockIdx.x * 256 + threadIdx.x;     // float4 over NB*OFFC*HWSZ/4
    if (i >= NB * OFFC * HWSZ / 4) return;
    int o = (i >> 10) % OFFC;
    float bv = bias[o];
    float4 a = ((const float4*)g_offp)[i];
    float4 c = ((const float4*)(g_offp + NB * OFFC * HWSZ))[i];
    float4 r = make_float4(a.x + c.x + bv, a.y + c.y + bv, a.z + c.z + bv, a.w + c.w + bv);
    ((float4*)g_offs)[i] = r;
}

// ---------------- deformable conv: fp16 2-product interleaved pipeline -------
// 128 CTAs x 512 thr. CTA tile 128m x 256n, 16 warps 4m x 4n.
// A split fp16 hi/lo (exact v_A), B fp16 hi only (error ~1.6e-4 RMS).
#define DS_CW   0                          // float4 cwgt[1152]  (18432 B)
#define DS_CI   18432                      // ushort4 cidx[1152] (9216 B)
#define DS_A0   27648                      // 32KB: hi 16K | lo 16K
#define DS_A1   (DS_A0 + 32768)
#define DS_B0   (DS_A1 + 32768)            // 32KB fp16 B
#define DS_B1   (DS_B0 + 32768)
#define DS_TILE DS_A0                      // epilogue staging 256x132 f = 135168
#define DS_TOT  (DS_A0 + 135168)           // 162816 B (covers B buffers too)

__device__ __forceinline__ void issue_B(int ch, uint32_t dst, int tid) {
    const char* src = (const char*)g_wbf + (size_t)ch * 32768;
    #pragma unroll
    for (int r = 0; r < 4; ++r) {
        int i = (tid + 512 * r) * 16;
        CPASYNC16(dst + i, src + i);
    }
    asm volatile("cp.async.commit_group;");
}

__global__ __launch_bounds__(512, 1) void deform_gemm(float* __restrict__ out) {
    extern __shared__ char smem[];
    uint32_t sb = smem_u32(smem);
    int tid = threadIdx.x, wid = tid >> 5, lid = tid & 31;
    int mw = wid & 3, nw = wid >> 2;
    int blk = blockIdx.x;
    int b    = blk >> 5;
    int hw0  = (blk & 31) << 7;
    const float* xtb = g_xt + (size_t)b * HWSZ * CIN;

    issue_B(0, sb + DS_B0, tid);

    float4*  cw4 = (float4*)(smem + DS_CW);
    ushort4* ci4 = (ushort4*)(smem + DS_CI);
    for (int e = tid; e < 128 * KTAP; e += 512) {
        int ml = e / 9, k = e - ml * 9;
        int hw = hw0 + ml;
        int hh = hw >> 6, wp = hw & 63;
        float dy = g_offs[(b * OFFC + 2 * k) * HWSZ + hw];
        float dx = g_offs[(b * OFFC + 2 * k + 1) * HWSZ + hw];
        int ky = k / 3, kx = k - ky * 3;
        float py = (float)(hh - 1 + ky) + dy;
        float px = (float)(wp - 1 + kx) + dx;
        float y0f = floorf(py), x0f = floorf(px);
        float ty = py - y0f, tx = px - x0f;
        int y0 = (int)y0f, x0 = (int)x0f;
        float wv[4]; unsigned short iv[4];
        #pragma unroll
        for (int j = 0; j < 4; ++j) {
            int yj = y0 + (j >> 1);
            int xj = x0 + (j & 1);
            float wj = ((j >> 1) ? ty : 1.0f - ty) * ((j & 1) ? tx : 1.0f - tx);
            bool ok = (yj >= 0) && (yj < HH) && (xj >= 0) && (xj < WW);
            wv[j] = ok ? wj : 0.0f;
            iv[j] = ok ? (unsigned short)(yj * WW + xj) : 0;
        }
        cw4[e] = make_float4(wv[0], wv[1], wv[2], wv[3]);
        ci4[e] = make_ushort4(iv[0], iv[1], iv[2], iv[3]);
    }
    __syncthreads();

    // build chunk 0 A tile (un-pipelined prologue)
    {
        #pragma unroll
        for (int it = 0; it < 4; ++it) {
            int e = it * 512 + tid;
            int m = e >> 4, q = e & 15;
            int ce = m * 9;                      // tap 0, chunk 0
            float4  w  = cw4[ce];
            ushort4 ix = ci4[ce];
            const float* base = xtb + q * 4;
            float4 s0 = *(const float4*)(base + ((int)ix.x << 8));
            float4 s1 = *(const float4*)(base + ((int)ix.y << 8));
            float4 s2 = *(const float4*)(base + ((int)ix.z << 8));
            float4 s3 = *(const float4*)(base + ((int)ix.w << 8));
            float v0 = w.x*s0.x + w.y*s1.x + w.z*s2.x + w.w*s3.x;
            float v1 = w.x*s0.y + w.y*s1.y + w.z*s2.y + w.w*s3.y;
            float v2 = w.x*s0.z + w.y*s1.z + w.z*s2.z + w.w*s3.z;
            float v3 = w.x*s0.w + w.y*s1.w + w.z*s2.w + w.w*s3.w;
            __half h0 = __float2half_rn(v0);
            __half h1 = __float2half_rn(v1);
            __half h2 = __float2half_rn(v2);
            __half h3 = __float2half_rn(v3);
            __half l0 = __float2half_rn(v0 - __half2float(h0));
            __half l1 = __float2half_rn(v1 - __half2float(h1));
            __half l2 = __float2half_rn(v2 - __half2float(h2));
            __half l3 = __float2half_rn(v3 - __half2float(h3));
            uint32_t sw = swz128((uint32_t)(m * 128 + q * 8));
            __half2* ph = (__half2*)(smem + DS_A0 + sw);
            __half2* pl = (__half2*)(smem + DS_A0 + 16384 + sw);
            ph[0] = __half2(h0, h1);
            ph[1] = __half2(h2, h3);
            pl[0] = __half2(l0, l1);
            pl[1] = __half2(l2, l3);
        }
    }
    asm volatile("cp.async.wait_group 0;" ::: "memory");
    __syncthreads();

    uint32_t amask = (uint32_t)((lid & 7) * 16);
    uint32_t ahalf = (lid >> 4) ? 16u : 0u;
    uint32_t arowoff = (uint32_t)((mw * 32 + (lid & 15)) * 128);
    int brow_in = (lid & 7) + ((lid >> 4) << 3);
    uint32_t bhalf = ((lid >> 3) & 1) ? 16u : 0u;
    uint32_t browoff = (uint32_t)((nw * 64 + brow_in) * 128);

    float acc[2][8][4];
    #pragma unroll
    for (int i = 0; i < 2; ++i)
        #pragma unroll
        for (int j = 0; j < 8; ++j)
            #pragma unroll
            for (int q = 0; q < 4; ++q) acc[i][j][q] = 0.0f;

    for (int ch = 0; ch < 36; ++ch) {
        uint32_t aoff  = (ch & 1) ? DS_A1 : DS_A0;
        uint32_t boff  = (ch & 1) ? DS_B1 : DS_B0;
        uint32_t anoff = (ch & 1) ? DS_A0 : DS_A1;
        uint32_t bnoff = (ch & 1) ? DS_B0 : DS_B1;
        bool dob = (ch < 35);
        if (dob) issue_B(ch + 1, sb + bnoff, tid);
        int tn  = (ch + 1) >> 2;
        int c0n = ((ch + 1) & 3) * 64;

        #pragma unroll
        for (int kk = 0; kk < 4; ++kk) {
            // ---- issue gathers for next chunk's build iteration it=kk ----
            float4 gw; float4 s0, s1, s2, s3;
            int gm = 0, gq = 0;
            if (dob) {
                int e = kk * 512 + tid;
                gm = e >> 4; gq = e & 15;
                int ce = gm * 9 + tn;
                gw = cw4[ce];
                ushort4 gix = ci4[ce];
                const float* gbase = xtb + c0n + gq * 4;
                s0 = *(const float4*)(gbase + ((int)gix.x << 8));
                s1 = *(const float4*)(gbase + ((int)gix.y << 8));
                s2 = *(const float4*)(gbase + ((int)gix.z << 8));
                s3 = *(const float4*)(gbase + ((int)gix.w << 8));
            }

            // ---- MMA step kk: 2 products (a_hi + a_lo) x b ----
            uint32_t acol = ((uint32_t)(kk * 32) + ahalf) ^ amask;
            uint32_t a_hi[2][4], a_lo[2][4];
            #pragma unroll
            for (int i = 0; i < 2; ++i) {
                uint32_t aa = sb + aoff + arowoff + (uint32_t)(i * 2048) + acol;
                LDSM4(a_hi[i][0], a_hi[i][1], a_hi[i][2], a_hi[i][3], aa);
                LDSM4(a_lo[i][0], a_lo[i][1], a_lo[i][2], a_lo[i][3], aa + 16384);
            }
            uint32_t bcol = ((uint32_t)(kk * 32) + bhalf) ^ amask;
            #pragma unroll
            for (int j2 = 0; j2 < 4; ++j2) {
                uint32_t bb = sb + boff + browoff + (uint32_t)(j2 * 2048) + bcol;
                uint32_t bh[4];
                LDSM4(bh[0], bh[1], bh[2], bh[3], bb);
                #pragma unroll
                for (int i = 0; i < 2; ++i) {
                    MMAF16(acc[i][2*j2],   a_hi[i], bh[0], bh[1]);
                    MMAF16(acc[i][2*j2],   a_lo[i], bh[0], bh[1]);
                    MMAF16(acc[i][2*j2+1], a_hi[i], bh[2], bh[3]);
                    MMAF16(acc[i][2*j2+1], a_lo[i], bh[2], bh[3]);
                }
            }

            // ---- convert + store next chunk A (it=kk) ----
            if (dob) {
                float v0 = gw.x*s0.x + gw.y*s1.x + gw.z*s2.x + gw.w*s3.x;
                float v1 = gw.x*s0.y + gw.y*s1.y + gw.z*s2.y + gw.w*s3.y;
                float v2 = gw.x*s0.z + gw.y*s1.z + gw.z*s2.z + gw.w*s3.z;
                float v3 = gw.x*s0.w + gw.y*s1.w + gw.z*s2.w + gw.w*s3.w;
                __half h0 = __float2half_rn(v0);
                __half h1 = __float2half_rn(v1);
                __half h2 = __float2half_rn(v2);
                __half h3 = __float2half_rn(v3);
                __half l0 = __float2half_rn(v0 - __half2float(h0));
                __half l1 = __float2half_rn(v1 - __half2float(h1));
                __half l2 = __float2half_rn(v2 - __half2float(h2));
                __half l3 = __float2half_rn(v3 - __half2float(h3));
                uint32_t sw = swz128((uint32_t)(gm * 128 + gq * 8));
                __half2* ph = (__half2*)(smem + anoff + sw);
                __half2* pl = (__half2*)(smem + anoff + 16384 + sw);
                ph[0] = __half2(h0, h1);
                ph[1] = __half2(h2, h3);
                pl[0] = __half2(l0, l1);
                pl[1] = __half2(l2, l3);
            }
        }

        asm volatile("cp.async.wait_group 0;" ::: "memory");
        __syncthreads();
    }

    // epilogue: stage accumulators into smem tile [n][m] (stride 132),
    // then fully coalesced float4 stores to out [b][n][hw]
    float* etile = (float*)(smem + DS_TILE);
    int mrow = lid >> 2;
    int ncol = (lid & 3) * 2;
    #pragma unroll
    for (int i = 0; i < 2; ++i) {
        int ml = mw * 32 + i * 16 + mrow;
        #pragma unroll
        for (int j = 0; j < 8; ++j) {
            int n = nw * 64 + j * 8 + ncol;
            etile[n * 132 + ml]           = acc[i][j][0];
            etile[(n + 1) * 132 + ml]     = acc[i][j][1];
            etile[n * 132 + ml + 8]       = acc[i][j][2];
            etile[(n + 1) * 132 + ml + 8] = acc[i][j][3];
        }
    }

    // fused GroupNorm partial reduction
    #pragma unroll
    for (int j = 0; j < 8; ++j) {
        float s = 0.0f, sq = 0.0f;
        #pragma unroll
        for (int i = 0; i < 2; ++i)
            #pragma unroll
            for (int q = 0; q < 4; ++q) {
                float v = acc[i][j][q];
                s += v; sq += v * v;
            }
        #pragma unroll
        for (int off = 16; off > 0; off >>= 1) {
            s  += __shfl_xor_sync(0xFFFFFFFF, s,  off);
            sq += __shfl_xor_sync(0xFFFFFFFF, sq, off);
        }
        if (lid == 0) {
            int bg = b * GN_GROUPS + nw * 8 + j;
            atomicAdd(&g_part[bg * 2 + 0], s);
            atomicAdd(&g_part[bg * 2 + 1], sq);
        }
    }
    __syncthreads();

    #pragma unroll
    for (int it = 0; it < 16; ++it) {
        int e = it * 512 + tid;        // over 256n x 32 float4
        int n  = e >> 5;
        int mq = e & 31;
        float4 v = ((const float4*)(etile + n * 132))[mq];
        *(float4*)(out + (((size_t)(b * COUT + n)) << 12) + hw0 + mq * 4) = v;
    }
}

// ---------------- GN finalize: partials -> (mean, rstd) ----------------------
__global__ void gn_finalize() {
    int bg = threadIdx.x;
    if (bg >= NB * GN_GROUPS) return;
    float n = (float)(CPG * HWSZ);
    float mean = g_part[bg * 2 + 0] / n;
    float var  = g_part[bg * 2 + 1] / n - mean * mean;
    g_stats[bg * 2 + 0] = mean;
    g_stats[bg * 2 + 1] = rsqrtf(var + EPS);
}

// ---------------- GroupNorm apply + ReLU (float4) -----------------------------
__global__ void gn_apply(float* __restrict__ out,
                         const float* __restrict__ gamma,
                         const float* __restrict__ beta) {
    int i = blockIdx.x * 256 + threadIdx.x;       // float4 over 4*256*4096/4
    int c = (i >> 10) & 255;
    int b = i >> 18;
    int bg = b * GN_GROUPS + (c >> 3);
    float mean = g_stats[bg * 2 + 0];
    float rstd = g_stats[bg * 2 + 1];
    float gmul = rstd * gamma[c];
    float add  = beta[c] - mean * gmul;
    float4 v = ((const float4*)out)[i];
    v.x = fmaxf(v.x * gmul + add, 0.0f);
    v.y = fmaxf(v.y * gmul + add, 0.0f);
    v.z = fmaxf(v.z * gmul + add, 0.0f);
    v.w = fmaxf(v.w * gmul + add, 0.0f);
    ((float4*)out)[i] = v;
}

// ---------------- launch ------------------------------------------------------
extern "C" void kernel_launch(void* const* d_in, const int* in_sizes, int n_in,
                              void* d_out, int out_size) {
    const float* x   = (const float*)d_in[0];
    const float* ow  = (const float*)d_in[1];
    const float* ob  = (const float*)d_in[2];
    const float* dw  = (const float*)d_in[3];
    const float* gam = (const float*)d_in[4];
    const float* bet = (const float*)d_in[5];
    float* out = (float*)d_out;

    cudaFuncSetAttribute(deform_gemm, cudaFuncAttributeMaxDynamicSharedMemorySize, DS_TOT);
    cudaFuncSetAttribute(offset_conv_mma, cudaFuncAttributeMaxDynamicSharedMemorySize, OS_TOT);

    prep_wbf<<<(KTAP * 4 * 16384 + 255) / 256, 256>>>(dw);
    prep_owbf<<<(KTAP * 4 * 2048 + 255) / 256, 256>>>(ow);
    transpose_x<<<dim3(HWSZ / 32, CIN / 32, NB), dim3(32, 8)>>>(x);
    offset_conv_mma<<<512, 256, OS_TOT>>>();
    combine_offs<<<(NB * OFFC * HWSZ / 4 + 255) / 256, 256>>>(ob);
    deform_gemm<<<128, 512, DS_TOT>>>(out);
    gn_finalize<<<1, 128>>>();
    gn_apply<<<(NB * COUT * HWSZ / 4 + 255) / 256, 256>>>(out, gam, bet);
}

// round 15
// speedup vs baseline: 3.7081x; 1.0290x over previous
#include <cuda_runtime.h>
#include <cuda_fp16.h>
#include <cstdint>

#define NB   4
#define CIN  256
#define COUT 256
#define HH   64
#define WW   64
#define HWSZ 4096
#define KTAP 9
#define OFFC 18
#define GN_GROUPS 32
#define CPG  8
#define EPS  1e-5f

// ---------------- scratch ----------------
__device__ float g_xt[NB * HWSZ * CIN];              // x as [b][hw][c]
__device__ float g_offs[NB * OFFC * HWSZ];           // offsets [b][ch][hw]
__device__ float g_offp[2 * NB * OFFC * HWSZ];       // split-K partials
__device__ __half g_wbf[KTAP * 4 * 16384];           // deform W fp16, SW128 tiles [tap*4+cc][256n x 64k]
__device__ __half g_owbf[KTAP * 4 * 2048];           // offset W fp16, SW128 tiles [tap*4+cc][32n x 64k]
__device__ float g_part[NB * GN_GROUPS * 2];         // GN partial (sum, sumsq)
__device__ float g_stats[NB * GN_GROUPS * 2];        // (mean, rstd)

__device__ __forceinline__ uint32_t smem_u32(const void* p) {
    uint32_t a;
    asm("{ .reg .u64 t; cvta.to.shared.u64 t, %1; cvt.u32.u64 %0, t; }" : "=r"(a) : "l"(p));
    return a;
}
__device__ __forceinline__ uint32_t swz128(uint32_t b) { return b ^ ((b >> 3) & 0x70); }

#define LDSM4(r0,r1,r2,r3,addr) \
    asm volatile("ldmatrix.sync.aligned.m8n8.x4.shared.b16 {%0,%1,%2,%3}, [%4];" \
        : "=r"(r0),"=r"(r1),"=r"(r2),"=r"(r3) : "r"(addr))

#define MMAF16(d, a, b0, b1) \
    asm volatile("mma.sync.aligned.m16n8k16.row.col.f32.f16.f16.f32 " \
        "{%0,%1,%2,%3}, {%4,%5,%6,%7}, {%8,%9}, {%0,%1,%2,%3};" \
        : "+f"((d)[0]),"+f"((d)[1]),"+f"((d)[2]),"+f"((d)[3]) \
        : "r"((a)[0]),"r"((a)[1]),"r"((a)[2]),"r"((a)[3]),"r"(b0),"r"(b1))

#define CPASYNC16(dst, src) \
    asm volatile("cp.async.cg.shared.global [%0], [%1], 16;" :: "r"(dst), "l"(src))

// ---------------- prep: deform weight -> fp16, SW128-swizzled ----------------
__global__ void prep_wbf(const float* __restrict__ dw) {
    int i = blockIdx.x * 256 + threadIdx.x;     // over 9*4*16384
    if (i >= KTAP * 4 * 16384) return;
    int t  = i >> 16;
    int r  = i & 65535;
    int cc = r >> 14;
    int r2 = r & 16383;
    int n  = r2 >> 6;
    int k  = r2 & 63;
    float v = dw[n * (CIN * KTAP) + (cc * 64 + k) * KTAP + t];
    uint32_t sw = swz128((uint32_t)(n * 128 + k * 2)) >> 1;
    g_wbf[(t * 4 + cc) * 16384 + sw] = __float2half_rn(v);
}

// ---------------- prep: offset weight -> fp16 SW128 [32n x 64k] tiles --------
__global__ void prep_owbf(const float* __restrict__ ow) {
    int i = blockIdx.x * 256 + threadIdx.x;     // over 36*2048
    if (blockIdx.x == 0 && threadIdx.x < NB * GN_GROUPS * 2)
        g_part[threadIdx.x] = 0.0f;             // zero GN partials
    if (i >= KTAP * 4 * 2048) return;
    int ch = i >> 11;
    int r  = i & 2047;
    int n  = r >> 6;
    int k  = r & 63;
    int t  = ch >> 2;
    int cc = ch & 3;
    float v = (n < OFFC) ? ow[n * (CIN * KTAP) + (cc * 64 + k) * KTAP + t] : 0.0f;
    uint32_t sw = swz128((uint32_t)(n * 128 + k * 2)) >> 1;
    g_owbf[ch * 2048 + sw] = __float2half_rn(v);
}

// ---------------- transpose x [b][c][hw] -> [b][hw][c] -----------------------
__global__ void transpose_x(const float* __restrict__ x) {
    __shared__ float t[32][33];
    int b   = blockIdx.z;
    int hw0 = blockIdx.x * 32;
    int c0  = blockIdx.y * 32;
    int tx  = threadIdx.x, ty = threadIdx.y;
    #pragma unroll
    for (int i = ty; i < 32; i += 8)
        t[i][tx] = x[((b * CIN + c0 + i) << 12) + hw0 + tx];
    __syncthreads();
    #pragma unroll
    for (int i = ty; i < 32; i += 8)
        g_xt[(size_t)((b << 12) + hw0 + i) * CIN + c0 + tx] = t[tx][i];
}

// ---------------- offset conv v5: fp16 single-product, split-K(2) ------------
#define OS_A0  0                      // 8KB fp16 A
#define OS_A1  8192
#define OS_B0  16384                  // 4KB fp16 B
#define OS_B1  20480
#define OS_TOT 24576

__device__ __forceinline__ void issue_OB(int ch, uint32_t dst, int tid) {
    if (tid < 256) {
        const char* src = (const char*)g_owbf + (size_t)ch * 4096;
        int i = tid * 16;
        CPASYNC16(dst + i, src + i);
    }
    asm volatile("cp.async.commit_group;");
}

__device__ __forceinline__ void build_OA(int ch, char* osm, uint32_t aoff,
                                         const float* xtb, int hh, int tid) {
    int t  = ch >> 2;
    int c0 = (ch & 3) * 64;
    int dyt = t / 3 - 1, dxt = t % 3 - 1;
    int yy = hh + dyt;
    bool rowok = ((unsigned)yy < 64u);
    #pragma unroll
    for (int it = 0; it < 4; ++it) {
        int e = it * 256 + tid;       // 0..1023 = 64m x 16q
        int m = e >> 4, q = e & 15;
        int xx = m + dxt;
        float4 v = make_float4(0.f, 0.f, 0.f, 0.f);
        if (rowok && (unsigned)xx < 64u)
            v = *(const float4*)(xtb + (((yy << 6) + xx) << 8) + c0 + q * 4);
        uint32_t sw = swz128((uint32_t)(m * 128 + q * 8));
        __half2* ph = (__half2*)(osm + aoff + sw);
        ph[0] = __half2(__float2half_rn(v.x), __float2half_rn(v.y));
        ph[1] = __half2(__float2half_rn(v.z), __float2half_rn(v.w));
    }
}

__global__ __launch_bounds__(256) void offset_conv_mma() {
    extern __shared__ char osm[];
    uint32_t sb = smem_u32(osm);
    int tid = threadIdx.x, wid = tid >> 5, lid = tid & 31;
    int mw = wid & 3, nw = wid >> 2;
    int blk = blockIdx.x;             // 0..511 = 2half x 4b x 64hh
    int half = blk >> 8;
    int b    = (blk >> 6) & 3;
    int hh   = blk & 63;
    int hw0  = hh << 6;
    int ch0  = half * 18;
    const float* xtb = g_xt + (size_t)b * HWSZ * CIN;

    issue_OB(ch0, sb + OS_B0, tid);
    build_OA(ch0, osm, OS_A0, xtb, hh, tid);
    asm volatile("cp.async.wait_group 0;" ::: "memory");
    __syncthreads();

    uint32_t amask = (uint32_t)((lid & 7) * 16);
    uint32_t ahalf = (lid >> 4) ? 16u : 0u;
    uint32_t arowoff = (uint32_t)((mw * 16 + (lid & 15)) * 128);
    int brow_in = (lid & 7) + ((lid >> 4) << 3);
    uint32_t bhalf = ((lid >> 3) & 1) ? 16u : 0u;
    uint32_t browoff = (uint32_t)((nw * 16 + brow_in) * 128);

    float acc[2][4];
    #pragma unroll
    for (int j = 0; j < 2; ++j)
        #pragma unroll
        for (int q = 0; q < 4; ++q) acc[j][q] = 0.0f;

    for (int lch = 0; lch < 18; ++lch) {
        uint32_t aoff  = (lch & 1) ? OS_A1 : OS_A0;
        uint32_t boff  = (lch & 1) ? OS_B1 : OS_B0;
        uint32_t anoff = (lch & 1) ? OS_A0 : OS_A1;
        uint32_t bnoff = (lch & 1) ? OS_B0 : OS_B1;
        if (lch < 17) issue_OB(ch0 + lch + 1, sb + bnoff, tid);

        #pragma unroll
        for (int kk = 0; kk < 4; ++kk) {
            uint32_t acol = ((uint32_t)(kk * 32) + ahalf) ^ amask;
            uint32_t aa = sb + aoff + arowoff + acol;
            uint32_t av[4];
            LDSM4(av[0], av[1], av[2], av[3], aa);
            uint32_t bcol = ((uint32_t)(kk * 32) + bhalf) ^ amask;
            uint32_t bb = sb + boff + browoff + bcol;
            uint32_t bh[4];
            LDSM4(bh[0], bh[1], bh[2], bh[3], bb);
            MMAF16(acc[0], av, bh[0], bh[1]);
            MMAF16(acc[1], av, bh[2], bh[3]);
        }

        if (lch < 17) build_OA(ch0 + lch + 1, osm, anoff, xtb, hh, tid);
        asm volatile("cp.async.wait_group 0;" ::: "memory");
        __syncthreads();
    }

    float* dst = g_offp + (size_t)half * (NB * OFFC * HWSZ);
    int mrow = lid >> 2, ncol = (lid & 3) * 2;
    int m = hw0 + mw * 16 + mrow;
    #pragma unroll
    for (int j2 = 0; j2 < 2; ++j2) {
        int n = nw * 16 + j2 * 8 + ncol;
        if (n < OFFC) {
            dst[(b * OFFC + n) * HWSZ + m]     = acc[j2][0];
            dst[(b * OFFC + n) * HWSZ + m + 8] = acc[j2][2];
        }
        if (n + 1 < OFFC) {
            dst[(b * OFFC + n + 1) * HWSZ + m]     = acc[j2][1];
            dst[(b * OFFC + n + 1) * HWSZ + m + 8] = acc[j2][3];
        }
    }
}

// ---------------- combine split-K halves + bias ------------------------------
__global__ void combine_offs(const float* __restrict__ bias) {
    int i = blockIdx.x * 256 + threadIdx.x;     // float4 over NB*OFFC*HWSZ/4
    if (i >= NB * OFFC * HWSZ / 4) return;
    int o = (i >> 10) % OFFC;
    float bv = bias[o];
    float4 a = ((const float4*)g_offp)[i];
    float4 c = ((const float4*)(g_offp + NB * OFFC * HWSZ))[i];
    float4 r = make_float4(a.x + c.x + bv, a.y + c.y + bv, a.z + c.z + bv, a.w + c.w + bv);
    ((float4*)g_offs)[i] = r;
}

// ---------------- deformable conv: fp16 2-product, 2 CTA/SM ------------------
// 256 CTAs x 256 thr, CTA tile 64m x 256n, 8 warps 2m x 4n (warp 32m x 64n).
// A split fp16 hi/lo (exact), B fp16. Interleaved build + double buffers.
#define DS_CW   0                          // float4 cwgt[576]  (9216 B)
#define DS_CI   9216                       // ushort4 cidx[576] (4608 B)
#define DS_A0   13824                      // 16KB: hi 8K | lo 8K
#define DS_A1   (DS_A0 + 16384)
#define DS_B0   (DS_A1 + 16384)            // 32KB fp16 B
#define DS_B1   (DS_B0 + 32768)
#define DS_TOT  (DS_B1 + 32768)            // 112128 B -> 2 CTAs/SM
#define DS_TILE DS_A0                      // epilogue staging 256n x 68 f = 69632 B

__device__ __forceinline__ void issue_B(int ch, uint32_t dst, int tid) {
    const char* src = (const char*)g_wbf + (size_t)ch * 32768;
    #pragma unroll
    for (int r = 0; r < 8; ++r) {
        int i = (tid + 256 * r) * 16;
        CPASYNC16(dst + i, src + i);
    }
    asm volatile("cp.async.commit_group;");
}

__global__ __launch_bounds__(256, 2) void deform_gemm(float* __restrict__ out) {
    extern __shared__ char smem[];
    uint32_t sb = smem_u32(smem);
    int tid = threadIdx.x, wid = tid >> 5, lid = tid & 31;
    int mw = wid & 1, nw = wid >> 1;
    int blk = blockIdx.x;          // 0..255 = 4b x 64 tiles
    int b    = blk >> 6;
    int hw0  = (blk & 63) << 6;
    const float* xtb = g_xt + (size_t)b * HWSZ * CIN;

    issue_B(0, sb + DS_B0, tid);

    float4*  cw4 = (float4*)(smem + DS_CW);
    ushort4* ci4 = (ushort4*)(smem + DS_CI);
    for (int e = tid; e < 64 * KTAP; e += 256) {
        int ml = e / 9, k = e - ml * 9;
        int hw = hw0 + ml;
        int hh = hw >> 6, wp = hw & 63;
        float dy = g_offs[(b * OFFC + 2 * k) * HWSZ + hw];
        float dx = g_offs[(b * OFFC + 2 * k + 1) * HWSZ + hw];
        int ky = k / 3, kx = k - ky * 3;
        float py = (float)(hh - 1 + ky) + dy;
        float px = (float)(wp - 1 + kx) + dx;
        float y0f = floorf(py), x0f = floorf(px);
        float ty = py - y0f, tx = px - x0f;
        int y0 = (int)y0f, x0 = (int)x0f;
        float wv[4]; unsigned short iv[4];
        #pragma unroll
        for (int j = 0; j < 4; ++j) {
            int yj = y0 + (j >> 1);
            int xj = x0 + (j & 1);
            float wj = ((j >> 1) ? ty : 1.0f - ty) * ((j & 1) ? tx : 1.0f - tx);
            bool ok = (yj >= 0) && (yj < HH) && (xj >= 0) && (xj < WW);
            wv[j] = ok ? wj : 0.0f;
            iv[j] = ok ? (unsigned short)(yj * WW + xj) : 0;
        }
        cw4[e] = make_float4(wv[0], wv[1], wv[2], wv[3]);
        ci4[e] = make_ushort4(iv[0], iv[1], iv[2], iv[3]);
    }
    __syncthreads();

    // build chunk 0 A tile (un-pipelined prologue)
    {
        #pragma unroll
        for (int it = 0; it < 4; ++it) {
            int e = it * 256 + tid;          // 0..1023 = 64m x 16q
            int m = e >> 4, q = e & 15;
            int ce = m * 9;                  // tap 0, chunk 0
            float4  w  = cw4[ce];
            ushort4 ix = ci4[ce];
            const float* base = xtb + q * 4;
            float4 s0 = *(const float4*)(base + ((int)ix.x << 8));
            float4 s1 = *(const float4*)(base + ((int)ix.y << 8));
            float4 s2 = *(const float4*)(base + ((int)ix.z << 8));
            float4 s3 = *(const float4*)(base + ((int)ix.w << 8));
            float v0 = w.x*s0.x + w.y*s1.x + w.z*s2.x + w.w*s3.x;
            float v1 = w.x*s0.y + w.y*s1.y + w.z*s2.y + w.w*s3.y;
            float v2 = w.x*s0.z + w.y*s1.z + w.z*s2.z + w.w*s3.z;
            float v3 = w.x*s0.w + w.y*s1.w + w.z*s2.w + w.w*s3.w;
            __half h0 = __float2half_rn(v0);
            __half h1 = __float2half_rn(v1);
            __half h2 = __float2half_rn(v2);
            __half h3 = __float2half_rn(v3);
            __half l0 = __float2half_rn(v0 - __half2float(h0));
            __half l1 = __float2half_rn(v1 - __half2float(h1));
            __half l2 = __float2half_rn(v2 - __half2float(h2));
            __half l3 = __float2half_rn(v3 - __half2float(h3));
            uint32_t sw = swz128((uint32_t)(m * 128 + q * 8));
            __half2* ph = (__half2*)(smem + DS_A0 + sw);
            __half2* pl = (__half2*)(smem + DS_A0 + 8192 + sw);
            ph[0] = __half2(h0, h1);
            ph[1] = __half2(h2, h3);
            pl[0] = __half2(l0, l1);
            pl[1] = __half2(l2, l3);
        }
    }
    asm volatile("cp.async.wait_group 0;" ::: "memory");
    __syncthreads();

    uint32_t amask = (uint32_t)((lid & 7) * 16);
    uint32_t ahalf = (lid >> 4) ? 16u : 0u;
    uint32_t arowoff = (uint32_t)((mw * 32 + (lid & 15)) * 128);
    int brow_in = (lid & 7) + ((lid >> 4) << 3);
    uint32_t bhalf = ((lid >> 3) & 1) ? 16u : 0u;
    uint32_t browoff = (uint32_t)((nw * 64 + brow_in) * 128);

    float acc[2][8][4];
    #pragma unroll
    for (int i = 0; i < 2; ++i)
        #pragma unroll
        for (int j = 0; j < 8; ++j)
            #pragma unroll
            for (int q = 0; q < 4; ++q) acc[i][j][q] = 0.0f;

    for (int ch = 0; ch < 36; ++ch) {
        uint32_t aoff  = (ch & 1) ? DS_A1 : DS_A0;
        uint32_t boff  = (ch & 1) ? DS_B1 : DS_B0;
        uint32_t anoff = (ch & 1) ? DS_A0 : DS_A1;
        uint32_t bnoff = (ch & 1) ? DS_B0 : DS_B1;
        bool dob = (ch < 35);
        if (dob) issue_B(ch + 1, sb + bnoff, tid);
        int tn  = (ch + 1) >> 2;
        int c0n = ((ch + 1) & 3) * 64;

        #pragma unroll
        for (int kk = 0; kk < 4; ++kk) {
            // ---- issue gathers for next chunk's build iteration it=kk ----
            float4 gw; float4 s0, s1, s2, s3;
            int gm = 0, gq = 0;
            if (dob) {
                int e = kk * 256 + tid;       // 64m x 16q over 4 kk
                gm = e >> 4; gq = e & 15;
                int ce = gm * 9 + tn;
                gw = cw4[ce];
                ushort4 gix = ci4[ce];
                const float* gbase = xtb + c0n + gq * 4;
                s0 = *(const float4*)(gbase + ((int)gix.x << 8));
                s1 = *(const float4*)(gbase + ((int)gix.y << 8));
                s2 = *(const float4*)(gbase + ((int)gix.z << 8));
                s3 = *(const float4*)(gbase + ((int)gix.w << 8));
            }

            // ---- MMA step kk: 2 products (a_hi + a_lo) x b ----
            uint32_t acol = ((uint32_t)(kk * 32) + ahalf) ^ amask;
            uint32_t a_hi[2][4], a_lo[2][4];
            #pragma unroll
            for (int i = 0; i < 2; ++i) {
                uint32_t aa = sb + aoff + arowoff + (uint32_t)(i * 2048) + acol;
                LDSM4(a_hi[i][0], a_hi[i][1], a_hi[i][2], a_hi[i][3], aa);
                LDSM4(a_lo[i][0], a_lo[i][1], a_lo[i][2], a_lo[i][3], aa + 8192);
            }
            uint32_t bcol = ((uint32_t)(kk * 32) + bhalf) ^ amask;
            #pragma unroll
            for (int j2 = 0; j2 < 4; ++j2) {
                uint32_t bb = sb + boff + browoff + (uint32_t)(j2 * 2048) + bcol;
                uint32_t bh[4];
                LDSM4(bh[0], bh[1], bh[2], bh[3], bb);
                #pragma unroll
                for (int i = 0; i < 2; ++i) {
                    MMAF16(acc[i][2*j2],   a_hi[i], bh[0], bh[1]);
                    MMAF16(acc[i][2*j2],   a_lo[i], bh[0], bh[1]);
                    MMAF16(acc[i][2*j2+1], a_hi[i], bh[2], bh[3]);
                    MMAF16(acc[i][2*j2+1], a_lo[i], bh[2], bh[3]);
                }
            }

            // ---- convert + store next chunk A (it=kk) ----
            if (dob) {
                float v0 = gw.x*s0.x + gw.y*s1.x + gw.z*s2.x + gw.w*s3.x;
                float v1 = gw.x*s0.y + gw.y*s1.y + gw.z*s2.y + gw.w*s3.y;
                float v2 = gw.x*s0.z + gw.y*s1.z + gw.z*s2.z + gw.w*s3.z;
                float v3 = gw.x*s0.w + gw.y*s1.w + gw.z*s2.w + gw.w*s3.w;
                __half h0 = __float2half_rn(v0);
                __half h1 = __float2half_rn(v1);
                __half h2 = __float2half_rn(v2);
                __half h3 = __float2half_rn(v3);
                __half l0 = __float2half_rn(v0 - __half2float(h0));
                __half l1 = __float2half_rn(v1 - __half2float(h1));
                __half l2 = __float2half_rn(v2 - __half2float(h2));
                __half l3 = __float2half_rn(v3 - __half2float(h3));
                uint32_t sw = swz128((uint32_t)(gm * 128 + gq * 8));
                __half2* ph = (__half2*)(smem + anoff + sw);
                __half2* pl = (__half2*)(smem + anoff + 8192 + sw);
                ph[0] = __half2(h0, h1);
                ph[1] = __half2(h2, h3);
                pl[0] = __half2(l0, l1);
                pl[1] = __half2(l2, l3);
            }
        }

        asm volatile("cp.async.wait_group 0;" ::: "memory");
        __syncthreads();
    }

    // epilogue: stage accumulators into smem tile [n][m] (stride 68),
    // then fully coalesced float4 stores to out [b][n][hw]
    float* etile = (float*)(smem + DS_TILE);
    int mrow = lid >> 2;
    int ncol = (lid & 3) * 2;
    #pragma unroll
    for (int i = 0; i < 2; ++i) {
        int ml = mw * 32 + i * 16 + mrow;
        #pragma unroll
        for (int j = 0; j < 8; ++j) {
            int n = nw * 64 + j * 8 + ncol;
            etile[n * 68 + ml]           = acc[i][j][0];
            etile[(n + 1) * 68 + ml]     = acc[i][j][1];
            etile[n * 68 + ml + 8]       = acc[i][j][2];
            etile[(n + 1) * 68 + ml + 8] = acc[i][j][3];
        }
    }

    // fused GroupNorm partial reduction
    #pragma unroll
    for (int j = 0; j < 8; ++j) {
        float s = 0.0f, sq = 0.0f;
        #pragma unroll
        for (int i = 0; i < 2; ++i)
            #pragma unroll
            for (int q = 0; q < 4; ++q) {
                float v = acc[i][j][q];
                s += v; sq += v * v;
            }
        #pragma unroll
        for (int off = 16; off > 0; off >>= 1) {
            s  += __shfl_xor_sync(0xFFFFFFFF, s,  off);
            sq += __shfl_xor_sync(0xFFFFFFFF, sq, off);
        }
        if (lid == 0) {
            int bg = b * GN_GROUPS + nw * 8 + j;
            atomicAdd(&g_part[bg * 2 + 0], s);
            atomicAdd(&g_part[bg * 2 + 1], sq);
        }
    }
    __syncthreads();

    #pragma unroll
    for (int it = 0; it < 16; ++it) {
        int e = it * 256 + tid;        // over 256n x 16 float4
        int n  = e >> 4;
        int mq = e & 15;
        float4 v = ((const float4*)(etile + n * 68))[mq];
        *(float4*)(out + (((size_t)(b * COUT + n)) << 12) + hw0 + mq * 4) = v;
    }
}

// ---------------- GN finalize: partials -> (mean, rstd) ----------------------
__global__ void gn_finalize() {
    int bg = threadIdx.x;
    if (bg >= NB * GN_GROUPS) return;
    float n = (float)(CPG * HWSZ);
    float mean = g_part[bg * 2 + 0] / n;
    float var  = g_part[bg * 2 + 1] / n - mean * mean;
    g_stats[bg * 2 + 0] = mean;
    g_stats[bg * 2 + 1] = rsqrtf(var + EPS);
}

// ---------------- GroupNorm apply + ReLU (float4) -----------------------------
__global__ void gn_apply(float* __restrict__ out,
                         const float* __restrict__ gamma,
                         const float* __restrict__ beta) {
    int i = blockIdx.x * 256 + threadIdx.x;       // float4 over 4*256*4096/4
    int c = (i >> 10) & 255;
    int b = i >> 18;
    int bg = b * GN_GROUPS + (c >> 3);
    float mean = g_stats[bg * 2 + 0];
    float rstd = g_stats[bg * 2 + 1];
    float gmul = rstd * gamma[c];
    float add  = beta[c] - mean * gmul;
    float4 v = ((const float4*)out)[i];
    v.x = fmaxf(v.x * gmul + add, 0.0f);
    v.y = fmaxf(v.y * gmul + add, 0.0f);
    v.z = fmaxf(v.z * gmul + add, 0.0f);
    v.w = fmaxf(v.w * gmul + add, 0.0f);
    ((float4*)out)[i] = v;
}

// ---------------- launch ------------------------------------------------------
extern "C" void kernel_launch(void* const* d_in, const int* in_sizes, int n_in,
                              void* d_out, int out_size) {
    const float* x   = (const float*)d_in[0];
    const float* ow  = (const float*)d_in[1];
    const float* ob  = (const float*)d_in[2];
    const float* dw  = (const float*)d_in[3];
    const float* gam = (const float*)d_in[4];
    const float* bet = (const float*)d_in[5];
    float* out = (float*)d_out;

    cudaFuncSetAttribute(deform_gemm, cudaFuncAttributeMaxDynamicSharedMemorySize, DS_TOT);
    cudaFuncSetAttribute(offset_conv_mma, cudaFuncAttributeMaxDynamicSharedMemorySize, OS_TOT);

    prep_wbf<<<(KTAP * 4 * 16384 + 255) / 256, 256>>>(dw);
    prep_owbf<<<(KTAP * 4 * 2048 + 255) / 256, 256>>>(ow);
    transpose_x<<<dim3(HWSZ / 32, CIN / 32, NB), dim3(32, 8)>>>(x);
    offset_conv_mma<<<512, 256, OS_TOT>>>();
    combine_offs<<<(NB * OFFC * HWSZ / 4 + 255) / 256, 256>>>(ob);
    deform_gemm<<<256, 256, DS_TOT>>>(out);
    gn_finalize<<<1, 128>>>();
    gn_apply<<<(NB * COUT * HWSZ / 4 + 255) / 256, 256>>>(out, gam, bet);
}

// round 16
// speedup vs baseline: 3.8876x; 1.0484x over previous
#include <cuda_runtime.h>
#include <cuda_fp16.h>
#include <cstdint>

#define NB   4
#define CIN  256
#define COUT 256
#define HH   64
#define WW   64
#define HWSZ 4096
#define KTAP 9
#define OFFC 18
#define GN_GROUPS 32
#define CPG  8
#define EPS  1e-5f

// ---------------- scratch ----------------
__device__ __half g_xh[NB * HWSZ * CIN];             // x as [b][hw][c], fp16 (8MB)
__device__ float g_offs[NB * OFFC * HWSZ];           // offsets [b][ch][hw]
__device__ float g_offp[2 * NB * OFFC * HWSZ];       // split-K partials
__device__ __half g_wbf[KTAP * 4 * 16384];           // deform W fp16, SW128 tiles [tap*4+cc][256n x 64k]
__device__ __half g_owbf[KTAP * 4 * 2048];           // offset W fp16, SW128 tiles [tap*4+cc][32n x 64k]
__device__ float g_part[NB * GN_GROUPS * 2];         // GN partial (sum, sumsq)
__device__ float g_stats[NB * GN_GROUPS * 2];        // (mean, rstd)

__device__ __forceinline__ uint32_t smem_u32(const void* p) {
    uint32_t a;
    asm("{ .reg .u64 t; cvta.to.shared.u64 t, %1; cvt.u32.u64 %0, t; }" : "=r"(a) : "l"(p));
    return a;
}
__device__ __forceinline__ uint32_t swz128(uint32_t b) { return b ^ ((b >> 3) & 0x70); }

#define LDSM4(r0,r1,r2,r3,addr) \
    asm volatile("ldmatrix.sync.aligned.m8n8.x4.shared.b16 {%0,%1,%2,%3}, [%4];" \
        : "=r"(r0),"=r"(r1),"=r"(r2),"=r"(r3) : "r"(addr))

#define MMAF16(d, a, b0, b1) \
    asm volatile("mma.sync.aligned.m16n8k16.row.col.f32.f16.f16.f32 " \
        "{%0,%1,%2,%3}, {%4,%5,%6,%7}, {%8,%9}, {%0,%1,%2,%3};" \
        : "+f"((d)[0]),"+f"((d)[1]),"+f"((d)[2]),"+f"((d)[3]) \
        : "r"((a)[0]),"r"((a)[1]),"r"((a)[2]),"r"((a)[3]),"r"(b0),"r"(b1))

#define CPASYNC16(dst, src) \
    asm volatile("cp.async.cg.shared.global [%0], [%1], 16;" :: "r"(dst), "l"(src))

// ---------------- prep: deform weight -> fp16, SW128-swizzled ----------------
__global__ void prep_wbf(const float* __restrict__ dw) {
    int i = blockIdx.x * 256 + threadIdx.x;     // over 9*4*16384
    if (i >= KTAP * 4 * 16384) return;
    int t  = i >> 16;
    int r  = i & 65535;
    int cc = r >> 14;
    int r2 = r & 16383;
    int n  = r2 >> 6;
    int k  = r2 & 63;
    float v = dw[n * (CIN * KTAP) + (cc * 64 + k) * KTAP + t];
    uint32_t sw = swz128((uint32_t)(n * 128 + k * 2)) >> 1;
    g_wbf[(t * 4 + cc) * 16384 + sw] = __float2half_rn(v);
}

// ---------------- prep: offset weight -> fp16 SW128 [32n x 64k] tiles --------
__global__ void prep_owbf(const float* __restrict__ ow) {
    int i = blockIdx.x * 256 + threadIdx.x;     // over 36*2048
    if (blockIdx.x == 0 && threadIdx.x < NB * GN_GROUPS * 2)
        g_part[threadIdx.x] = 0.0f;             // zero GN partials
    if (i >= KTAP * 4 * 2048) return;
    int ch = i >> 11;
    int r  = i & 2047;
    int n  = r >> 6;
    int k  = r & 63;
    int t  = ch >> 2;
    int cc = ch & 3;
    float v = (n < OFFC) ? ow[n * (CIN * KTAP) + (cc * 64 + k) * KTAP + t] : 0.0f;
    uint32_t sw = swz128((uint32_t)(n * 128 + k * 2)) >> 1;
    g_owbf[ch * 2048 + sw] = __float2half_rn(v);
}

// ---------------- transpose x [b][c][hw] -> [b][hw][c] fp16 ------------------
__global__ void transpose_x(const float* __restrict__ x) {
    __shared__ float t[32][33];
    int b   = blockIdx.z;
    int hw0 = blockIdx.x * 32;
    int c0  = blockIdx.y * 32;
    int tx  = threadIdx.x, ty = threadIdx.y;
    #pragma unroll
    for (int i = ty; i < 32; i += 8)
        t[i][tx] = x[((b * CIN + c0 + i) << 12) + hw0 + tx];
    __syncthreads();
    #pragma unroll
    for (int i = ty; i < 32; i += 8)
        g_xh[(size_t)((b << 12) + hw0 + i) * CIN + c0 + tx] = __float2half_rn(t[tx][i]);
}

// ---------------- offset conv v6: fp16 copy A-build, split-K(2) --------------
#define OS_A0  0                      // 8KB fp16 A
#define OS_A1  8192
#define OS_B0  16384                  // 4KB fp16 B
#define OS_B1  20480
#define OS_TOT 24576

__device__ __forceinline__ void issue_OB(int ch, uint32_t dst, int tid) {
    if (tid < 256) {
        const char* src = (const char*)g_owbf + (size_t)ch * 4096;
        int i = tid * 16;
        CPASYNC16(dst + i, src + i);
    }
    asm volatile("cp.async.commit_group;");
}

__device__ __forceinline__ void build_OA(int ch, char* osm, uint32_t aoff,
                                         const __half* xhb, int hh, int tid) {
    int t  = ch >> 2;
    int c0 = (ch & 3) * 64;
    int dyt = t / 3 - 1, dxt = t % 3 - 1;
    int yy = hh + dyt;
    bool rowok = ((unsigned)yy < 64u);
    #pragma unroll
    for (int it = 0; it < 4; ++it) {
        int e = it * 256 + tid;       // 0..1023 = 64m x 16q
        int m = e >> 4, q = e & 15;
        int xx = m + dxt;
        uint2 v = make_uint2(0u, 0u);
        if (rowok && (unsigned)xx < 64u)
            v = *(const uint2*)(xhb + (((yy << 6) + xx) << 8) + c0 + q * 4);
        uint32_t sw = swz128((uint32_t)(m * 128 + q * 8));
        *(uint2*)(osm + aoff + sw) = v;     // direct fp16 copy, no conversion
    }
}

__global__ __launch_bounds__(256) void offset_conv_mma() {
    extern __shared__ char osm[];
    uint32_t sb = smem_u32(osm);
    int tid = threadIdx.x, wid = tid >> 5, lid = tid & 31;
    int mw = wid & 3, nw = wid >> 2;
    int blk = blockIdx.x;             // 0..511 = 2half x 4b x 64hh
    int half = blk >> 8;
    int b    = (blk >> 6) & 3;
    int hh   = blk & 63;
    int hw0  = hh << 6;
    int ch0  = half * 18;
    const __half* xhb = g_xh + (size_t)b * HWSZ * CIN;

    issue_OB(ch0, sb + OS_B0, tid);
    build_OA(ch0, osm, OS_A0, xhb, hh, tid);
    asm volatile("cp.async.wait_group 0;" ::: "memory");
    __syncthreads();

    uint32_t amask = (uint32_t)((lid & 7) * 16);
    uint32_t ahalf = (lid >> 4) ? 16u : 0u;
    uint32_t arowoff = (uint32_t)((mw * 16 + (lid & 15)) * 128);
    int brow_in = (lid & 7) + ((lid >> 4) << 3);
    uint32_t bhalf = ((lid >> 3) & 1) ? 16u : 0u;
    uint32_t browoff = (uint32_t)((nw * 16 + brow_in) * 128);

    float acc[2][4];
    #pragma unroll
    for (int j = 0; j < 2; ++j)
        #pragma unroll
        for (int q = 0; q < 4; ++q) acc[j][q] = 0.0f;

    for (int lch = 0; lch < 18; ++lch) {
        uint32_t aoff  = (lch & 1) ? OS_A1 : OS_A0;
        uint32_t boff  = (lch & 1) ? OS_B1 : OS_B0;
        uint32_t anoff = (lch & 1) ? OS_A0 : OS_A1;
        uint32_t bnoff = (lch & 1) ? OS_B0 : OS_B1;
        if (lch < 17) issue_OB(ch0 + lch + 1, sb + bnoff, tid);

        #pragma unroll
        for (int kk = 0; kk < 4; ++kk) {
            uint32_t acol = ((uint32_t)(kk * 32) + ahalf) ^ amask;
            uint32_t aa = sb + aoff + arowoff + acol;
            uint32_t av[4];
            LDSM4(av[0], av[1], av[2], av[3], aa);
            uint32_t bcol = ((uint32_t)(kk * 32) + bhalf) ^ amask;
            uint32_t bb = sb + boff + browoff + bcol;
            uint32_t bh[4];
            LDSM4(bh[0], bh[1], bh[2], bh[3], bb);
            MMAF16(acc[0], av, bh[0], bh[1]);
            MMAF16(acc[1], av, bh[2], bh[3]);
        }

        if (lch < 17) build_OA(ch0 + lch + 1, osm, anoff, xhb, hh, tid);
        asm volatile("cp.async.wait_group 0;" ::: "memory");
        __syncthreads();
    }

    float* dst = g_offp + (size_t)half * (NB * OFFC * HWSZ);
    int mrow = lid >> 2, ncol = (lid & 3) * 2;
    int m = hw0 + mw * 16 + mrow;
    #pragma unroll
    for (int j2 = 0; j2 < 2; ++j2) {
        int n = nw * 16 + j2 * 8 + ncol;
        if (n < OFFC) {
            dst[(b * OFFC + n) * HWSZ + m]     = acc[j2][0];
            dst[(b * OFFC + n) * HWSZ + m + 8] = acc[j2][2];
        }
        if (n + 1 < OFFC) {
            dst[(b * OFFC + n + 1) * HWSZ + m]     = acc[j2][1];
            dst[(b * OFFC + n + 1) * HWSZ + m + 8] = acc[j2][3];
        }
    }
}

// ---------------- combine split-K halves + bias ------------------------------
__global__ void combine_offs(const float* __restrict__ bias) {
    int i = blockIdx.x * 256 + threadIdx.x;     // float4 over NB*OFFC*HWSZ/4
    if (i >= NB * OFFC * HWSZ / 4) return;
    int o = (i >> 10) % OFFC;
    float bv = bias[o];
    float4 a = ((const float4*)g_offp)[i];
    float4 c = ((const float4*)(g_offp + NB * OFFC * HWSZ))[i];
    float4 r = make_float4(a.x + c.x + bv, a.y + c.y + bv, a.z + c.z + bv, a.w + c.w + bv);
    ((float4*)g_offs)[i] = r;
}

// ---------------- deformable conv: fp16-gather 2-product, 2 CTA/SM -----------
// 256 CTAs x 256 thr, CTA tile 64m x 256n, 8 warps 2m x 4n (warp 32m x 64n).
// A gathered from fp16 x (8B/corner), weighted fp32, split hi/lo fp16 (exact).
#define DS_CW   0                          // float4 cwgt[576]  (9216 B)
#define DS_CI   9216                       // ushort4 cidx[576] (4608 B)
#define DS_A0   13824                      // 16KB: hi 8K | lo 8K
#define DS_A1   (DS_A0 + 16384)
#define DS_B0   (DS_A1 + 16384)            // 32KB fp16 B
#define DS_B1   (DS_B0 + 32768)
#define DS_TOT  (DS_B1 + 32768)            // 112128 B -> 2 CTAs/SM
#define DS_TILE DS_A0                      // epilogue staging 256n x 68 f = 69632 B

__device__ __forceinline__ void issue_B(int ch, uint32_t dst, int tid) {
    const char* src = (const char*)g_wbf + (size_t)ch * 32768;
    #pragma unroll
    for (int r = 0; r < 8; ++r) {
        int i = (tid + 256 * r) * 16;
        CPASYNC16(dst + i, src + i);
    }
    asm volatile("cp.async.commit_group;");
}

// convert a gathered uint2 (4 halves) to 4 floats
__device__ __forceinline__ void u2_to_f4(uint2 u, float& a, float& b2, float& c, float& d) {
    float2 p0 = __half22float2(*(__half2*)&u.x);
    float2 p1 = __half22float2(*(__half2*)&u.y);
    a = p0.x; b2 = p0.y; c = p1.x; d = p1.y;
}

__global__ __launch_bounds__(256, 2) void deform_gemm(float* __restrict__ out) {
    extern __shared__ char smem[];
    uint32_t sb = smem_u32(smem);
    int tid = threadIdx.x, wid = tid >> 5, lid = tid & 31;
    int mw = wid & 1, nw = wid >> 1;
    int blk = blockIdx.x;          // 0..255 = 4b x 64 tiles
    int b    = blk >> 6;
    int hw0  = (blk & 63) << 6;
    const __half* xhb = g_xh + (size_t)b * HWSZ * CIN;

    issue_B(0, sb + DS_B0, tid);

    float4*  cw4 = (float4*)(smem + DS_CW);
    ushort4* ci4 = (ushort4*)(smem + DS_CI);
    for (int e = tid; e < 64 * KTAP; e += 256) {
        int ml = e / 9, k = e - ml * 9;
        int hw = hw0 + ml;
        int hh = hw >> 6, wp = hw & 63;
        float dy = g_offs[(b * OFFC + 2 * k) * HWSZ + hw];
        float dx = g_offs[(b * OFFC + 2 * k + 1) * HWSZ + hw];
        int ky = k / 3, kx = k - ky * 3;
        float py = (float)(hh - 1 + ky) + dy;
        float px = (float)(wp - 1 + kx) + dx;
        float y0f = floorf(py), x0f = floorf(px);
        float ty = py - y0f, tx = px - x0f;
        int y0 = (int)y0f, x0 = (int)x0f;
        float wv[4]; unsigned short iv[4];
        #pragma unroll
        for (int j = 0; j < 4; ++j) {
            int yj = y0 + (j >> 1);
            int xj = x0 + (j & 1);
            float wj = ((j >> 1) ? ty : 1.0f - ty) * ((j & 1) ? tx : 1.0f - tx);
            bool ok = (yj >= 0) && (yj < HH) && (xj >= 0) && (xj < WW);
            wv[j] = ok ? wj : 0.0f;
            iv[j] = ok ? (unsigned short)(yj * WW + xj) : 0;
        }
        cw4[e] = make_float4(wv[0], wv[1], wv[2], wv[3]);
        ci4[e] = make_ushort4(iv[0], iv[1], iv[2], iv[3]);
    }
    __syncthreads();

    // build chunk 0 A tile (un-pipelined prologue)
    {
        #pragma unroll
        for (int it = 0; it < 4; ++it) {
            int e = it * 256 + tid;          // 0..1023 = 64m x 16q
            int m = e >> 4, q = e & 15;
            int ce = m * 9;                  // tap 0, chunk 0
            float4  w  = cw4[ce];
            ushort4 ix = ci4[ce];
            const __half* base = xhb + q * 4;
            uint2 u0 = *(const uint2*)(base + ((int)ix.x << 8));
            uint2 u1 = *(const uint2*)(base + ((int)ix.y << 8));
            uint2 u2 = *(const uint2*)(base + ((int)ix.z << 8));
            uint2 u3 = *(const uint2*)(base + ((int)ix.w << 8));
            float a0,a1,a2,a3, b0,b1,b2,b3, c0,c1,c2,c3, d0,d1,d2,d3;
            u2_to_f4(u0, a0,a1,a2,a3);
            u2_to_f4(u1, b0,b1,b2,b3);
            u2_to_f4(u2, c0,c1,c2,c3);
            u2_to_f4(u3, d0,d1,d2,d3);
            float v0 = w.x*a0 + w.y*b0 + w.z*c0 + w.w*d0;
            float v1 = w.x*a1 + w.y*b1 + w.z*c1 + w.w*d1;
            float v2 = w.x*a2 + w.y*b2 + w.z*c2 + w.w*d2;
            float v3 = w.x*a3 + w.y*b3 + w.z*c3 + w.w*d3;
            __half h0 = __float2half_rn(v0);
            __half h1 = __float2half_rn(v1);
            __half h2 = __float2half_rn(v2);
            __half h3 = __float2half_rn(v3);
            __half l0 = __float2half_rn(v0 - __half2float(h0));
            __half l1 = __float2half_rn(v1 - __half2float(h1));
            __half l2 = __float2half_rn(v2 - __half2float(h2));
            __half l3 = __float2half_rn(v3 - __half2float(h3));
            uint32_t sw = swz128((uint32_t)(m * 128 + q * 8));
            __half2* ph = (__half2*)(smem + DS_A0 + sw);
            __half2* pl = (__half2*)(smem + DS_A0 + 8192 + sw);
            ph[0] = __half2(h0, h1);
            ph[1] = __half2(h2, h3);
            pl[0] = __half2(l0, l1);
            pl[1] = __half2(l2, l3);
        }
    }
    asm volatile("cp.async.wait_group 0;" ::: "memory");
    __syncthreads();

    uint32_t amask = (uint32_t)((lid & 7) * 16);
    uint32_t ahalf = (lid >> 4) ? 16u : 0u;
    uint32_t arowoff = (uint32_t)((mw * 32 + (lid & 15)) * 128);
    int brow_in = (lid & 7) + ((lid >> 4) << 3);
    uint32_t bhalf = ((lid >> 3) & 1) ? 16u : 0u;
    uint32_t browoff = (uint32_t)((nw * 64 + brow_in) * 128);

    float acc[2][8][4];
    #pragma unroll
    for (int i = 0; i < 2; ++i)
        #pragma unroll
        for (int j = 0; j < 8; ++j)
            #pragma unroll
            for (int q = 0; q < 4; ++q) acc[i][j][q] = 0.0f;

    for (int ch = 0; ch < 36; ++ch) {
        uint32_t aoff  = (ch & 1) ? DS_A1 : DS_A0;
        uint32_t boff  = (ch & 1) ? DS_B1 : DS_B0;
        uint32_t anoff = (ch & 1) ? DS_A0 : DS_A1;
        uint32_t bnoff = (ch & 1) ? DS_B0 : DS_B1;
        bool dob = (ch < 35);
        if (dob) issue_B(ch + 1, sb + bnoff, tid);
        int tn  = (ch + 1) >> 2;
        int c0n = ((ch + 1) & 3) * 64;

        #pragma unroll
        for (int kk = 0; kk < 4; ++kk) {
            // ---- issue gathers for next chunk's build iteration it=kk ----
            float4 gw; uint2 u0, u1, u2, u3;
            int gm = 0, gq = 0;
            if (dob) {
                int e = kk * 256 + tid;       // 64m x 16q over 4 kk
                gm = e >> 4; gq = e & 15;
                int ce = gm * 9 + tn;
                gw = cw4[ce];
                ushort4 gix = ci4[ce];
                const __half* gbase = xhb + c0n + gq * 4;
                u0 = *(const uint2*)(gbase + ((int)gix.x << 8));
                u1 = *(const uint2*)(gbase + ((int)gix.y << 8));
                u2 = *(const uint2*)(gbase + ((int)gix.z << 8));
                u3 = *(const uint2*)(gbase + ((int)gix.w << 8));
            }

            // ---- MMA step kk: 2 products (a_hi + a_lo) x b ----
            uint32_t acol = ((uint32_t)(kk * 32) + ahalf) ^ amask;
            uint32_t a_hi[2][4], a_lo[2][4];
            #pragma unroll
            for (int i = 0; i < 2; ++i) {
                uint32_t aa = sb + aoff + arowoff + (uint32_t)(i * 2048) + acol;
                LDSM4(a_hi[i][0], a_hi[i][1], a_hi[i][2], a_hi[i][3], aa);
                LDSM4(a_lo[i][0], a_lo[i][1], a_lo[i][2], a_lo[i][3], aa + 8192);
            }
            uint32_t bcol = ((uint32_t)(kk * 32) + bhalf) ^ amask;
            #pragma unroll
            for (int j2 = 0; j2 < 4; ++j2) {
                uint32_t bb = sb + boff + browoff + (uint32_t)(j2 * 2048) + bcol;
                uint32_t bh[4];
                LDSM4(bh[0], bh[1], bh[2], bh[3], bb);
                #pragma unroll
                for (int i = 0; i < 2; ++i) {
                    MMAF16(acc[i][2*j2],   a_hi[i], bh[0], bh[1]);
                    MMAF16(acc[i][2*j2],   a_lo[i], bh[0], bh[1]);
                    MMAF16(acc[i][2*j2+1], a_hi[i], bh[2], bh[3]);
                    MMAF16(acc[i][2*j2+1], a_lo[i], bh[2], bh[3]);
                }
            }

            // ---- convert + store next chunk A (it=kk) ----
            if (dob) {
                float a0,a1,a2,a3, b0,b1,b2,b3, c0f,c1,c2,c3, d0,d1,d2,d3;
                u2_to_f4(u0, a0,a1,a2,a3);
                u2_to_f4(u1, b0,b1,b2,b3);
                u2_to_f4(u2, c0f,c1,c2,c3);
                u2_to_f4(u3, d0,d1,d2,d3);
                float v0 = gw.x*a0 + gw.y*b0 + gw.z*c0f + gw.w*d0;
                float v1 = gw.x*a1 + gw.y*b1 + gw.z*c1  + gw.w*d1;
                float v2 = gw.x*a2 + gw.y*b2 + gw.z*c2  + gw.w*d2;
                float v3 = gw.x*a3 + gw.y*b3 + gw.z*c3  + gw.w*d3;
                __half h0 = __float2half_rn(v0);
                __half h1 = __float2half_rn(v1);
                __half h2 = __float2half_rn(v2);
                __half h3 = __float2half_rn(v3);
                __half l0 = __float2half_rn(v0 - __half2float(h0));
                __half l1 = __float2half_rn(v1 - __half2float(h1));
                __half l2 = __float2half_rn(v2 - __half2float(h2));
                __half l3 = __float2half_rn(v3 - __half2float(h3));
                uint32_t sw = swz128((uint32_t)(gm * 128 + gq * 8));
                __half2* ph = (__half2*)(smem + anoff + sw);
                __half2* pl = (__half2*)(smem + anoff + 8192 + sw);
                ph[0] = __half2(h0, h1);
                ph[1] = __half2(h2, h3);
                pl[0] = __half2(l0, l1);
                pl[1] = __half2(l2, l3);
            }
        }

        asm volatile("cp.async.wait_group 0;" ::: "memory");
        __syncthreads();
    }

    // epilogue: stage accumulators into smem tile [n][m] (stride 68),
    // then fully coalesced float4 stores to out [b][n][hw]
    float* etile = (float*)(smem + DS_TILE);
    int mrow = lid >> 2;
    int ncol = (lid & 3) * 2;
    #pragma unroll
    for (int i = 0; i < 2; ++i) {
        int ml = mw * 32 + i * 16 + mrow;
        #pragma unroll
        for (int j = 0; j < 8; ++j) {
            int n = nw * 64 + j * 8 + ncol;
            etile[n * 68 + ml]           = acc[i][j][0];
            etile[(n + 1) * 68 + ml]     = acc[i][j][1];
            etile[n * 68 + ml + 8]       = acc[i][j][2];
            etile[(n + 1) * 68 + ml + 8] = acc[i][j][3];
        }
    }

    // fused GroupNorm partial reduction
    #pragma unroll
    for (int j = 0; j < 8; ++j) {
        float s = 0.0f, sq = 0.0f;
        #pragma unroll
        for (int i = 0; i < 2; ++i)
            #pragma unroll
            for (int q = 0; q < 4; ++q) {
                float v = acc[i][j][q];
                s += v; sq += v * v;
            }
        #pragma unroll
        for (int off = 16; off > 0; off >>= 1) {
            s  += __shfl_xor_sync(0xFFFFFFFF, s,  off);
            sq += __shfl_xor_sync(0xFFFFFFFF, sq, off);
        }
        if (lid == 0) {
            int bg = b * GN_GROUPS + nw * 8 + j;
            atomicAdd(&g_part[bg * 2 + 0], s);
            atomicAdd(&g_part[bg * 2 + 1], sq);
        }
    }
    __syncthreads();

    #pragma unroll
    for (int it = 0; it < 16; ++it) {
        int e = it * 256 + tid;        // over 256n x 16 float4
        int n  = e >> 4;
        int mq = e & 15;
        float4 v = ((const float4*)(etile + n * 68))[mq];
        *(float4*)(out + (((size_t)(b * COUT + n)) << 12) + hw0 + mq * 4) = v;
    }
}

// ---------------- GN finalize: partials -> (mean, rstd) ----------------------
__global__ void gn_finalize() {
    int bg = threadIdx.x;
    if (bg >= NB * GN_GROUPS) return;
    float n = (float)(CPG * HWSZ);
    float mean = g_part[bg * 2 + 0] / n;
    float var  = g_part[bg * 2 + 1] / n - mean * mean;
    g_stats[bg * 2 + 0] = mean;
    g_stats[bg * 2 + 1] = rsqrtf(var + EPS);
}

// ---------------- GroupNorm apply + ReLU (float4) -----------------------------
__global__ void gn_apply(float* __restrict__ out,
                         const float* __restrict__ gamma,
                         const float* __restrict__ beta) {
    int i = blockIdx.x * 256 + threadIdx.x;       // float4 over 4*256*4096/4
    int c = (i >> 10) & 255;
    int b = i >> 18;
    int bg = b * GN_GROUPS + (c >> 3);
    float mean = g_stats[bg * 2 + 0];
    float rstd = g_stats[bg * 2 + 1];
    float gmul = rstd * gamma[c];
    float add  = beta[c] - mean * gmul;
    float4 v = ((const float4*)out)[i];
    v.x = fmaxf(v.x * gmul + add, 0.0f);
    v.y = fmaxf(v.y * gmul + add, 0.0f);
    v.z = fmaxf(v.z * gmul + add, 0.0f);
    v.w = fmaxf(v.w * gmul + add, 0.0f);
    ((float4*)out)[i] = v;
}

// ---------------- launch ------------------------------------------------------
extern "C" void kernel_launch(void* const* d_in, const int* in_sizes, int n_in,
                              void* d_out, int out_size) {
    const float* x   = (const float*)d_in[0];
    const float* ow  = (const float*)d_in[1];
    const float* ob  = (const float*)d_in[2];
    const float* dw  = (const float*)d_in[3];
    const float* gam = (const float*)d_in[4];
    const float* bet = (const float*)d_in[5];
    float* out = (float*)d_out;

    cudaFuncSetAttribute(deform_gemm, cudaFuncAttributeMaxDynamicSharedMemorySize, DS_TOT);
    cudaFuncSetAttribute(offset_conv_mma, cudaFuncAttributeMaxDynamicSharedMemorySize, OS_TOT);

    prep_wbf<<<(KTAP * 4 * 16384 + 255) / 256, 256>>>(dw);
    prep_owbf<<<(KTAP * 4 * 2048 + 255) / 256, 256>>>(ow);
    transpose_x<<<dim3(HWSZ / 32, CIN / 32, NB), dim3(32, 8)>>>(x);
    offset_conv_mma<<<512, 256, OS_TOT>>>();
    combine_offs<<<(NB * OFFC * HWSZ / 4 + 255) / 256, 256>>>(ob);
    deform_gemm<<<256, 256, DS_TOT>>>(out);
    gn_finalize<<<1, 128>>>();
    gn_apply<<<(NB * COUT * HWSZ / 4 + 255) / 256, 256>>>(out, gam, bet);
}